// round 4
// baseline (speedup 1.0000x reference)
#include <cuda_runtime.h>
#include <math.h>

#define Bn 16
#define Tn 1000
#define NT 64
#define TPB 256
#define NTILES 16
#define GAMMA_F 1e-4f
#define BXT (Bn*8*Tn)    /* 128000 */
#define BHT (Bn*48*Tn)   /* 768000 */

// ---------------- device scratch (static, allowed) ----------------
__device__ float g_xs0[BXT];
__device__ float g_cy[BXT];
__device__ float g_yterm[BHT];
__device__ float g_hxbuf[2][BHT];
__device__ float g_Qi[64], g_QiF[64], g_FtQi[64], g_FtQiF[64], g_HtRiH[64], g_HtRi[32];
__device__ float g_b2sum[48];

// ---------------- shared layout (floats) ----------------
constexpr int OFF_WP_H = 0;
constexpr int OFF_WP_N = 2352;
constexpr int OFF_WF_H = 4704;
constexpr int OFF_WF_N = 7056;
constexpr int OFF_WY_H = 9408;
constexpr int OFF_W2P  = 11760;
constexpr int OFF_W2F  = 14112;
constexpr int OFF_W2Y  = 16464;
constexpr int OFF_WIH  = 18816;
constexpr int OFF_WHH  = 25872;
constexpr int OFF_WP_M = 32928;
constexpr int OFF_WF_M = 33312;
constexpr int OFF_WY_M = 33696;
constexpr int OFF_WDEC = 34080;
constexpr int OFF_B1P  = 34464;
constexpr int OFF_B1F  = 34512;
constexpr int OFF_B2S  = 34560;
constexpr int OFF_BIH  = 34608;
constexpr int OFF_BHH  = 34752;
constexpr int OFF_BDEC = 34896;
constexpr int OFF_SQI    = 34904;
constexpr int OFF_SQIF   = 34968;
constexpr int OFF_SFTQI  = 35032;
constexpr int OFF_SFTQIF = 35096;
constexpr int OFF_SHTRIH = 35160;
constexpr int OFF_HSH  = 35224;   // 48 x 66 (halo)
constexpr int OFF_XSH  = 38392;   // 8 x 66 (halo)
constexpr int OFF_MP   = 38920;   // 8 x 64
constexpr int OFF_MF   = 39432;
constexpr int OFF_MY   = 39944;
constexpr int OFF_RP   = 40456;   // 48 x 64
constexpr int OFF_RF   = 43528;
constexpr int OFF_RY   = 46600;
constexpr int OFF_AGG  = 49672;
constexpr int SMEM_FLOATS = 52744;
constexpr int SMEM_BYTES  = SMEM_FLOATS * 4;  // 210,976 B

// ---------------- small-matrix prep (fp64 Gauss-Jordan, one thread) ----------------
__device__ void gj_invert(double* a, double* inv, int n) {
    for (int i = 0; i < n; i++)
        for (int j = 0; j < n; j++) inv[i*n+j] = (i == j) ? 1.0 : 0.0;
    for (int c = 0; c < n; c++) {
        int piv = c; double best = fabs(a[c*n+c]);
        for (int r = c+1; r < n; r++) { double v = fabs(a[r*n+c]); if (v > best) { best = v; piv = r; } }
        if (piv != c) {
            for (int j = 0; j < n; j++) {
                double t = a[c*n+j]; a[c*n+j] = a[piv*n+j]; a[piv*n+j] = t;
                t = inv[c*n+j]; inv[c*n+j] = inv[piv*n+j]; inv[piv*n+j] = t;
            }
        }
        double ip = 1.0 / a[c*n+c];
        for (int j = 0; j < n; j++) { a[c*n+j] *= ip; inv[c*n+j] *= ip; }
        for (int r = 0; r < n; r++) if (r != c) {
            double f = a[r*n+c];
            if (f != 0.0) for (int j = 0; j < n; j++) {
                a[r*n+j] -= f * a[c*n+j];
                inv[r*n+j] -= f * inv[c*n+j];
            }
        }
    }
}

__global__ void prep_small(const float* __restrict__ F, const float* __restrict__ H,
                           const float* __restrict__ Q, const float* __restrict__ R,
                           const float* __restrict__ b2p, const float* __restrict__ b2f,
                           const float* __restrict__ b2y) {
    if (threadIdx.x != 0 || blockIdx.x != 0) return;
    double Qd[64], Qi[64], Rd[16], Ri[16], Fd[64], Hd[32];
    for (int i = 0; i < 64; i++) Qd[i] = (double)Q[i];
    for (int i = 0; i < 16; i++) Rd[i] = (double)R[i];
    for (int i = 0; i < 64; i++) Fd[i] = (double)F[i];
    for (int i = 0; i < 32; i++) Hd[i] = (double)H[i];
    gj_invert(Qd, Qi, 8);
    gj_invert(Rd, Ri, 4);

    double QiF[64], FtQi[64], FtQiF[64], HtRi[32], HtRiH[64];
    for (int i = 0; i < 8; i++) for (int j = 0; j < 8; j++) {
        double s = 0; for (int k = 0; k < 8; k++) s += Qi[i*8+k] * Fd[k*8+j];
        QiF[i*8+j] = s;
    }
    for (int i = 0; i < 8; i++) for (int j = 0; j < 8; j++) {
        double s = 0; for (int k = 0; k < 8; k++) s += Fd[k*8+i] * Qi[k*8+j];
        FtQi[i*8+j] = s;
    }
    for (int i = 0; i < 8; i++) for (int j = 0; j < 8; j++) {
        double s = 0; for (int k = 0; k < 8; k++) s += FtQi[i*8+k] * Fd[k*8+j];
        FtQiF[i*8+j] = s;
    }
    for (int i = 0; i < 8; i++) for (int z = 0; z < 4; z++) {
        double s = 0; for (int y = 0; y < 4; y++) s += Hd[y*8+i] * Ri[y*4+z];
        HtRi[i*4+z] = s;
    }
    for (int i = 0; i < 8; i++) for (int j = 0; j < 8; j++) {
        double s = 0; for (int z = 0; z < 4; z++) s += HtRi[i*4+z] * Hd[z*8+j];
        HtRiH[i*8+j] = s;
    }
    for (int i = 0; i < 64; i++) { g_Qi[i] = (float)Qi[i]; g_QiF[i] = (float)QiF[i];
                                   g_FtQi[i] = (float)FtQi[i]; g_FtQiF[i] = (float)FtQiF[i];
                                   g_HtRiH[i] = (float)HtRiH[i]; }
    for (int i = 0; i < 32; i++) g_HtRi[i] = (float)HtRi[i];
    for (int o = 0; o < 48; o++) g_b2sum[o] = b2p[o] + b2f[o] + b2y[o];
}

// ---------------- per-node iteration-invariant prep ----------------
__global__ void prep_nodes(const float* __restrict__ ys, const float* __restrict__ H,
                           const float* __restrict__ W_hy, const float* __restrict__ b_hy,
                           const float* __restrict__ W1y, const float* __restrict__ b1y) {
    int node = blockIdx.x * blockDim.x + threadIdx.x;
    if (node >= Bn * Tn) return;
    int b = node / Tn, t = node - b * Tn;
    float yv[4];
    #pragma unroll
    for (int z = 0; z < 4; z++) yv[z] = ys[(b*Tn + t)*4 + z];

    #pragma unroll
    for (int i = 0; i < 8; i++) {
        float s0 = 0.f, s1 = 0.f;
        #pragma unroll
        for (int y = 0; y < 4; y++) { s0 = fmaf(H[y*8+i], yv[y], s0); s1 = fmaf(g_HtRi[i*4+y], yv[y], s1); }
        g_xs0[(b*8+i)*Tn + t] = s0;
        g_cy[(b*8+i)*Tn + t] = s1;
    }
    float hy[48];
    #pragma unroll
    for (int o = 0; o < 48; o++) {
        float s = b_hy[o];
        #pragma unroll
        for (int y = 0; y < 4; y++) s = fmaf(W_hy[o*4+y], yv[y], s);
        hy[o] = s;
    }
    for (int o = 0; o < 48; o++) {
        float s = b1y[o];
        #pragma unroll
        for (int k = 0; k < 48; k++) s = fmaf(W1y[o*104 + 48 + k], hy[k], s);
        g_yterm[(b*48+o)*Tn + t] = s;
    }
}

// ---------------- GEMM fragments ----------------
__device__ __forceinline__ void gemm48(const float* __restrict__ W, const float* __restrict__ inp,
                                       int ldi, int off, int ty, int nb,
                                       float a0[4], float a1[4], float a2[4]) {
    #pragma unroll 4
    for (int k = 0; k < 48; k++) {
        float w0 = W[ty*49 + k], w1 = W[(ty+16)*49 + k], w2 = W[(ty+32)*49 + k];
        #pragma unroll
        for (int nn = 0; nn < 4; nn++) {
            float x = inp[k*ldi + off + nb + nn];
            a0[nn] = fmaf(w0, x, a0[nn]);
            a1[nn] = fmaf(w1, x, a1[nn]);
            a2[nn] = fmaf(w2, x, a2[nn]);
        }
    }
}

__device__ __forceinline__ void gemm48v(const float* __restrict__ W, const float* __restrict__ inp,
                                        int ty, int nb, float a0[4], float a1[4], float a2[4]) {
    #pragma unroll 4
    for (int k = 0; k < 48; k++) {
        float w0 = W[ty*49 + k], w1 = W[(ty+16)*49 + k], w2 = W[(ty+32)*49 + k];
        float4 xv = *reinterpret_cast<const float4*>(&inp[k*64 + nb]);
        a0[0] = fmaf(w0, xv.x, a0[0]); a0[1] = fmaf(w0, xv.y, a0[1]);
        a0[2] = fmaf(w0, xv.z, a0[2]); a0[3] = fmaf(w0, xv.w, a0[3]);
        a1[0] = fmaf(w1, xv.x, a1[0]); a1[1] = fmaf(w1, xv.y, a1[1]);
        a1[2] = fmaf(w1, xv.z, a1[2]); a1[3] = fmaf(w1, xv.w, a1[3]);
        a2[0] = fmaf(w2, xv.x, a2[0]); a2[1] = fmaf(w2, xv.y, a2[1]);
        a2[2] = fmaf(w2, xv.z, a2[2]); a2[3] = fmaf(w2, xv.w, a2[3]);
    }
}

__device__ __forceinline__ void gemm8(const float* __restrict__ Wm, const float* __restrict__ msg,
                                      int ty, int nb, float a0[4], float a1[4], float a2[4]) {
    #pragma unroll
    for (int k = 0; k < 8; k++) {
        float w0 = Wm[ty*8 + k], w1 = Wm[(ty+16)*8 + k], w2 = Wm[(ty+32)*8 + k];
        float4 xv = *reinterpret_cast<const float4*>(&msg[k*64 + nb]);
        a0[0] = fmaf(w0, xv.x, a0[0]); a0[1] = fmaf(w0, xv.y, a0[1]);
        a0[2] = fmaf(w0, xv.z, a0[2]); a0[3] = fmaf(w0, xv.w, a0[3]);
        a1[0] = fmaf(w1, xv.x, a1[0]); a1[1] = fmaf(w1, xv.y, a1[1]);
        a1[2] = fmaf(w1, xv.z, a1[2]); a1[3] = fmaf(w1, xv.w, a1[3]);
        a2[0] = fmaf(w2, xv.x, a2[0]); a2[1] = fmaf(w2, xv.y, a2[1]);
        a2[2] = fmaf(w2, xv.z, a2[2]); a2[3] = fmaf(w2, xv.w, a2[3]);
    }
}

__device__ __forceinline__ float sigmf(float x) { return 1.f / (1.f + __expf(-x)); }
__device__ __forceinline__ float tanhfast(float x) { return 1.f - 2.f / (__expf(2.f * x) + 1.f); }

// ---------------- the iteration step ----------------
__global__ void __launch_bounds__(TPB, 1)
step_kernel(const float* __restrict__ xs_in, const float* __restrict__ hx_in,
            float* __restrict__ xs_out, float* __restrict__ hx_out,
            const float* __restrict__ W1p, const float* __restrict__ b1p,
            const float* __restrict__ W2p,
            const float* __restrict__ W1f, const float* __restrict__ b1f,
            const float* __restrict__ W2f,
            const float* __restrict__ W1y,
            const float* __restrict__ W2y,
            const float* __restrict__ Wih, const float* __restrict__ bih,
            const float* __restrict__ Whh, const float* __restrict__ bhh,
            const float* __restrict__ Wdec, const float* __restrict__ bdec) {
    extern __shared__ float sm[];
    float* Wp_h = sm + OFF_WP_H;  float* Wp_n = sm + OFF_WP_N;
    float* Wf_h = sm + OFF_WF_H;  float* Wf_n = sm + OFF_WF_N;
    float* Wy_h = sm + OFF_WY_H;
    float* W2p_s = sm + OFF_W2P;  float* W2f_s = sm + OFF_W2F;  float* W2y_s = sm + OFF_W2Y;
    float* Wih_s = sm + OFF_WIH;  float* Whh_s = sm + OFF_WHH;
    float* Wp_m = sm + OFF_WP_M;  float* Wf_m = sm + OFF_WF_M;  float* Wy_m = sm + OFF_WY_M;
    float* Wdec_s = sm + OFF_WDEC;
    float* b1p_s = sm + OFF_B1P;  float* b1f_s = sm + OFF_B1F;  float* b2s_s = sm + OFF_B2S;
    float* bih_s = sm + OFF_BIH;  float* bhh_s = sm + OFF_BHH;  float* bdec_s = sm + OFF_BDEC;
    float* sQi = sm + OFF_SQI;    float* sQiF = sm + OFF_SQIF;
    float* sFtQi = sm + OFF_SFTQI; float* sFtQiF = sm + OFF_SFTQIF; float* sHtRiH = sm + OFF_SHTRIH;
    float* hsh = sm + OFF_HSH;    float* xsh = sm + OFF_XSH;
    float* mp_s = sm + OFF_MP;    float* mf_s = sm + OFF_MF;    float* my_s = sm + OFF_MY;
    float* rp = sm + OFF_RP;      float* rf = sm + OFF_RF;      float* ry = sm + OFF_RY;
    float* agg_s = sm + OFF_AGG;

    const int tid = threadIdx.x;
    const int b = blockIdx.y;
    const int t0 = blockIdx.x * NT;

    // -- stage weights --
    for (int idx = tid; idx < 48*104; idx += TPB) {
        int o = idx / 104, c = idx - o*104;
        float vp = W1p[idx], vf = W1f[idx], vy = W1y[idx];
        if (c < 48)       { Wp_h[o*49+c] = vp; Wf_h[o*49+c] = vf; Wy_h[o*49+c] = vy; }
        else if (c < 96)  { int cc = c-48; Wp_n[o*49+cc] = vp; Wf_n[o*49+cc] = vf; }
        else              { int cc = c-96; Wp_m[o*8+cc] = vp; Wf_m[o*8+cc] = vf; Wy_m[o*8+cc] = vy; }
    }
    for (int idx = tid; idx < 48*48; idx += TPB) {
        int o = idx / 48, k = idx - o*48;
        W2p_s[o*49+k] = W2p[idx]; W2f_s[o*49+k] = W2f[idx]; W2y_s[o*49+k] = W2y[idx];
    }
    for (int idx = tid; idx < 144*48; idx += TPB) {
        int o = idx / 48, k = idx - o*48;
        Wih_s[o*49+k] = Wih[idx]; Whh_s[o*49+k] = Whh[idx];
    }
    for (int idx = tid; idx < 384; idx += TPB) Wdec_s[idx] = Wdec[idx];
    if (tid < 48) { b1p_s[tid] = b1p[tid]; b1f_s[tid] = b1f[tid]; b2s_s[tid] = g_b2sum[tid]; }
    for (int idx = tid; idx < 144; idx += TPB) { bih_s[idx] = bih[idx]; bhh_s[idx] = bhh[idx]; }
    if (tid < 8) bdec_s[tid] = bdec[tid];
    for (int idx = tid; idx < 64; idx += TPB) {
        sQi[idx] = g_Qi[idx]; sQiF[idx] = g_QiF[idx]; sFtQi[idx] = g_FtQi[idx];
        sFtQiF[idx] = g_FtQiF[idx]; sHtRiH[idx] = g_HtRiH[idx];
    }
    // -- stage state tiles with halo --
    for (int idx = tid; idx < 48*66; idx += TPB) {
        int k = idx / 66, c = idx - k*66; int t = t0 + c - 1;
        hsh[idx] = (t >= 0 && t < Tn) ? hx_in[(b*48+k)*Tn + t] : 0.f;
    }
    for (int idx = tid; idx < 8*66; idx += TPB) {
        int k = idx / 66, c = idx - k*66; int t = t0 + c - 1;
        xsh[idx] = (t >= 0 && t < Tn) ? xs_in[(b*8+k)*Tn + t] : 0.f;
    }
    __syncthreads();

    // -- messages --
    #pragma unroll
    for (int rep = 0; rep < 2; rep++) {
        int item = tid + rep*TPB;
        int i = item >> 6, n = item & 63, t = t0 + n;
        bool valid = t < Tn;
        float accp = 0.f, accf = 0.f;
        float accy = valid ? g_cy[(b*8+i)*Tn + t] : 0.f;
        #pragma unroll
        for (int j = 0; j < 8; j++) {
            float xc = xsh[j*66 + 1 + n];
            accp = fmaf(-sQi[i*8+j], xc, accp);
            accp = fmaf(sQiF[i*8+j], xsh[j*66 + n], accp);
            accf = fmaf(sFtQi[i*8+j], xsh[j*66 + 2 + n], accf);
            accf = fmaf(-sFtQiF[i*8+j], xc, accf);
            accy = fmaf(-sHtRiH[i*8+j], xc, accy);
        }
        mp_s[i*64+n] = (valid && t > 0) ? accp : 0.f;
        mf_s[i*64+n] = (t < Tn-1) ? accf : 0.f;
        my_s[i*64+n] = valid ? accy : 0.f;
    }
    __syncthreads();

    const int ty = tid >> 4, tx = tid & 15, nb = 4*tx;

    // -- edge past --
    {
        float a0[4], a1[4], a2[4];
        #pragma unroll
        for (int nn = 0; nn < 4; nn++) { a0[nn] = b1p_s[ty]; a1[nn] = b1p_s[ty+16]; a2[nn] = b1p_s[ty+32]; }
        gemm48(Wp_h, hsh, 66, 1, ty, nb, a0, a1, a2);
        gemm48(Wp_n, hsh, 66, 0, ty, nb, a0, a1, a2);
        gemm8(Wp_m, mp_s, ty, nb, a0, a1, a2);
        *reinterpret_cast<float4*>(&rp[ty*64 + nb])      = make_float4(fmaxf(a0[0],0.f), fmaxf(a0[1],0.f), fmaxf(a0[2],0.f), fmaxf(a0[3],0.f));
        *reinterpret_cast<float4*>(&rp[(ty+16)*64 + nb]) = make_float4(fmaxf(a1[0],0.f), fmaxf(a1[1],0.f), fmaxf(a1[2],0.f), fmaxf(a1[3],0.f));
        *reinterpret_cast<float4*>(&rp[(ty+32)*64 + nb]) = make_float4(fmaxf(a2[0],0.f), fmaxf(a2[1],0.f), fmaxf(a2[2],0.f), fmaxf(a2[3],0.f));
    }
    // -- edge future --
    {
        float a0[4], a1[4], a2[4];
        #pragma unroll
        for (int nn = 0; nn < 4; nn++) { a0[nn] = b1f_s[ty]; a1[nn] = b1f_s[ty+16]; a2[nn] = b1f_s[ty+32]; }
        gemm48(Wf_h, hsh, 66, 1, ty, nb, a0, a1, a2);
        gemm48(Wf_n, hsh, 66, 2, ty, nb, a0, a1, a2);
        gemm8(Wf_m, mf_s, ty, nb, a0, a1, a2);
        *reinterpret_cast<float4*>(&rf[ty*64 + nb])      = make_float4(fmaxf(a0[0],0.f), fmaxf(a0[1],0.f), fmaxf(a0[2],0.f), fmaxf(a0[3],0.f));
        *reinterpret_cast<float4*>(&rf[(ty+16)*64 + nb]) = make_float4(fmaxf(a1[0],0.f), fmaxf(a1[1],0.f), fmaxf(a1[2],0.f), fmaxf(a1[3],0.f));
        *reinterpret_cast<float4*>(&rf[(ty+32)*64 + nb]) = make_float4(fmaxf(a2[0],0.f), fmaxf(a2[1],0.f), fmaxf(a2[2],0.f), fmaxf(a2[3],0.f));
    }
    // -- edge y (hy-part + b1y precomputed in g_yterm) --
    {
        float a0[4], a1[4], a2[4];
        #pragma unroll
        for (int nn = 0; nn < 4; nn++) {
            int t = t0 + nb + nn; bool v = t < Tn;
            a0[nn] = v ? g_yterm[(b*48 + ty)*Tn + t] : 0.f;
            a1[nn] = v ? g_yterm[(b*48 + ty+16)*Tn + t] : 0.f;
            a2[nn] = v ? g_yterm[(b*48 + ty+32)*Tn + t] : 0.f;
        }
        gemm48(Wy_h, hsh, 66, 1, ty, nb, a0, a1, a2);
        gemm8(Wy_m, my_s, ty, nb, a0, a1, a2);
        *reinterpret_cast<float4*>(&ry[ty*64 + nb])      = make_float4(fmaxf(a0[0],0.f), fmaxf(a0[1],0.f), fmaxf(a0[2],0.f), fmaxf(a0[3],0.f));
        *reinterpret_cast<float4*>(&ry[(ty+16)*64 + nb]) = make_float4(fmaxf(a1[0],0.f), fmaxf(a1[1],0.f), fmaxf(a1[2],0.f), fmaxf(a1[3],0.f));
        *reinterpret_cast<float4*>(&ry[(ty+32)*64 + nb]) = make_float4(fmaxf(a2[0],0.f), fmaxf(a2[1],0.f), fmaxf(a2[2],0.f), fmaxf(a2[3],0.f));
    }
    __syncthreads();

    // -- agg = W2p@rp + W2f@rf + W2y@ry + b2sum --
    {
        float a0[4], a1[4], a2[4];
        #pragma unroll
        for (int nn = 0; nn < 4; nn++) { a0[nn] = b2s_s[ty]; a1[nn] = b2s_s[ty+16]; a2[nn] = b2s_s[ty+32]; }
        gemm48v(W2p_s, rp, ty, nb, a0, a1, a2);
        gemm48v(W2f_s, rf, ty, nb, a0, a1, a2);
        gemm48v(W2y_s, ry, ty, nb, a0, a1, a2);
        *reinterpret_cast<float4*>(&agg_s[ty*64 + nb])      = make_float4(a0[0], a0[1], a0[2], a0[3]);
        *reinterpret_cast<float4*>(&agg_s[(ty+16)*64 + nb]) = make_float4(a1[0], a1[1], a1[2], a1[3]);
        *reinterpret_cast<float4*>(&agg_s[(ty+32)*64 + nb]) = make_float4(a2[0], a2[1], a2[2], a2[3]);
    }
    __syncthreads();

    // -- GRU --
    {
        float A[9][4], Bv[3][4];
        #pragma unroll
        for (int j = 0; j < 9; j++) {
            float bi = bih_s[ty + 16*j] + ((j < 6) ? bhh_s[ty + 16*j] : 0.f);
            #pragma unroll
            for (int nn = 0; nn < 4; nn++) A[j][nn] = bi;
        }
        #pragma unroll
        for (int jj = 0; jj < 3; jj++) {
            float bb = bhh_s[96 + ty + 16*jj];
            #pragma unroll
            for (int nn = 0; nn < 4; nn++) Bv[jj][nn] = bb;
        }
        #pragma unroll 2
        for (int k = 0; k < 48; k++) {
            float4 xv = *reinterpret_cast<const float4*>(&agg_s[k*64 + nb]);
            #pragma unroll
            for (int j = 0; j < 9; j++) {
                float w = Wih_s[(ty + 16*j)*49 + k];
                A[j][0] = fmaf(w, xv.x, A[j][0]); A[j][1] = fmaf(w, xv.y, A[j][1]);
                A[j][2] = fmaf(w, xv.z, A[j][2]); A[j][3] = fmaf(w, xv.w, A[j][3]);
            }
        }
        #pragma unroll 2
        for (int k = 0; k < 48; k++) {
            float h0 = hsh[k*66 + 1 + nb], h1 = hsh[k*66 + 2 + nb];
            float h2 = hsh[k*66 + 3 + nb], h3 = hsh[k*66 + 4 + nb];
            #pragma unroll
            for (int j = 0; j < 6; j++) {
                float w = Whh_s[(ty + 16*j)*49 + k];
                A[j][0] = fmaf(w, h0, A[j][0]); A[j][1] = fmaf(w, h1, A[j][1]);
                A[j][2] = fmaf(w, h2, A[j][2]); A[j][3] = fmaf(w, h3, A[j][3]);
            }
            #pragma unroll
            for (int jj = 0; jj < 3; jj++) {
                float w = Whh_s[(96 + ty + 16*jj)*49 + k];
                Bv[jj][0] = fmaf(w, h0, Bv[jj][0]); Bv[jj][1] = fmaf(w, h1, Bv[jj][1]);
                Bv[jj][2] = fmaf(w, h2, Bv[jj][2]); Bv[jj][3] = fmaf(w, h3, Bv[jj][3]);
            }
        }
        __syncthreads();  // all rp readers (agg phase) done before overwrite with hnew
        #pragma unroll
        for (int jj = 0; jj < 3; jj++) {
            int o = ty + 16*jj;
            #pragma unroll
            for (int nn = 0; nn < 4; nn++) {
                float r = sigmf(A[jj][nn]);
                float z = sigmf(A[3+jj][nn]);
                float ng = tanhfast(A[6+jj][nn] + r * Bv[jj][nn]);
                float hold = hsh[o*66 + 1 + nb + nn];
                float hv = (1.f - z)*ng + z*hold;
                rp[o*64 + nb + nn] = hv;  // hnew staged in rp
                int t = t0 + nb + nn;
                if (t < Tn) hx_out[(b*48+o)*Tn + t] = hv;
            }
        }
    }
    __syncthreads();

    // -- eps = W_dec @ hnew + b_dec; xs update --
    #pragma unroll
    for (int rep = 0; rep < 2; rep++) {
        int item = tid + rep*TPB;
        int i = item >> 6, n = item & 63, t = t0 + n;
        float e = bdec_s[i];
        #pragma unroll 8
        for (int k = 0; k < 48; k++) e = fmaf(Wdec_s[i*48+k], rp[k*64+n], e);
        if (t < Tn) {
            float xn = xsh[i*66 + 1 + n]
                     + GAMMA_F * (e + mp_s[i*64+n] + mf_s[i*64+n] + my_s[i*64+n]);
            xs_out[(b*8+i)*Tn + t] = xn;
        }
    }
}

// ---------------- host ----------------
extern "C" void kernel_launch(void* const* d_in, const int* in_sizes, int n_in,
                              void* d_out, int out_size) {
    const float* ys   = (const float*)d_in[0];
    const float* hx0  = (const float*)d_in[1];
    const float* F    = (const float*)d_in[2];
    const float* H    = (const float*)d_in[3];
    const float* Q    = (const float*)d_in[4];
    const float* R    = (const float*)d_in[5];
    const float* W_hy = (const float*)d_in[6];
    const float* b_hy = (const float*)d_in[7];
    const float* W1p  = (const float*)d_in[8];
    const float* b1p  = (const float*)d_in[9];
    const float* W2p  = (const float*)d_in[10];
    const float* b2p  = (const float*)d_in[11];
    const float* W1f  = (const float*)d_in[12];
    const float* b1f  = (const float*)d_in[13];
    const float* W2f  = (const float*)d_in[14];
    const float* b2f  = (const float*)d_in[15];
    const float* W1y  = (const float*)d_in[16];
    const float* b1y  = (const float*)d_in[17];
    const float* W2y  = (const float*)d_in[18];
    const float* b2y  = (const float*)d_in[19];
    const float* Wih  = (const float*)d_in[20];
    const float* bih  = (const float*)d_in[21];
    const float* Whh  = (const float*)d_in[22];
    const float* bhh  = (const float*)d_in[23];
    const float* Wdec = (const float*)d_in[24];
    const float* bdec = (const float*)d_in[25];
    float* out = (float*)d_out;

    const int iters = out_size / BXT - 1;   // out = xs (BXT) + iters*BXT preds

    cudaFuncSetAttribute(step_kernel, cudaFuncAttributeMaxDynamicSharedMemorySize, SMEM_BYTES);

    float *xs0_p = nullptr, *hx_p = nullptr;
    cudaGetSymbolAddress((void**)&xs0_p, g_xs0);
    cudaGetSymbolAddress((void**)&hx_p, g_hxbuf);

    prep_small<<<1, 32>>>(F, H, Q, R, b2p, b2f, b2y);
    prep_nodes<<<(Bn*Tn + 127)/128, 128>>>(ys, H, W_hy, b_hy, W1y, b1y);

    dim3 grid(NTILES, Bn);
    const float* xs_in = xs0_p;
    const float* hx_in = hx0;
    for (int it = 0; it < iters; it++) {
        float* xs_out = out + (size_t)BXT * (1 + it);
        float* hx_out = hx_p + (size_t)(it & 1) * BHT;
        step_kernel<<<grid, TPB, SMEM_BYTES>>>(xs_in, hx_in, xs_out, hx_out,
                                               W1p, b1p, W2p,
                                               W1f, b1f, W2f,
                                               W1y, W2y,
                                               Wih, bih, Whh, bhh, Wdec, bdec);
        xs_in = xs_out;
        hx_in = hx_out;
    }
    // final xs = last iter_pred
    cudaMemcpyAsync(out, out + (size_t)BXT * iters, (size_t)BXT * sizeof(float),
                    cudaMemcpyDeviceToDevice);
}

// round 5
// speedup vs baseline: 1.0018x; 1.0018x over previous
#include <cuda_runtime.h>
#include <math.h>

#define Bn 16
#define Tn 1000
#define NT 64
#define TPB 256
#define NTILES 16
#define GAMMA_F 1e-4f
#define BXT (Bn*8*Tn)    /* 128000 */
#define BHT (Bn*48*Tn)   /* 768000 */

// ---------------- device scratch (static, allowed) ----------------
__device__ float g_xs0[BXT];
__device__ float g_cy[BXT];
__device__ float g_yterm[BHT];
__device__ float g_hxbuf[2][BHT];
__device__ float g_Qi[64], g_QiF[64], g_FtQi[64], g_FtQiF[64], g_HtRiH[64], g_HtRi[32];
__device__ float g_b2sum[48];

// ---------------- shared layout (floats) ----------------
constexpr int OFF_WP_H = 0;
constexpr int OFF_WP_N = 2352;
constexpr int OFF_WF_H = 4704;
constexpr int OFF_WF_N = 7056;
constexpr int OFF_WY_H = 9408;
constexpr int OFF_W2P  = 11760;
constexpr int OFF_W2F  = 14112;
constexpr int OFF_W2Y  = 16464;
constexpr int OFF_WIH  = 18816;
constexpr int OFF_WHH  = 25872;
constexpr int OFF_WP_M = 32928;
constexpr int OFF_WF_M = 33312;
constexpr int OFF_WY_M = 33696;
constexpr int OFF_WDEC = 34080;
constexpr int OFF_B1P  = 34464;
constexpr int OFF_B1F  = 34512;
constexpr int OFF_B2S  = 34560;
constexpr int OFF_BIH  = 34608;
constexpr int OFF_BHH  = 34752;
constexpr int OFF_BDEC = 34896;
constexpr int OFF_SQI    = 34904;
constexpr int OFF_SQIF   = 34968;
constexpr int OFF_SFTQI  = 35032;
constexpr int OFF_SFTQIF = 35096;
constexpr int OFF_SHTRIH = 35160;
constexpr int OFF_HSH  = 35224;   // 48 x 66 (halo)
constexpr int OFF_XSH  = 38392;   // 8 x 66 (halo)
constexpr int OFF_MP   = 38920;   // 8 x 64
constexpr int OFF_MF   = 39432;
constexpr int OFF_MY   = 39944;
constexpr int OFF_RP   = 40456;   // 48 x 64
constexpr int OFF_RF   = 43528;
constexpr int OFF_RY   = 46600;
constexpr int OFF_AGG  = 49672;
constexpr int SMEM_FLOATS = 52744;
constexpr int SMEM_BYTES  = SMEM_FLOATS * 4;  // 210,976 B

// ---------------- small-matrix prep (fp64 Gauss-Jordan, one thread) ----------------
__device__ void gj_invert(double* a, double* inv, int n) {
    for (int i = 0; i < n; i++)
        for (int j = 0; j < n; j++) inv[i*n+j] = (i == j) ? 1.0 : 0.0;
    for (int c = 0; c < n; c++) {
        int piv = c; double best = fabs(a[c*n+c]);
        for (int r = c+1; r < n; r++) { double v = fabs(a[r*n+c]); if (v > best) { best = v; piv = r; } }
        if (piv != c) {
            for (int j = 0; j < n; j++) {
                double t = a[c*n+j]; a[c*n+j] = a[piv*n+j]; a[piv*n+j] = t;
                t = inv[c*n+j]; inv[c*n+j] = inv[piv*n+j]; inv[piv*n+j] = t;
            }
        }
        double ip = 1.0 / a[c*n+c];
        for (int j = 0; j < n; j++) { a[c*n+j] *= ip; inv[c*n+j] *= ip; }
        for (int r = 0; r < n; r++) if (r != c) {
            double f = a[r*n+c];
            if (f != 0.0) for (int j = 0; j < n; j++) {
                a[r*n+j] -= f * a[c*n+j];
                inv[r*n+j] -= f * inv[c*n+j];
            }
        }
    }
}

__global__ void prep_small(const float* __restrict__ F, const float* __restrict__ H,
                           const float* __restrict__ Q, const float* __restrict__ R,
                           const float* __restrict__ b2p, const float* __restrict__ b2f,
                           const float* __restrict__ b2y) {
    if (threadIdx.x != 0 || blockIdx.x != 0) return;
    double Qd[64], Qi[64], Rd[16], Ri[16], Fd[64], Hd[32];
    for (int i = 0; i < 64; i++) Qd[i] = (double)Q[i];
    for (int i = 0; i < 16; i++) Rd[i] = (double)R[i];
    for (int i = 0; i < 64; i++) Fd[i] = (double)F[i];
    for (int i = 0; i < 32; i++) Hd[i] = (double)H[i];
    gj_invert(Qd, Qi, 8);
    gj_invert(Rd, Ri, 4);

    double QiF[64], FtQi[64], FtQiF[64], HtRi[32], HtRiH[64];
    for (int i = 0; i < 8; i++) for (int j = 0; j < 8; j++) {
        double s = 0; for (int k = 0; k < 8; k++) s += Qi[i*8+k] * Fd[k*8+j];
        QiF[i*8+j] = s;
    }
    for (int i = 0; i < 8; i++) for (int j = 0; j < 8; j++) {
        double s = 0; for (int k = 0; k < 8; k++) s += Fd[k*8+i] * Qi[k*8+j];
        FtQi[i*8+j] = s;
    }
    for (int i = 0; i < 8; i++) for (int j = 0; j < 8; j++) {
        double s = 0; for (int k = 0; k < 8; k++) s += FtQi[i*8+k] * Fd[k*8+j];
        FtQiF[i*8+j] = s;
    }
    for (int i = 0; i < 8; i++) for (int z = 0; z < 4; z++) {
        double s = 0; for (int y = 0; y < 4; y++) s += Hd[y*8+i] * Ri[y*4+z];
        HtRi[i*4+z] = s;
    }
    for (int i = 0; i < 8; i++) for (int j = 0; j < 8; j++) {
        double s = 0; for (int z = 0; z < 4; z++) s += HtRi[i*4+z] * Hd[z*8+j];
        HtRiH[i*8+j] = s;
    }
    for (int i = 0; i < 64; i++) { g_Qi[i] = (float)Qi[i]; g_QiF[i] = (float)QiF[i];
                                   g_FtQi[i] = (float)FtQi[i]; g_FtQiF[i] = (float)FtQiF[i];
                                   g_HtRiH[i] = (float)HtRiH[i]; }
    for (int i = 0; i < 32; i++) g_HtRi[i] = (float)HtRi[i];
    for (int o = 0; o < 48; o++) g_b2sum[o] = b2p[o] + b2f[o] + b2y[o];
}

// ---------------- per-node iteration-invariant prep ----------------
__global__ void prep_nodes(const float* __restrict__ ys, const float* __restrict__ H,
                           const float* __restrict__ W_hy, const float* __restrict__ b_hy,
                           const float* __restrict__ W1y, const float* __restrict__ b1y) {
    int node = blockIdx.x * blockDim.x + threadIdx.x;
    if (node >= Bn * Tn) return;
    int b = node / Tn, t = node - b * Tn;
    float yv[4];
    #pragma unroll
    for (int z = 0; z < 4; z++) yv[z] = ys[(b*Tn + t)*4 + z];

    #pragma unroll
    for (int i = 0; i < 8; i++) {
        float s0 = 0.f, s1 = 0.f;
        #pragma unroll
        for (int y = 0; y < 4; y++) { s0 = fmaf(H[y*8+i], yv[y], s0); s1 = fmaf(g_HtRi[i*4+y], yv[y], s1); }
        g_xs0[(b*8+i)*Tn + t] = s0;
        g_cy[(b*8+i)*Tn + t] = s1;
    }
    float hy[48];
    #pragma unroll
    for (int o = 0; o < 48; o++) {
        float s = b_hy[o];
        #pragma unroll
        for (int y = 0; y < 4; y++) s = fmaf(W_hy[o*4+y], yv[y], s);
        hy[o] = s;
    }
    for (int o = 0; o < 48; o++) {
        float s = b1y[o];
        #pragma unroll
        for (int k = 0; k < 48; k++) s = fmaf(W1y[o*104 + 48 + k], hy[k], s);
        g_yterm[(b*48+o)*Tn + t] = s;
    }
}

// ---------------- GEMM fragments ----------------
__device__ __forceinline__ void gemm48(const float* __restrict__ W, const float* __restrict__ inp,
                                       int ldi, int off, int ty, int nb,
                                       float a0[4], float a1[4], float a2[4]) {
    #pragma unroll 4
    for (int k = 0; k < 48; k++) {
        float w0 = W[ty*49 + k], w1 = W[(ty+16)*49 + k], w2 = W[(ty+32)*49 + k];
        #pragma unroll
        for (int nn = 0; nn < 4; nn++) {
            float x = inp[k*ldi + off + nb + nn];
            a0[nn] = fmaf(w0, x, a0[nn]);
            a1[nn] = fmaf(w1, x, a1[nn]);
            a2[nn] = fmaf(w2, x, a2[nn]);
        }
    }
}

__device__ __forceinline__ void gemm48v(const float* __restrict__ W, const float* __restrict__ inp,
                                        int ty, int nb, float a0[4], float a1[4], float a2[4]) {
    #pragma unroll 4
    for (int k = 0; k < 48; k++) {
        float w0 = W[ty*49 + k], w1 = W[(ty+16)*49 + k], w2 = W[(ty+32)*49 + k];
        float4 xv = *reinterpret_cast<const float4*>(&inp[k*64 + nb]);
        a0[0] = fmaf(w0, xv.x, a0[0]); a0[1] = fmaf(w0, xv.y, a0[1]);
        a0[2] = fmaf(w0, xv.z, a0[2]); a0[3] = fmaf(w0, xv.w, a0[3]);
        a1[0] = fmaf(w1, xv.x, a1[0]); a1[1] = fmaf(w1, xv.y, a1[1]);
        a1[2] = fmaf(w1, xv.z, a1[2]); a1[3] = fmaf(w1, xv.w, a1[3]);
        a2[0] = fmaf(w2, xv.x, a2[0]); a2[1] = fmaf(w2, xv.y, a2[1]);
        a2[2] = fmaf(w2, xv.z, a2[2]); a2[3] = fmaf(w2, xv.w, a2[3]);
    }
}

__device__ __forceinline__ void gemm8(const float* __restrict__ Wm, const float* __restrict__ msg,
                                      int ty, int nb, float a0[4], float a1[4], float a2[4]) {
    #pragma unroll
    for (int k = 0; k < 8; k++) {
        float w0 = Wm[ty*8 + k], w1 = Wm[(ty+16)*8 + k], w2 = Wm[(ty+32)*8 + k];
        float4 xv = *reinterpret_cast<const float4*>(&msg[k*64 + nb]);
        a0[0] = fmaf(w0, xv.x, a0[0]); a0[1] = fmaf(w0, xv.y, a0[1]);
        a0[2] = fmaf(w0, xv.z, a0[2]); a0[3] = fmaf(w0, xv.w, a0[3]);
        a1[0] = fmaf(w1, xv.x, a1[0]); a1[1] = fmaf(w1, xv.y, a1[1]);
        a1[2] = fmaf(w1, xv.z, a1[2]); a1[3] = fmaf(w1, xv.w, a1[3]);
        a2[0] = fmaf(w2, xv.x, a2[0]); a2[1] = fmaf(w2, xv.y, a2[1]);
        a2[2] = fmaf(w2, xv.z, a2[2]); a2[3] = fmaf(w2, xv.w, a2[3]);
    }
}

__device__ __forceinline__ float sigmf(float x) { return 1.f / (1.f + __expf(-x)); }
__device__ __forceinline__ float tanhfast(float x) { return 1.f - 2.f / (__expf(2.f * x) + 1.f); }

// ---------------- the iteration step ----------------
__global__ void __launch_bounds__(TPB, 1)
step_kernel(const float* __restrict__ xs_in, const float* __restrict__ hx_in,
            float* __restrict__ xs_out, float* __restrict__ hx_out,
            const float* __restrict__ W1p, const float* __restrict__ b1p,
            const float* __restrict__ W2p,
            const float* __restrict__ W1f, const float* __restrict__ b1f,
            const float* __restrict__ W2f,
            const float* __restrict__ W1y,
            const float* __restrict__ W2y,
            const float* __restrict__ Wih, const float* __restrict__ bih,
            const float* __restrict__ Whh, const float* __restrict__ bhh,
            const float* __restrict__ Wdec, const float* __restrict__ bdec) {
    extern __shared__ float sm[];
    float* Wp_h = sm + OFF_WP_H;  float* Wp_n = sm + OFF_WP_N;
    float* Wf_h = sm + OFF_WF_H;  float* Wf_n = sm + OFF_WF_N;
    float* Wy_h = sm + OFF_WY_H;
    float* W2p_s = sm + OFF_W2P;  float* W2f_s = sm + OFF_W2F;  float* W2y_s = sm + OFF_W2Y;
    float* Wih_s = sm + OFF_WIH;  float* Whh_s = sm + OFF_WHH;
    float* Wp_m = sm + OFF_WP_M;  float* Wf_m = sm + OFF_WF_M;  float* Wy_m = sm + OFF_WY_M;
    float* Wdec_s = sm + OFF_WDEC;
    float* b1p_s = sm + OFF_B1P;  float* b1f_s = sm + OFF_B1F;  float* b2s_s = sm + OFF_B2S;
    float* bih_s = sm + OFF_BIH;  float* bhh_s = sm + OFF_BHH;  float* bdec_s = sm + OFF_BDEC;
    float* sQi = sm + OFF_SQI;    float* sQiF = sm + OFF_SQIF;
    float* sFtQi = sm + OFF_SFTQI; float* sFtQiF = sm + OFF_SFTQIF; float* sHtRiH = sm + OFF_SHTRIH;
    float* hsh = sm + OFF_HSH;    float* xsh = sm + OFF_XSH;
    float* mp_s = sm + OFF_MP;    float* mf_s = sm + OFF_MF;    float* my_s = sm + OFF_MY;
    float* rp = sm + OFF_RP;      float* rf = sm + OFF_RF;      float* ry = sm + OFF_RY;
    float* agg_s = sm + OFF_AGG;

    const int tid = threadIdx.x;
    const int b = blockIdx.y;
    const int t0 = blockIdx.x * NT;

    // -- stage weights --
    for (int idx = tid; idx < 48*104; idx += TPB) {
        int o = idx / 104, c = idx - o*104;
        float vp = W1p[idx], vf = W1f[idx], vy = W1y[idx];
        if (c < 48)       { Wp_h[o*49+c] = vp; Wf_h[o*49+c] = vf; Wy_h[o*49+c] = vy; }
        else if (c < 96)  { int cc = c-48; Wp_n[o*49+cc] = vp; Wf_n[o*49+cc] = vf; }
        else              { int cc = c-96; Wp_m[o*8+cc] = vp; Wf_m[o*8+cc] = vf; Wy_m[o*8+cc] = vy; }
    }
    for (int idx = tid; idx < 48*48; idx += TPB) {
        int o = idx / 48, k = idx - o*48;
        W2p_s[o*49+k] = W2p[idx]; W2f_s[o*49+k] = W2f[idx]; W2y_s[o*49+k] = W2y[idx];
    }
    for (int idx = tid; idx < 144*48; idx += TPB) {
        int o = idx / 48, k = idx - o*48;
        Wih_s[o*49+k] = Wih[idx]; Whh_s[o*49+k] = Whh[idx];
    }
    for (int idx = tid; idx < 384; idx += TPB) Wdec_s[idx] = Wdec[idx];
    if (tid < 48) { b1p_s[tid] = b1p[tid]; b1f_s[tid] = b1f[tid]; b2s_s[tid] = g_b2sum[tid]; }
    for (int idx = tid; idx < 144; idx += TPB) { bih_s[idx] = bih[idx]; bhh_s[idx] = bhh[idx]; }
    if (tid < 8) bdec_s[tid] = bdec[tid];
    for (int idx = tid; idx < 64; idx += TPB) {
        sQi[idx] = g_Qi[idx]; sQiF[idx] = g_QiF[idx]; sFtQi[idx] = g_FtQi[idx];
        sFtQiF[idx] = g_FtQiF[idx]; sHtRiH[idx] = g_HtRiH[idx];
    }
    // -- stage state tiles with halo --
    for (int idx = tid; idx < 48*66; idx += TPB) {
        int k = idx / 66, c = idx - k*66; int t = t0 + c - 1;
        hsh[idx] = (t >= 0 && t < Tn) ? hx_in[(b*48+k)*Tn + t] : 0.f;
    }
    for (int idx = tid; idx < 8*66; idx += TPB) {
        int k = idx / 66, c = idx - k*66; int t = t0 + c - 1;
        xsh[idx] = (t >= 0 && t < Tn) ? xs_in[(b*8+k)*Tn + t] : 0.f;
    }
    __syncthreads();

    // -- messages --
    #pragma unroll
    for (int rep = 0; rep < 2; rep++) {
        int item = tid + rep*TPB;
        int i = item >> 6, n = item & 63, t = t0 + n;
        bool valid = t < Tn;
        float accp = 0.f, accf = 0.f;
        float accy = valid ? g_cy[(b*8+i)*Tn + t] : 0.f;
        #pragma unroll
        for (int j = 0; j < 8; j++) {
            float xc = xsh[j*66 + 1 + n];
            accp = fmaf(-sQi[i*8+j], xc, accp);
            accp = fmaf(sQiF[i*8+j], xsh[j*66 + n], accp);
            accf = fmaf(sFtQi[i*8+j], xsh[j*66 + 2 + n], accf);
            accf = fmaf(-sFtQiF[i*8+j], xc, accf);
            accy = fmaf(-sHtRiH[i*8+j], xc, accy);
        }
        mp_s[i*64+n] = (valid && t > 0) ? accp : 0.f;
        mf_s[i*64+n] = (t < Tn-1) ? accf : 0.f;
        my_s[i*64+n] = valid ? accy : 0.f;
    }
    __syncthreads();

    const int ty = tid >> 4, tx = tid & 15, nb = 4*tx;

    // -- edge past --
    {
        float a0[4], a1[4], a2[4];
        #pragma unroll
        for (int nn = 0; nn < 4; nn++) { a0[nn] = b1p_s[ty]; a1[nn] = b1p_s[ty+16]; a2[nn] = b1p_s[ty+32]; }
        gemm48(Wp_h, hsh, 66, 1, ty, nb, a0, a1, a2);
        gemm48(Wp_n, hsh, 66, 0, ty, nb, a0, a1, a2);
        gemm8(Wp_m, mp_s, ty, nb, a0, a1, a2);
        *reinterpret_cast<float4*>(&rp[ty*64 + nb])      = make_float4(fmaxf(a0[0],0.f), fmaxf(a0[1],0.f), fmaxf(a0[2],0.f), fmaxf(a0[3],0.f));
        *reinterpret_cast<float4*>(&rp[(ty+16)*64 + nb]) = make_float4(fmaxf(a1[0],0.f), fmaxf(a1[1],0.f), fmaxf(a1[2],0.f), fmaxf(a1[3],0.f));
        *reinterpret_cast<float4*>(&rp[(ty+32)*64 + nb]) = make_float4(fmaxf(a2[0],0.f), fmaxf(a2[1],0.f), fmaxf(a2[2],0.f), fmaxf(a2[3],0.f));
    }
    // -- edge future --
    {
        float a0[4], a1[4], a2[4];
        #pragma unroll
        for (int nn = 0; nn < 4; nn++) { a0[nn] = b1f_s[ty]; a1[nn] = b1f_s[ty+16]; a2[nn] = b1f_s[ty+32]; }
        gemm48(Wf_h, hsh, 66, 1, ty, nb, a0, a1, a2);
        gemm48(Wf_n, hsh, 66, 2, ty, nb, a0, a1, a2);
        gemm8(Wf_m, mf_s, ty, nb, a0, a1, a2);
        *reinterpret_cast<float4*>(&rf[ty*64 + nb])      = make_float4(fmaxf(a0[0],0.f), fmaxf(a0[1],0.f), fmaxf(a0[2],0.f), fmaxf(a0[3],0.f));
        *reinterpret_cast<float4*>(&rf[(ty+16)*64 + nb]) = make_float4(fmaxf(a1[0],0.f), fmaxf(a1[1],0.f), fmaxf(a1[2],0.f), fmaxf(a1[3],0.f));
        *reinterpret_cast<float4*>(&rf[(ty+32)*64 + nb]) = make_float4(fmaxf(a2[0],0.f), fmaxf(a2[1],0.f), fmaxf(a2[2],0.f), fmaxf(a2[3],0.f));
    }
    // -- edge y (hy-part + b1y precomputed in g_yterm) --
    {
        float a0[4], a1[4], a2[4];
        #pragma unroll
        for (int nn = 0; nn < 4; nn++) {
            int t = t0 + nb + nn; bool v = t < Tn;
            a0[nn] = v ? g_yterm[(b*48 + ty)*Tn + t] : 0.f;
            a1[nn] = v ? g_yterm[(b*48 + ty+16)*Tn + t] : 0.f;
            a2[nn] = v ? g_yterm[(b*48 + ty+32)*Tn + t] : 0.f;
        }
        gemm48(Wy_h, hsh, 66, 1, ty, nb, a0, a1, a2);
        gemm8(Wy_m, my_s, ty, nb, a0, a1, a2);
        *reinterpret_cast<float4*>(&ry[ty*64 + nb])      = make_float4(fmaxf(a0[0],0.f), fmaxf(a0[1],0.f), fmaxf(a0[2],0.f), fmaxf(a0[3],0.f));
        *reinterpret_cast<float4*>(&ry[(ty+16)*64 + nb]) = make_float4(fmaxf(a1[0],0.f), fmaxf(a1[1],0.f), fmaxf(a1[2],0.f), fmaxf(a1[3],0.f));
        *reinterpret_cast<float4*>(&ry[(ty+32)*64 + nb]) = make_float4(fmaxf(a2[0],0.f), fmaxf(a2[1],0.f), fmaxf(a2[2],0.f), fmaxf(a2[3],0.f));
    }
    __syncthreads();

    // -- agg = W2p@rp + W2f@rf + W2y@ry + b2sum --
    {
        float a0[4], a1[4], a2[4];
        #pragma unroll
        for (int nn = 0; nn < 4; nn++) { a0[nn] = b2s_s[ty]; a1[nn] = b2s_s[ty+16]; a2[nn] = b2s_s[ty+32]; }
        gemm48v(W2p_s, rp, ty, nb, a0, a1, a2);
        gemm48v(W2f_s, rf, ty, nb, a0, a1, a2);
        gemm48v(W2y_s, ry, ty, nb, a0, a1, a2);
        *reinterpret_cast<float4*>(&agg_s[ty*64 + nb])      = make_float4(a0[0], a0[1], a0[2], a0[3]);
        *reinterpret_cast<float4*>(&agg_s[(ty+16)*64 + nb]) = make_float4(a1[0], a1[1], a1[2], a1[3]);
        *reinterpret_cast<float4*>(&agg_s[(ty+32)*64 + nb]) = make_float4(a2[0], a2[1], a2[2], a2[3]);
    }
    __syncthreads();

    // -- GRU --
    {
        float A[9][4], Bv[3][4];
        #pragma unroll
        for (int j = 0; j < 9; j++) {
            float bi = bih_s[ty + 16*j] + ((j < 6) ? bhh_s[ty + 16*j] : 0.f);
            #pragma unroll
            for (int nn = 0; nn < 4; nn++) A[j][nn] = bi;
        }
        #pragma unroll
        for (int jj = 0; jj < 3; jj++) {
            float bb = bhh_s[96 + ty + 16*jj];
            #pragma unroll
            for (int nn = 0; nn < 4; nn++) Bv[jj][nn] = bb;
        }
        #pragma unroll 2
        for (int k = 0; k < 48; k++) {
            float4 xv = *reinterpret_cast<const float4*>(&agg_s[k*64 + nb]);
            #pragma unroll
            for (int j = 0; j < 9; j++) {
                float w = Wih_s[(ty + 16*j)*49 + k];
                A[j][0] = fmaf(w, xv.x, A[j][0]); A[j][1] = fmaf(w, xv.y, A[j][1]);
                A[j][2] = fmaf(w, xv.z, A[j][2]); A[j][3] = fmaf(w, xv.w, A[j][3]);
            }
        }
        #pragma unroll 2
        for (int k = 0; k < 48; k++) {
            float h0 = hsh[k*66 + 1 + nb], h1 = hsh[k*66 + 2 + nb];
            float h2 = hsh[k*66 + 3 + nb], h3 = hsh[k*66 + 4 + nb];
            #pragma unroll
            for (int j = 0; j < 6; j++) {
                float w = Whh_s[(ty + 16*j)*49 + k];
                A[j][0] = fmaf(w, h0, A[j][0]); A[j][1] = fmaf(w, h1, A[j][1]);
                A[j][2] = fmaf(w, h2, A[j][2]); A[j][3] = fmaf(w, h3, A[j][3]);
            }
            #pragma unroll
            for (int jj = 0; jj < 3; jj++) {
                float w = Whh_s[(96 + ty + 16*jj)*49 + k];
                Bv[jj][0] = fmaf(w, h0, Bv[jj][0]); Bv[jj][1] = fmaf(w, h1, Bv[jj][1]);
                Bv[jj][2] = fmaf(w, h2, Bv[jj][2]); Bv[jj][3] = fmaf(w, h3, Bv[jj][3]);
            }
        }
        __syncthreads();  // all rp readers (agg phase) done before overwrite with hnew
        #pragma unroll
        for (int jj = 0; jj < 3; jj++) {
            int o = ty + 16*jj;
            #pragma unroll
            for (int nn = 0; nn < 4; nn++) {
                float r = sigmf(A[jj][nn]);
                float z = sigmf(A[3+jj][nn]);
                float ng = tanhfast(A[6+jj][nn] + r * Bv[jj][nn]);
                float hold = hsh[o*66 + 1 + nb + nn];
                float hv = (1.f - z)*ng + z*hold;
                rp[o*64 + nb + nn] = hv;  // hnew staged in rp
                int t = t0 + nb + nn;
                if (t < Tn) hx_out[(b*48+o)*Tn + t] = hv;
            }
        }
    }
    __syncthreads();

    // -- eps = W_dec @ hnew + b_dec; xs update --
    #pragma unroll
    for (int rep = 0; rep < 2; rep++) {
        int item = tid + rep*TPB;
        int i = item >> 6, n = item & 63, t = t0 + n;
        float e = bdec_s[i];
        #pragma unroll 8
        for (int k = 0; k < 48; k++) e = fmaf(Wdec_s[i*48+k], rp[k*64+n], e);
        if (t < Tn) {
            float xn = xsh[i*66 + 1 + n]
                     + GAMMA_F * (e + mp_s[i*64+n] + mf_s[i*64+n] + my_s[i*64+n]);
            xs_out[(b*8+i)*Tn + t] = xn;
        }
    }
}

// ---------------- host ----------------
extern "C" void kernel_launch(void* const* d_in, const int* in_sizes, int n_in,
                              void* d_out, int out_size) {
    const float* ys   = (const float*)d_in[0];
    const float* hx0  = (const float*)d_in[1];
    const float* F    = (const float*)d_in[2];
    const float* H    = (const float*)d_in[3];
    const float* Q    = (const float*)d_in[4];
    const float* R    = (const float*)d_in[5];
    const float* W_hy = (const float*)d_in[6];
    const float* b_hy = (const float*)d_in[7];
    const float* W1p  = (const float*)d_in[8];
    const float* b1p  = (const float*)d_in[9];
    const float* W2p  = (const float*)d_in[10];
    const float* b2p  = (const float*)d_in[11];
    const float* W1f  = (const float*)d_in[12];
    const float* b1f  = (const float*)d_in[13];
    const float* W2f  = (const float*)d_in[14];
    const float* b2f  = (const float*)d_in[15];
    const float* W1y  = (const float*)d_in[16];
    const float* b1y  = (const float*)d_in[17];
    const float* W2y  = (const float*)d_in[18];
    const float* b2y  = (const float*)d_in[19];
    const float* Wih  = (const float*)d_in[20];
    const float* bih  = (const float*)d_in[21];
    const float* Whh  = (const float*)d_in[22];
    const float* bhh  = (const float*)d_in[23];
    const float* Wdec = (const float*)d_in[24];
    const float* bdec = (const float*)d_in[25];
    float* out = (float*)d_out;

    const int iters = out_size / BXT - 1;   // out = xs (BXT) + iters*BXT preds

    cudaFuncSetAttribute(step_kernel, cudaFuncAttributeMaxDynamicSharedMemorySize, SMEM_BYTES);

    float *xs0_p = nullptr, *hx_p = nullptr;
    cudaGetSymbolAddress((void**)&xs0_p, g_xs0);
    cudaGetSymbolAddress((void**)&hx_p, g_hxbuf);

    prep_small<<<1, 32>>>(F, H, Q, R, b2p, b2f, b2y);
    prep_nodes<<<(Bn*Tn + 127)/128, 128>>>(ys, H, W_hy, b_hy, W1y, b1y);

    dim3 grid(NTILES, Bn);
    const float* xs_in = xs0_p;
    const float* hx_in = hx0;
    for (int it = 0; it < iters; it++) {
        float* xs_out = out + (size_t)BXT * (1 + it);
        float* hx_out = hx_p + (size_t)(it & 1) * BHT;
        step_kernel<<<grid, TPB, SMEM_BYTES>>>(xs_in, hx_in, xs_out, hx_out,
                                               W1p, b1p, W2p,
                                               W1f, b1f, W2f,
                                               W1y, W2y,
                                               Wih, bih, Whh, bhh, Wdec, bdec);
        xs_in = xs_out;
        hx_in = hx_out;
    }
    // final xs = last iter_pred
    cudaMemcpyAsync(out, out + (size_t)BXT * iters, (size_t)BXT * sizeof(float),
                    cudaMemcpyDeviceToDevice);
}

// round 6
// speedup vs baseline: 1.4709x; 1.4683x over previous
#include <cuda_runtime.h>
#include <math.h>

#define Bn 16
#define Tn 1000
#define NT 128
#define TPB 512
#define NCHUNK 8
#define GAMMA_F 1e-4f
#define BXT (Bn*8*Tn)
#define BHT (Bn*48*Tn)

__device__ float g_xs0[BXT];
__device__ float g_cy[BXT];
__device__ float g_yterm[BHT];
__device__ float g_hxbuf[2][BHT];
__device__ float g_Qi[64], g_QiF[64], g_FtQi[64], g_FtQiF[64], g_HtRiH[64], g_HtRi[32];
__device__ float g_b2sum[48];

// shared layout (floats)
constexpr int OFF_WP_H=0, OFF_WP_N=2304, OFF_WF_H=4608, OFF_WF_N=6912, OFF_WY_H=9216;
constexpr int OFF_W2P=11520, OFF_W2F=13824, OFF_W2Y=16128;
constexpr int OFF_WIH=18432, OFF_WHH=25344;
constexpr int OFF_WP_M=32256, OFF_WF_M=32640, OFF_WY_M=33024, OFF_WDEC=33408;
constexpr int OFF_B1P=33792, OFF_B1F=33840, OFF_B2S=33888, OFF_BIH=33936, OFF_BHH=34080, OFF_BDEC=34224;
constexpr int OFF_SQI=34232, OFF_SQIF=34296, OFF_SFTQI=34360, OFF_SFTQIF=34424, OFF_SHTRIH=34488;
constexpr int OFF_HSH=34552;   // 48 x 130 halo
constexpr int OFF_XSH=40792;   // 8 x 130 halo
constexpr int OFF_MP=41832, OFF_MF=42856, OFF_MY=43880;  // 8 x 128 each
constexpr int OFF_R=44904;     // 48 x 128 (r -> agg -> hnew)
constexpr int SMEM_FLOATS=51048;
constexpr int SMEM_BYTES=SMEM_FLOATS*4;   // 204,192 B

__device__ void gj_invert(double* a, double* inv, int n) {
    for (int i = 0; i < n; i++)
        for (int j = 0; j < n; j++) inv[i*n+j] = (i == j) ? 1.0 : 0.0;
    for (int c = 0; c < n; c++) {
        int piv = c; double best = fabs(a[c*n+c]);
        for (int r = c+1; r < n; r++) { double v = fabs(a[r*n+c]); if (v > best) { best = v; piv = r; } }
        if (piv != c) for (int j = 0; j < n; j++) {
            double t = a[c*n+j]; a[c*n+j] = a[piv*n+j]; a[piv*n+j] = t;
            t = inv[c*n+j]; inv[c*n+j] = inv[piv*n+j]; inv[piv*n+j] = t;
        }
        double ip = 1.0 / a[c*n+c];
        for (int j = 0; j < n; j++) { a[c*n+j] *= ip; inv[c*n+j] *= ip; }
        for (int r = 0; r < n; r++) if (r != c) {
            double f = a[r*n+c];
            if (f != 0.0) for (int j = 0; j < n; j++) {
                a[r*n+j] -= f * a[c*n+j]; inv[r*n+j] -= f * inv[c*n+j];
            }
        }
    }
}

__global__ void prep_small(const float* __restrict__ F, const float* __restrict__ H,
                           const float* __restrict__ Q, const float* __restrict__ R,
                           const float* __restrict__ b2p, const float* __restrict__ b2f,
                           const float* __restrict__ b2y) {
    if (threadIdx.x != 0 || blockIdx.x != 0) return;
    double Qd[64], Qi[64], Rd[16], Ri[16], Fd[64], Hd[32];
    for (int i = 0; i < 64; i++) Qd[i] = (double)Q[i];
    for (int i = 0; i < 16; i++) Rd[i] = (double)R[i];
    for (int i = 0; i < 64; i++) Fd[i] = (double)F[i];
    for (int i = 0; i < 32; i++) Hd[i] = (double)H[i];
    gj_invert(Qd, Qi, 8); gj_invert(Rd, Ri, 4);
    double QiF[64], FtQi[64], FtQiF[64], HtRi[32], HtRiH[64];
    for (int i = 0; i < 8; i++) for (int j = 0; j < 8; j++) {
        double s = 0; for (int k = 0; k < 8; k++) s += Qi[i*8+k]*Fd[k*8+j]; QiF[i*8+j] = s; }
    for (int i = 0; i < 8; i++) for (int j = 0; j < 8; j++) {
        double s = 0; for (int k = 0; k < 8; k++) s += Fd[k*8+i]*Qi[k*8+j]; FtQi[i*8+j] = s; }
    for (int i = 0; i < 8; i++) for (int j = 0; j < 8; j++) {
        double s = 0; for (int k = 0; k < 8; k++) s += FtQi[i*8+k]*Fd[k*8+j]; FtQiF[i*8+j] = s; }
    for (int i = 0; i < 8; i++) for (int z = 0; z < 4; z++) {
        double s = 0; for (int y = 0; y < 4; y++) s += Hd[y*8+i]*Ri[y*4+z]; HtRi[i*4+z] = s; }
    for (int i = 0; i < 8; i++) for (int j = 0; j < 8; j++) {
        double s = 0; for (int z = 0; z < 4; z++) s += HtRi[i*4+z]*Hd[z*8+j]; HtRiH[i*8+j] = s; }
    for (int i = 0; i < 64; i++) { g_Qi[i]=(float)Qi[i]; g_QiF[i]=(float)QiF[i];
        g_FtQi[i]=(float)FtQi[i]; g_FtQiF[i]=(float)FtQiF[i]; g_HtRiH[i]=(float)HtRiH[i]; }
    for (int i = 0; i < 32; i++) g_HtRi[i] = (float)HtRi[i];
    for (int o = 0; o < 48; o++) g_b2sum[o] = b2p[o] + b2f[o] + b2y[o];
}

__global__ void prep_nodes(const float* __restrict__ ys, const float* __restrict__ H,
                           const float* __restrict__ W_hy, const float* __restrict__ b_hy,
                           const float* __restrict__ W1y, const float* __restrict__ b1y) {
    int node = blockIdx.x * blockDim.x + threadIdx.x;
    if (node >= Bn * Tn) return;
    int b = node / Tn, t = node - b * Tn;
    float yv[4];
    #pragma unroll
    for (int z = 0; z < 4; z++) yv[z] = ys[(b*Tn + t)*4 + z];
    #pragma unroll
    for (int i = 0; i < 8; i++) {
        float s0 = 0.f, s1 = 0.f;
        #pragma unroll
        for (int y = 0; y < 4; y++) { s0 = fmaf(H[y*8+i], yv[y], s0); s1 = fmaf(g_HtRi[i*4+y], yv[y], s1); }
        g_xs0[(b*8+i)*Tn + t] = s0;
        g_cy[(b*8+i)*Tn + t] = s1;
    }
    float hy[48];
    #pragma unroll
    for (int o = 0; o < 48; o++) {
        float s = b_hy[o];
        #pragma unroll
        for (int y = 0; y < 4; y++) s = fmaf(W_hy[o*4+y], yv[y], s);
        hy[o] = s;
    }
    for (int o = 0; o < 48; o++) {
        float s = b1y[o];
        #pragma unroll
        for (int k = 0; k < 48; k++) s = fmaf(W1y[o*104 + 48 + k], hy[k], s);
        g_yterm[(b*48+o)*Tn + t] = s;
    }
}

__device__ __forceinline__ float sigmf(float x) { return 1.f / (1.f + __expf(-x)); }
__device__ __forceinline__ float tanhfast(float x) { return 1.f - 2.f / (__expf(2.f*x) + 1.f); }

// edge layer-1: acc += Wh @ hsh[center] (+ Wn @ hsh[shifted]) + Wm @ msg, relu -> r
// columns: lane tx handles c = tx + 32*nn (conflict-free stride-1 smem access)
template<bool HAS_N>
__device__ __forceinline__ void edge1(const float* __restrict__ Wh, int offh,
                                      const float* __restrict__ Wn, int offn,
                                      const float* __restrict__ Wm, const float* __restrict__ msg,
                                      const float* __restrict__ hsh, float* __restrict__ r,
                                      float acc[3][4], int ty, int tx) {
    #pragma unroll 2
    for (int k = 0; k < 48; k++) {
        float w0 = Wh[ty*48+k], w1 = Wh[(ty+16)*48+k], w2 = Wh[(ty+32)*48+k];
        const float* row = &hsh[k*130];
        #pragma unroll
        for (int nn = 0; nn < 4; nn++) {
            float x = row[offh + tx + 32*nn];
            acc[0][nn] = fmaf(w0, x, acc[0][nn]);
            acc[1][nn] = fmaf(w1, x, acc[1][nn]);
            acc[2][nn] = fmaf(w2, x, acc[2][nn]);
        }
        if (HAS_N) {
            float u0 = Wn[ty*48+k], u1 = Wn[(ty+16)*48+k], u2 = Wn[(ty+32)*48+k];
            #pragma unroll
            for (int nn = 0; nn < 4; nn++) {
                float x = row[offn + tx + 32*nn];
                acc[0][nn] = fmaf(u0, x, acc[0][nn]);
                acc[1][nn] = fmaf(u1, x, acc[1][nn]);
                acc[2][nn] = fmaf(u2, x, acc[2][nn]);
            }
        }
    }
    #pragma unroll
    for (int k = 0; k < 8; k++) {
        float w0 = Wm[ty*8+k], w1 = Wm[(ty+16)*8+k], w2 = Wm[(ty+32)*8+k];
        #pragma unroll
        for (int nn = 0; nn < 4; nn++) {
            float x = msg[k*128 + tx + 32*nn];
            acc[0][nn] = fmaf(w0, x, acc[0][nn]);
            acc[1][nn] = fmaf(w1, x, acc[1][nn]);
            acc[2][nn] = fmaf(w2, x, acc[2][nn]);
        }
    }
    #pragma unroll
    for (int j = 0; j < 3; j++) {
        int o = ty + 16*j;
        #pragma unroll
        for (int nn = 0; nn < 4; nn++) r[o*128 + tx + 32*nn] = fmaxf(acc[j][nn], 0.f);
    }
}

// agg += W2 @ r
__device__ __forceinline__ void layer2(const float* __restrict__ W2, const float* __restrict__ r,
                                       float agg[3][4], int ty, int tx) {
    #pragma unroll 2
    for (int k = 0; k < 48; k++) {
        float w0 = W2[ty*48+k], w1 = W2[(ty+16)*48+k], w2 = W2[(ty+32)*48+k];
        #pragma unroll
        for (int nn = 0; nn < 4; nn++) {
            float x = r[k*128 + tx + 32*nn];
            agg[0][nn] = fmaf(w0, x, agg[0][nn]);
            agg[1][nn] = fmaf(w1, x, agg[1][nn]);
            agg[2][nn] = fmaf(w2, x, agg[2][nn]);
        }
    }
}

__global__ void __launch_bounds__(TPB, 1)
step_kernel(const float* __restrict__ xs_in, const float* __restrict__ hx_in,
            float* __restrict__ xs_out, float* __restrict__ hx_out,
            const float* __restrict__ W1p, const float* __restrict__ b1p,
            const float* __restrict__ W2p,
            const float* __restrict__ W1f, const float* __restrict__ b1f,
            const float* __restrict__ W2f,
            const float* __restrict__ W1y, const float* __restrict__ W2y,
            const float* __restrict__ Wih, const float* __restrict__ bih,
            const float* __restrict__ Whh, const float* __restrict__ bhh,
            const float* __restrict__ Wdec, const float* __restrict__ bdec) {
    extern __shared__ float sm[];
    float* hsh = sm + OFF_HSH;  float* xsh = sm + OFF_XSH;
    float* mp_s = sm + OFF_MP;  float* mf_s = sm + OFF_MF;  float* my_s = sm + OFF_MY;
    float* r = sm + OFF_R;

    const int tid = threadIdx.x;
    const int b = blockIdx.y;
    const int t0 = blockIdx.x * NT;

    // stage weights (stride-48; reads are warp-uniform broadcasts later)
    for (int idx = tid; idx < 48*104; idx += TPB) {
        int o = idx / 104, c = idx - o*104;
        float vp = W1p[idx], vf = W1f[idx], vy = W1y[idx];
        if (c < 48) { sm[OFF_WP_H+o*48+c]=vp; sm[OFF_WF_H+o*48+c]=vf; sm[OFF_WY_H+o*48+c]=vy; }
        else if (c < 96) { int cc=c-48; sm[OFF_WP_N+o*48+cc]=vp; sm[OFF_WF_N+o*48+cc]=vf; }
        else { int cc=c-96; sm[OFF_WP_M+o*8+cc]=vp; sm[OFF_WF_M+o*8+cc]=vf; sm[OFF_WY_M+o*8+cc]=vy; }
    }
    for (int idx = tid; idx < 48*48; idx += TPB) {
        sm[OFF_W2P+idx]=W2p[idx]; sm[OFF_W2F+idx]=W2f[idx]; sm[OFF_W2Y+idx]=W2y[idx];
    }
    for (int idx = tid; idx < 144*48; idx += TPB) {
        sm[OFF_WIH+idx]=Wih[idx]; sm[OFF_WHH+idx]=Whh[idx];
    }
    for (int idx = tid; idx < 384; idx += TPB) sm[OFF_WDEC+idx]=Wdec[idx];
    if (tid < 48) { sm[OFF_B1P+tid]=b1p[tid]; sm[OFF_B1F+tid]=b1f[tid]; sm[OFF_B2S+tid]=g_b2sum[tid]; }
    for (int idx = tid; idx < 144; idx += TPB) { sm[OFF_BIH+idx]=bih[idx]; sm[OFF_BHH+idx]=bhh[idx]; }
    if (tid < 8) sm[OFF_BDEC+tid]=bdec[tid];
    for (int idx = tid; idx < 64; idx += TPB) {
        sm[OFF_SQI+idx]=g_Qi[idx]; sm[OFF_SQIF+idx]=g_QiF[idx]; sm[OFF_SFTQI+idx]=g_FtQi[idx];
        sm[OFF_SFTQIF+idx]=g_FtQiF[idx]; sm[OFF_SHTRIH+idx]=g_HtRiH[idx];
    }
    // stage state (halo: col c -> t = t0 + c - 1)
    for (int idx = tid; idx < 48*130; idx += TPB) {
        int k = idx / 130, c = idx - k*130; int t = t0 + c - 1;
        hsh[idx] = (t >= 0 && t < Tn) ? hx_in[(b*48+k)*Tn + t] : 0.f;
    }
    for (int idx = tid; idx < 8*130; idx += TPB) {
        int k = idx / 130, c = idx - k*130; int t = t0 + c - 1;
        xsh[idx] = (t >= 0 && t < Tn) ? xs_in[(b*8+k)*Tn + t] : 0.f;
    }
    __syncthreads();

    // messages (1024 items)
    #pragma unroll
    for (int rep = 0; rep < 2; rep++) {
        int item = tid + rep*TPB;
        int i = item >> 7, n = item & 127, t = t0 + n;
        bool valid = t < Tn;
        float accp = 0.f, accf = 0.f;
        float accy = valid ? g_cy[(b*8+i)*Tn + t] : 0.f;
        #pragma unroll
        for (int j = 0; j < 8; j++) {
            float xc = xsh[j*130 + 1 + n];
            accp = fmaf(-sm[OFF_SQI+i*8+j], xc, accp);
            accp = fmaf(sm[OFF_SQIF+i*8+j], xsh[j*130 + n], accp);
            accf = fmaf(sm[OFF_SFTQI+i*8+j], xsh[j*130 + 2 + n], accf);
            accf = fmaf(-sm[OFF_SFTQIF+i*8+j], xc, accf);
            accy = fmaf(-sm[OFF_SHTRIH+i*8+j], xc, accy);
        }
        mp_s[i*128+n] = (valid && t > 0) ? accp : 0.f;
        mf_s[i*128+n] = (t < Tn-1) ? accf : 0.f;
        my_s[i*128+n] = valid ? accy : 0.f;
    }
    __syncthreads();

    const int ty = tid >> 5, tx = tid & 31;
    float agg[3][4];
    #pragma unroll
    for (int nn = 0; nn < 4; nn++) {
        agg[0][nn]=sm[OFF_B2S+ty]; agg[1][nn]=sm[OFF_B2S+ty+16]; agg[2][nn]=sm[OFF_B2S+ty+32];
    }
    {   // edge past
        float acc[3][4];
        #pragma unroll
        for (int nn = 0; nn < 4; nn++) {
            acc[0][nn]=sm[OFF_B1P+ty]; acc[1][nn]=sm[OFF_B1P+ty+16]; acc[2][nn]=sm[OFF_B1P+ty+32];
        }
        edge1<true>(sm+OFF_WP_H, 1, sm+OFF_WP_N, 0, sm+OFF_WP_M, mp_s, hsh, r, acc, ty, tx);
    }
    __syncthreads();
    layer2(sm+OFF_W2P, r, agg, ty, tx);
    __syncthreads();
    {   // edge future
        float acc[3][4];
        #pragma unroll
        for (int nn = 0; nn < 4; nn++) {
            acc[0][nn]=sm[OFF_B1F+ty]; acc[1][nn]=sm[OFF_B1F+ty+16]; acc[2][nn]=sm[OFF_B1F+ty+32];
        }
        edge1<true>(sm+OFF_WF_H, 1, sm+OFF_WF_N, 2, sm+OFF_WF_M, mf_s, hsh, r, acc, ty, tx);
    }
    __syncthreads();
    layer2(sm+OFF_W2F, r, agg, ty, tx);
    __syncthreads();
    {   // edge y (hy-part precomputed in g_yterm)
        float acc[3][4];
        #pragma unroll
        for (int nn = 0; nn < 4; nn++) {
            int t = t0 + tx + 32*nn; bool v = t < Tn;
            acc[0][nn] = v ? g_yterm[(b*48+ty)*Tn + t] : 0.f;
            acc[1][nn] = v ? g_yterm[(b*48+ty+16)*Tn + t] : 0.f;
            acc[2][nn] = v ? g_yterm[(b*48+ty+32)*Tn + t] : 0.f;
        }
        edge1<false>(sm+OFF_WY_H, 1, nullptr, 0, sm+OFF_WY_M, my_s, hsh, r, acc, ty, tx);
    }
    __syncthreads();
    layer2(sm+OFF_W2Y, r, agg, ty, tx);
    __syncthreads();
    // spill agg into r
    #pragma unroll
    for (int j = 0; j < 3; j++) {
        int o = ty + 16*j;
        #pragma unroll
        for (int nn = 0; nn < 4; nn++) r[o*128 + tx + 32*nn] = agg[j][nn];
    }
    __syncthreads();

    // GRU
    {
        float A[9][4], Bv[3][4];
        #pragma unroll
        for (int j = 0; j < 9; j++) {
            float bi = sm[OFF_BIH+ty+16*j] + ((j < 6) ? sm[OFF_BHH+ty+16*j] : 0.f);
            #pragma unroll
            for (int nn = 0; nn < 4; nn++) A[j][nn] = bi;
        }
        #pragma unroll
        for (int jj = 0; jj < 3; jj++) {
            float bb = sm[OFF_BHH+96+ty+16*jj];
            #pragma unroll
            for (int nn = 0; nn < 4; nn++) Bv[jj][nn] = bb;
        }
        #pragma unroll 1
        for (int k = 0; k < 48; k++) {
            float x0 = r[k*128+tx], x1 = r[k*128+tx+32], x2 = r[k*128+tx+64], x3 = r[k*128+tx+96];
            #pragma unroll
            for (int j = 0; j < 9; j++) {
                float w = sm[OFF_WIH+(ty+16*j)*48+k];
                A[j][0]=fmaf(w,x0,A[j][0]); A[j][1]=fmaf(w,x1,A[j][1]);
                A[j][2]=fmaf(w,x2,A[j][2]); A[j][3]=fmaf(w,x3,A[j][3]);
            }
        }
        #pragma unroll 1
        for (int k = 0; k < 48; k++) {
            const float* row = &hsh[k*130 + 1];
            float h0 = row[tx], h1 = row[tx+32], h2 = row[tx+64], h3 = row[tx+96];
            #pragma unroll
            for (int j = 0; j < 6; j++) {
                float w = sm[OFF_WHH+(ty+16*j)*48+k];
                A[j][0]=fmaf(w,h0,A[j][0]); A[j][1]=fmaf(w,h1,A[j][1]);
                A[j][2]=fmaf(w,h2,A[j][2]); A[j][3]=fmaf(w,h3,A[j][3]);
            }
            #pragma unroll
            for (int jj = 0; jj < 3; jj++) {
                float w = sm[OFF_WHH+(96+ty+16*jj)*48+k];
                Bv[jj][0]=fmaf(w,h0,Bv[jj][0]); Bv[jj][1]=fmaf(w,h1,Bv[jj][1]);
                Bv[jj][2]=fmaf(w,h2,Bv[jj][2]); Bv[jj][3]=fmaf(w,h3,Bv[jj][3]);
            }
        }
        __syncthreads();   // all reads of r(=agg) and hsh done
        #pragma unroll
        for (int jj = 0; jj < 3; jj++) {
            int o = ty + 16*jj;
            #pragma unroll
            for (int nn = 0; nn < 4; nn++) {
                int c = tx + 32*nn;
                float rg = sigmf(A[jj][nn]);
                float z = sigmf(A[3+jj][nn]);
                float ng = tanhfast(A[6+jj][nn] + rg * Bv[jj][nn]);
                float hold = hsh[o*130 + 1 + c];
                float hv = (1.f - z)*ng + z*hold;
                r[o*128 + c] = hv;   // hnew
                int t = t0 + c;
                if (t < Tn) hx_out[(b*48+o)*Tn + t] = hv;
            }
        }
    }
    __syncthreads();

    // decoder + xs update
    #pragma unroll
    for (int rep = 0; rep < 2; rep++) {
        int item = tid + rep*TPB;
        int i = item >> 7, n = item & 127, t = t0 + n;
        float e = sm[OFF_BDEC+i];
        #pragma unroll 8
        for (int k = 0; k < 48; k++) e = fmaf(sm[OFF_WDEC+i*48+k], r[k*128+n], e);
        if (t < Tn) {
            float xn = xsh[i*130 + 1 + n]
                     + GAMMA_F * (e + mp_s[i*128+n] + mf_s[i*128+n] + my_s[i*128+n]);
            xs_out[(b*8+i)*Tn + t] = xn;
        }
    }
}

extern "C" void kernel_launch(void* const* d_in, const int* in_sizes, int n_in,
                              void* d_out, int out_size) {
    const float* ys   = (const float*)d_in[0];
    const float* hx0  = (const float*)d_in[1];
    const float* F    = (const float*)d_in[2];
    const float* H    = (const float*)d_in[3];
    const float* Q    = (const float*)d_in[4];
    const float* R    = (const float*)d_in[5];
    const float* W_hy = (const float*)d_in[6];
    const float* b_hy = (const float*)d_in[7];
    const float* W1p  = (const float*)d_in[8];
    const float* b1p  = (const float*)d_in[9];
    const float* W2p  = (const float*)d_in[10];
    const float* b2p  = (const float*)d_in[11];
    const float* W1f  = (const float*)d_in[12];
    const float* b1f  = (const float*)d_in[13];
    const float* W2f  = (const float*)d_in[14];
    const float* b2f  = (const float*)d_in[15];
    const float* W1y  = (const float*)d_in[16];
    const float* b1y  = (const float*)d_in[17];
    const float* W2y  = (const float*)d_in[18];
    const float* b2y  = (const float*)d_in[19];
    const float* Wih  = (const float*)d_in[20];
    const float* bih  = (const float*)d_in[21];
    const float* Whh  = (const float*)d_in[22];
    const float* bhh  = (const float*)d_in[23];
    const float* Wdec = (const float*)d_in[24];
    const float* bdec = (const float*)d_in[25];
    float* out = (float*)d_out;

    const int iters = out_size / BXT - 1;

    cudaFuncSetAttribute(step_kernel, cudaFuncAttributeMaxDynamicSharedMemorySize, SMEM_BYTES);

    float *xs0_p = nullptr, *hx_p = nullptr;
    cudaGetSymbolAddress((void**)&xs0_p, g_xs0);
    cudaGetSymbolAddress((void**)&hx_p, g_hxbuf);

    prep_small<<<1, 32>>>(F, H, Q, R, b2p, b2f, b2y);
    prep_nodes<<<(Bn*Tn + 127)/128, 128>>>(ys, H, W_hy, b_hy, W1y, b1y);

    dim3 grid(NCHUNK, Bn);
    const float* xs_in = xs0_p;
    const float* hx_in = hx0;
    for (int it = 0; it < iters; it++) {
        float* xs_out = out + (size_t)BXT * (1 + it);
        float* hx_out = hx_p + (size_t)(it & 1) * BHT;
        step_kernel<<<grid, TPB, SMEM_BYTES>>>(xs_in, hx_in, xs_out, hx_out,
                                               W1p, b1p, W2p, W1f, b1f, W2f,
                                               W1y, W2y, Wih, bih, Whh, bhh, Wdec, bdec);
        xs_in = xs_out;
        hx_in = hx_out;
    }
    cudaMemcpyAsync(out, out + (size_t)BXT * iters, (size_t)BXT * sizeof(float),
                    cudaMemcpyDeviceToDevice);
}

// round 7
// speedup vs baseline: 1.6475x; 1.1201x over previous
#include <cuda_runtime.h>
#include <math.h>
typedef unsigned long long ull;

#define Bn 16
#define Tn 1000
#define NT 128
#define TPB 512
#define NCHUNK 8
#define GAMMA_F 1e-4f
#define BXT (Bn*8*Tn)
#define BHT (Bn*48*Tn)

__device__ float g_xs0[BXT];
__device__ float g_cy[BXT];
__device__ float g_yterm[BHT];   // [b][t][48]
__device__ float g_hxbuf[2][BHT];
__device__ float g_Qi[64], g_QiF[64], g_FtQi[64], g_FtQiF[64], g_HtRiH[64], g_HtRi[32];
__device__ float g_b2sum[48];

// shared layout (floats); transposed weights: W_T[k*50 + o] (GRU: k*150 + row)
constexpr int WPH=0, WPN=2400, WFH=4800, WFN=7200, WYH=9600;
constexpr int W2Po=12000, W2Fo=14400, W2Yo=16800;
constexpr int WIHo=19200, WHHo=26400;
constexpr int WPM=33600, WFM=34000, WYM=34400, WDEC=34800;
constexpr int B1P=35184, B1F=35232, B2S=35280, BIH=35328, BHH=35472, BDEC=35616;
constexpr int SQI=35624, SQIF=35688, SFTQI=35752, SFTQIF=35816, SHTRIH=35880;
constexpr int HLo=35944, HRo=35992, HSH=36040;          // hsh 48x128
constexpr int XSH=42184;                                 // xsh 8x130 halo
constexpr int MPo=43224, MFo=44248, MYo=45272, RB=46296; // r 48x128
constexpr int SMEM_FLOATS=52440;
constexpr int SMEM_BYTES=SMEM_FLOATS*4;   // 209,760 B

__device__ __forceinline__ ull pack2(float a, float b){ull r;asm("mov.b64 %0,{%1,%2};":"=l"(r):"f"(a),"f"(b));return r;}
__device__ __forceinline__ void unpack2(ull v, float&a, float&b){asm("mov.b64 {%0,%1},%2;":"=f"(a),"=f"(b):"l"(v));}
__device__ __forceinline__ ull fma2(ull a, ull b, ull c){ull d;asm("fma.rn.f32x2 %0,%1,%2,%3;":"=l"(d):"l"(a),"l"(b),"l"(c));return d;}
__device__ __forceinline__ ull add2(ull a, ull b){ull d;asm("add.rn.f32x2 %0,%1,%2;":"=l"(d):"l"(a),"l"(b));return d;}
__device__ __forceinline__ float sigmf(float x){ return 1.f/(1.f+__expf(-x)); }
__device__ __forceinline__ float tanhfast(float x){ return 1.f - 2.f/(__expf(2.f*x)+1.f); }

__device__ void gj_invert(double* a, double* inv, int n) {
    for (int i = 0; i < n; i++) for (int j = 0; j < n; j++) inv[i*n+j] = (i==j)?1.0:0.0;
    for (int c = 0; c < n; c++) {
        int piv = c; double best = fabs(a[c*n+c]);
        for (int r = c+1; r < n; r++) { double v = fabs(a[r*n+c]); if (v > best) { best=v; piv=r; } }
        if (piv != c) for (int j = 0; j < n; j++) {
            double t=a[c*n+j]; a[c*n+j]=a[piv*n+j]; a[piv*n+j]=t;
            t=inv[c*n+j]; inv[c*n+j]=inv[piv*n+j]; inv[piv*n+j]=t;
        }
        double ip = 1.0/a[c*n+c];
        for (int j = 0; j < n; j++) { a[c*n+j]*=ip; inv[c*n+j]*=ip; }
        for (int r = 0; r < n; r++) if (r != c) {
            double f = a[r*n+c];
            if (f != 0.0) for (int j = 0; j < n; j++) { a[r*n+j]-=f*a[c*n+j]; inv[r*n+j]-=f*inv[c*n+j]; }
        }
    }
}

__global__ void prep_small(const float* __restrict__ F, const float* __restrict__ H,
                           const float* __restrict__ Q, const float* __restrict__ R,
                           const float* __restrict__ b2p, const float* __restrict__ b2f,
                           const float* __restrict__ b2y) {
    if (threadIdx.x != 0 || blockIdx.x != 0) return;
    double Qd[64], Qi[64], Rd[16], Ri[16], Fd[64], Hd[32];
    for (int i=0;i<64;i++) Qd[i]=(double)Q[i];
    for (int i=0;i<16;i++) Rd[i]=(double)R[i];
    for (int i=0;i<64;i++) Fd[i]=(double)F[i];
    for (int i=0;i<32;i++) Hd[i]=(double)H[i];
    gj_invert(Qd,Qi,8); gj_invert(Rd,Ri,4);
    double QiF[64], FtQi[64], FtQiF[64], HtRi[32], HtRiH[64];
    for (int i=0;i<8;i++) for (int j=0;j<8;j++){ double s=0; for(int k=0;k<8;k++) s+=Qi[i*8+k]*Fd[k*8+j]; QiF[i*8+j]=s; }
    for (int i=0;i<8;i++) for (int j=0;j<8;j++){ double s=0; for(int k=0;k<8;k++) s+=Fd[k*8+i]*Qi[k*8+j]; FtQi[i*8+j]=s; }
    for (int i=0;i<8;i++) for (int j=0;j<8;j++){ double s=0; for(int k=0;k<8;k++) s+=FtQi[i*8+k]*Fd[k*8+j]; FtQiF[i*8+j]=s; }
    for (int i=0;i<8;i++) for (int z=0;z<4;z++){ double s=0; for(int y=0;y<4;y++) s+=Hd[y*8+i]*Ri[y*4+z]; HtRi[i*4+z]=s; }
    for (int i=0;i<8;i++) for (int j=0;j<8;j++){ double s=0; for(int z=0;z<4;z++) s+=HtRi[i*4+z]*Hd[z*8+j]; HtRiH[i*8+j]=s; }
    for (int i=0;i<64;i++){ g_Qi[i]=(float)Qi[i]; g_QiF[i]=(float)QiF[i];
        g_FtQi[i]=(float)FtQi[i]; g_FtQiF[i]=(float)FtQiF[i]; g_HtRiH[i]=(float)HtRiH[i]; }
    for (int i=0;i<32;i++) g_HtRi[i]=(float)HtRi[i];
    for (int o=0;o<48;o++) g_b2sum[o]=b2p[o]+b2f[o]+b2y[o];
}

__global__ void prep_nodes(const float* __restrict__ ys, const float* __restrict__ H,
                           const float* __restrict__ W_hy, const float* __restrict__ b_hy,
                           const float* __restrict__ W1y, const float* __restrict__ b1y) {
    int node = blockIdx.x * blockDim.x + threadIdx.x;
    if (node >= Bn*Tn) return;
    int b = node / Tn, t = node - b*Tn;
    float yv[4];
    #pragma unroll
    for (int z=0;z<4;z++) yv[z] = ys[(b*Tn+t)*4+z];
    #pragma unroll
    for (int i=0;i<8;i++){
        float s0=0.f, s1=0.f;
        #pragma unroll
        for (int y=0;y<4;y++){ s0=fmaf(H[y*8+i],yv[y],s0); s1=fmaf(g_HtRi[i*4+y],yv[y],s1); }
        g_xs0[(b*8+i)*Tn+t]=s0; g_cy[(b*8+i)*Tn+t]=s1;
    }
    float hy[48];
    #pragma unroll
    for (int o=0;o<48;o++){
        float s=b_hy[o];
        #pragma unroll
        for (int y=0;y<4;y++) s=fmaf(W_hy[o*4+y],yv[y],s);
        hy[o]=s;
    }
    for (int o=0;o<48;o++){
        float s=b1y[o];
        #pragma unroll
        for (int k=0;k<48;k++) s=fmaf(W1y[o*104+48+k],hy[k],s);
        g_yterm[(b*Tn+t)*48+o]=s;   // [b][t][o]
    }
}

// edge layer-1, f32x2 row-pair scheme. SHIFT: -1 past, +1 fut, 0 none.
template<int SHIFT>
__device__ __forceinline__ void edge1v(const float* __restrict__ sm, int WHo_, int WNo_, int WMo_,
    const float* __restrict__ msg, const float* __restrict__ hsh, float* __restrict__ r,
    ull acc[3][2], int rbase, int lane, int cbase,
    const float* __restrict__ lsrc, int lstr, const float* __restrict__ rsrc, int rstr)
{
    #pragma unroll 2
    for (int k = 0; k < 48; k++) {
        float2 v = *(const float2*)&hsh[k*128 + cbase];
        ull b0 = pack2(v.x,v.x), b1 = pack2(v.y,v.y);
        #pragma unroll
        for (int p = 0; p < 3; p++) {
            ull wp = *(const ull*)&sm[WHo_ + k*50 + rbase + 2*p];
            acc[p][0] = fma2(wp,b0,acc[p][0]);
            acc[p][1] = fma2(wp,b1,acc[p][1]);
        }
        if (SHIFT != 0) {
            ull n0, n1;
            if (SHIFT < 0) {
                float pv = __shfl_up_sync(0xffffffffu, v.y, 1);
                if (lane == 0) pv = lsrc[k*lstr];
                n0 = pack2(pv,pv); n1 = b0;
            } else {
                float qv = __shfl_down_sync(0xffffffffu, v.x, 1);
                if (lane == 31) qv = rsrc[k*rstr];
                n0 = b1; n1 = pack2(qv,qv);
            }
            #pragma unroll
            for (int p = 0; p < 3; p++) {
                ull up = *(const ull*)&sm[WNo_ + k*50 + rbase + 2*p];
                acc[p][0] = fma2(up,n0,acc[p][0]);
                acc[p][1] = fma2(up,n1,acc[p][1]);
            }
        }
    }
    #pragma unroll
    for (int k = 0; k < 8; k++) {
        float2 m = *(const float2*)&msg[k*128 + cbase];
        ull b0 = pack2(m.x,m.x), b1 = pack2(m.y,m.y);
        #pragma unroll
        for (int p = 0; p < 3; p++) {
            ull wp = *(const ull*)&sm[WMo_ + k*50 + rbase + 2*p];
            acc[p][0] = fma2(wp,b0,acc[p][0]);
            acc[p][1] = fma2(wp,b1,acc[p][1]);
        }
    }
    #pragma unroll
    for (int p = 0; p < 3; p++) {
        float x0,x1,y0,y1;
        unpack2(acc[p][0],x0,y0); unpack2(acc[p][1],x1,y1);
        int o0 = rbase + 2*p;
        r[o0*128 + cbase]       = fmaxf(x0,0.f);
        r[o0*128 + cbase+1]     = fmaxf(x1,0.f);
        r[(o0+1)*128 + cbase]   = fmaxf(y0,0.f);
        r[(o0+1)*128 + cbase+1] = fmaxf(y1,0.f);
    }
}

__device__ __forceinline__ void layer2v(const float* __restrict__ sm, int W2o_,
    const float* __restrict__ r, ull agg[3][2], int rbase, int cbase)
{
    #pragma unroll 2
    for (int k = 0; k < 48; k++) {
        float2 v = *(const float2*)&r[k*128 + cbase];
        ull b0 = pack2(v.x,v.x), b1 = pack2(v.y,v.y);
        #pragma unroll
        for (int p = 0; p < 3; p++) {
            ull wp = *(const ull*)&sm[W2o_ + k*50 + rbase + 2*p];
            agg[p][0] = fma2(wp,b0,agg[p][0]);
            agg[p][1] = fma2(wp,b1,agg[p][1]);
        }
    }
}

__global__ void __launch_bounds__(TPB, 1)
step_kernel(const float* __restrict__ xs_in, const float* __restrict__ hx_in,
            float* __restrict__ xs_out, float* __restrict__ hx_out,
            const float* __restrict__ W1p, const float* __restrict__ b1p,
            const float* __restrict__ W2p,
            const float* __restrict__ W1f, const float* __restrict__ b1f,
            const float* __restrict__ W2f,
            const float* __restrict__ W1y, const float* __restrict__ W2y,
            const float* __restrict__ Wih, const float* __restrict__ bih,
            const float* __restrict__ Whh, const float* __restrict__ bhh,
            const float* __restrict__ Wdec, const float* __restrict__ bdec) {
    extern __shared__ float sm[];
    float* hsh = sm + HSH;  float* xsh = sm + XSH;  float* r = sm + RB;

    const int tid = threadIdx.x;
    const int b = blockIdx.y;
    const int t0 = blockIdx.x * NT;

    // stage weights transposed
    for (int idx = tid; idx < 48*104; idx += TPB) {
        int o = idx/104, c = idx - o*104;
        float vp = W1p[idx], vf = W1f[idx], vy = W1y[idx];
        if (c < 48) { sm[WPH+c*50+o]=vp; sm[WFH+c*50+o]=vf; sm[WYH+c*50+o]=vy; }
        else if (c < 96) { int cc=c-48; sm[WPN+cc*50+o]=vp; sm[WFN+cc*50+o]=vf; }
        else { int cc=c-96; sm[WPM+cc*50+o]=vp; sm[WFM+cc*50+o]=vf; sm[WYM+cc*50+o]=vy; }
    }
    for (int idx = tid; idx < 48*48; idx += TPB) {
        int o = idx/48, k = idx - o*48;
        sm[W2Po+k*50+o]=W2p[idx]; sm[W2Fo+k*50+o]=W2f[idx]; sm[W2Yo+k*50+o]=W2y[idx];
    }
    for (int idx = tid; idx < 144*48; idx += TPB) {
        int o = idx/48, k = idx - o*48;
        sm[WIHo+k*150+o]=Wih[idx]; sm[WHHo+k*150+o]=Whh[idx];
    }
    for (int idx = tid; idx < 384; idx += TPB) sm[WDEC+idx]=Wdec[idx];
    if (tid < 48) { sm[B1P+tid]=b1p[tid]; sm[B1F+tid]=b1f[tid]; sm[B2S+tid]=g_b2sum[tid]; }
    for (int idx = tid; idx < 144; idx += TPB) { sm[BIH+idx]=bih[idx]; sm[BHH+idx]=bhh[idx]; }
    if (tid < 8) sm[BDEC+tid]=bdec[tid];
    for (int idx = tid; idx < 64; idx += TPB) {
        sm[SQI+idx]=g_Qi[idx]; sm[SQIF+idx]=g_QiF[idx]; sm[SFTQI+idx]=g_FtQi[idx];
        sm[SFTQIF+idx]=g_FtQiF[idx]; sm[SHTRIH+idx]=g_HtRiH[idx];
    }
    // state: hsh 48x128 interior + hL/hR boundary columns; xsh 8x130 halo
    for (int idx = tid; idx < 48*128; idx += TPB) {
        int k = idx >> 7, c = idx & 127; int t = t0 + c;
        hsh[idx] = (t < Tn) ? hx_in[(b*48+k)*Tn + t] : 0.f;
    }
    if (tid < 48) {
        int tl = t0 - 1, tr = t0 + 128;
        sm[HLo+tid] = (tl >= 0) ? hx_in[(b*48+tid)*Tn + tl] : 0.f;
        sm[HRo+tid] = (tr < Tn) ? hx_in[(b*48+tid)*Tn + tr] : 0.f;
    }
    for (int idx = tid; idx < 8*130; idx += TPB) {
        int k = idx / 130, c = idx - k*130; int t = t0 + c - 1;
        xsh[idx] = (t >= 0 && t < Tn) ? xs_in[(b*8+k)*Tn + t] : 0.f;
    }
    __syncthreads();

    // messages
    #pragma unroll
    for (int rep = 0; rep < 2; rep++) {
        int item = tid + rep*TPB;
        int i = item >> 7, n = item & 127, t = t0 + n;
        bool valid = t < Tn;
        float accp = 0.f, accf = 0.f;
        float accy = valid ? g_cy[(b*8+i)*Tn + t] : 0.f;
        #pragma unroll
        for (int j = 0; j < 8; j++) {
            float xc = xsh[j*130 + 1 + n];
            accp = fmaf(-sm[SQI+i*8+j], xc, accp);
            accp = fmaf(sm[SQIF+i*8+j], xsh[j*130 + n], accp);
            accf = fmaf(sm[SFTQI+i*8+j], xsh[j*130 + 2 + n], accf);
            accf = fmaf(-sm[SFTQIF+i*8+j], xc, accf);
            accy = fmaf(-sm[SHTRIH+i*8+j], xc, accy);
        }
        sm[MPo + i*128+n] = (valid && t > 0) ? accp : 0.f;
        sm[MFo + i*128+n] = (t < Tn-1) ? accf : 0.f;
        sm[MYo + i*128+n] = valid ? accy : 0.f;
    }
    __syncthreads();

    const int w = tid >> 5, lane = tid & 31, cg = w & 1, rg = w >> 1;
    const int rbase = 6*rg, cbase = cg*64 + 2*lane;
    const float* lsrc; int lstr; const float* rsrc; int rstr;
    if (cg == 0) { lsrc = sm+HLo; lstr = 1; rsrc = hsh+64; rstr = 128; }
    else         { lsrc = hsh+63; lstr = 128; rsrc = sm+HRo; rstr = 1; }

    ull agg[3][2];
    #pragma unroll
    for (int p = 0; p < 3; p++) {
        ull bp = *(const ull*)&sm[B2S + rbase + 2*p];
        agg[p][0] = bp; agg[p][1] = bp;
    }
    {   // edge past
        ull acc[3][2];
        #pragma unroll
        for (int p = 0; p < 3; p++) { ull bp = *(const ull*)&sm[B1P+rbase+2*p]; acc[p][0]=bp; acc[p][1]=bp; }
        edge1v<-1>(sm, WPH, WPN, WPM, sm+MPo, hsh, r, acc, rbase, lane, cbase, lsrc, lstr, rsrc, rstr);
    }
    __syncthreads();
    layer2v(sm, W2Po, r, agg, rbase, cbase);
    __syncthreads();
    {   // edge future
        ull acc[3][2];
        #pragma unroll
        for (int p = 0; p < 3; p++) { ull bp = *(const ull*)&sm[B1F+rbase+2*p]; acc[p][0]=bp; acc[p][1]=bp; }
        edge1v<1>(sm, WFH, WFN, WFM, sm+MFo, hsh, r, acc, rbase, lane, cbase, lsrc, lstr, rsrc, rstr);
    }
    __syncthreads();
    layer2v(sm, W2Fo, r, agg, rbase, cbase);
    __syncthreads();
    {   // edge y (hy-part precomputed in g_yterm[b][t][o])
        ull acc[3][2];
        const float* yt = g_yterm + (size_t)b*Tn*48;
        int tc = t0 + cbase;
        #pragma unroll
        for (int p = 0; p < 3; p++) {
            acc[p][0] = (tc   < Tn) ? *(const ull*)&yt[(size_t)tc*48     + rbase+2*p] : 0ull;
            acc[p][1] = (tc+1 < Tn) ? *(const ull*)&yt[(size_t)(tc+1)*48 + rbase+2*p] : 0ull;
        }
        edge1v<0>(sm, WYH, 0, WYM, sm+MYo, hsh, r, acc, rbase, lane, cbase, lsrc, lstr, rsrc, rstr);
    }
    __syncthreads();
    layer2v(sm, W2Yo, r, agg, rbase, cbase);
    __syncthreads();
    // spill agg into r
    #pragma unroll
    for (int p = 0; p < 3; p++) {
        float x0,x1,y0,y1;
        unpack2(agg[p][0],x0,y0); unpack2(agg[p][1],x1,y1);
        int o0 = rbase + 2*p;
        r[o0*128+cbase] = x0;   r[o0*128+cbase+1] = x1;
        r[(o0+1)*128+cbase] = y0; r[(o0+1)*128+cbase+1] = y1;
    }
    __syncthreads();

    // GRU (A: gx + gh for r,z; Bv: gh n-part)
    {
        ull A[9][2], Bv[3][2];
        #pragma unroll
        for (int g = 0; g < 3; g++)
            #pragma unroll
            for (int p = 0; p < 3; p++) {
                ull bi = *(const ull*)&sm[BIH + g*48 + rbase + 2*p];
                if (g < 2) bi = add2(bi, *(const ull*)&sm[BHH + g*48 + rbase + 2*p]);
                A[g*3+p][0] = bi; A[g*3+p][1] = bi;
            }
        #pragma unroll
        for (int p = 0; p < 3; p++) {
            ull bb = *(const ull*)&sm[BHH + 96 + rbase + 2*p];
            Bv[p][0] = bb; Bv[p][1] = bb;
        }
        #pragma unroll 1
        for (int k = 0; k < 48; k++) {
            float2 xv = *(const float2*)&r[k*128 + cbase];
            ull b0 = pack2(xv.x,xv.x), b1 = pack2(xv.y,xv.y);
            #pragma unroll
            for (int g = 0; g < 3; g++)
                #pragma unroll
                for (int p = 0; p < 3; p++) {
                    ull wp = *(const ull*)&sm[WIHo + k*150 + g*48 + rbase + 2*p];
                    A[g*3+p][0] = fma2(wp,b0,A[g*3+p][0]);
                    A[g*3+p][1] = fma2(wp,b1,A[g*3+p][1]);
                }
        }
        #pragma unroll 1
        for (int k = 0; k < 48; k++) {
            float2 hv = *(const float2*)&hsh[k*128 + cbase];
            ull b0 = pack2(hv.x,hv.x), b1 = pack2(hv.y,hv.y);
            #pragma unroll
            for (int g = 0; g < 2; g++)
                #pragma unroll
                for (int p = 0; p < 3; p++) {
                    ull wp = *(const ull*)&sm[WHHo + k*150 + g*48 + rbase + 2*p];
                    A[g*3+p][0] = fma2(wp,b0,A[g*3+p][0]);
                    A[g*3+p][1] = fma2(wp,b1,A[g*3+p][1]);
                }
            #pragma unroll
            for (int p = 0; p < 3; p++) {
                ull wp = *(const ull*)&sm[WHHo + k*150 + 96 + rbase + 2*p];
                Bv[p][0] = fma2(wp,b0,Bv[p][0]);
                Bv[p][1] = fma2(wp,b1,Bv[p][1]);
            }
        }
        __syncthreads();   // all agg reads done before r is overwritten with hnew
        #pragma unroll
        for (int p = 0; p < 3; p++)
            #pragma unroll
            for (int cc = 0; cc < 2; cc++) {
                float rv0,rv1,zv0,zv1,nv0,nv1,bn0,bn1;
                unpack2(A[p][cc],rv0,rv1); unpack2(A[3+p][cc],zv0,zv1);
                unpack2(A[6+p][cc],nv0,nv1); unpack2(Bv[p][cc],bn0,bn1);
                int c = cbase + cc, t = t0 + c;
                int o0 = rbase + 2*p, o1 = o0 + 1;
                float rr0 = sigmf(rv0), rr1 = sigmf(rv1);
                float zz0 = sigmf(zv0), zz1 = sigmf(zv1);
                float ng0 = tanhfast(nv0 + rr0*bn0), ng1 = tanhfast(nv1 + rr1*bn1);
                float h0 = hsh[o0*128 + c], h1 = hsh[o1*128 + c];
                float hn0 = (1.f-zz0)*ng0 + zz0*h0;
                float hn1 = (1.f-zz1)*ng1 + zz1*h1;
                r[o0*128+c] = hn0; r[o1*128+c] = hn1;
                if (t < Tn) { hx_out[(b*48+o0)*Tn+t] = hn0; hx_out[(b*48+o1)*Tn+t] = hn1; }
            }
    }
    __syncthreads();

    // decoder + xs update
    #pragma unroll
    for (int rep = 0; rep < 2; rep++) {
        int item = tid + rep*TPB;
        int i = item >> 7, n = item & 127, t = t0 + n;
        float e = sm[BDEC+i];
        #pragma unroll 8
        for (int k = 0; k < 48; k++) e = fmaf(sm[WDEC+i*48+k], r[k*128+n], e);
        if (t < Tn) {
            float xn = xsh[i*130 + 1 + n]
                     + GAMMA_F * (e + sm[MPo+i*128+n] + sm[MFo+i*128+n] + sm[MYo+i*128+n]);
            xs_out[(b*8+i)*Tn + t] = xn;
        }
    }
}

extern "C" void kernel_launch(void* const* d_in, const int* in_sizes, int n_in,
                              void* d_out, int out_size) {
    const float* ys   = (const float*)d_in[0];
    const float* hx0  = (const float*)d_in[1];
    const float* F    = (const float*)d_in[2];
    const float* H    = (const float*)d_in[3];
    const float* Q    = (const float*)d_in[4];
    const float* R    = (const float*)d_in[5];
    const float* W_hy = (const float*)d_in[6];
    const float* b_hy = (const float*)d_in[7];
    const float* W1p  = (const float*)d_in[8];
    const float* b1p  = (const float*)d_in[9];
    const float* W2p  = (const float*)d_in[10];
    const float* b2p  = (const float*)d_in[11];
    const float* W1f  = (const float*)d_in[12];
    const float* b1f  = (const float*)d_in[13];
    const float* W2f  = (const float*)d_in[14];
    const float* b2f  = (const float*)d_in[15];
    const float* W1y  = (const float*)d_in[16];
    const float* b1y  = (const float*)d_in[17];
    const float* W2y  = (const float*)d_in[18];
    const float* b2y  = (const float*)d_in[19];
    const float* Wih  = (const float*)d_in[20];
    const float* bih  = (const float*)d_in[21];
    const float* Whh  = (const float*)d_in[22];
    const float* bhh  = (const float*)d_in[23];
    const float* Wdec = (const float*)d_in[24];
    const float* bdec = (const float*)d_in[25];
    float* out = (float*)d_out;

    const int iters = out_size / BXT - 1;

    cudaFuncSetAttribute(step_kernel, cudaFuncAttributeMaxDynamicSharedMemorySize, SMEM_BYTES);

    float *xs0_p = nullptr, *hx_p = nullptr;
    cudaGetSymbolAddress((void**)&xs0_p, g_xs0);
    cudaGetSymbolAddress((void**)&hx_p, g_hxbuf);

    prep_small<<<1, 32>>>(F, H, Q, R, b2p, b2f, b2y);
    prep_nodes<<<(Bn*Tn + 127)/128, 128>>>(ys, H, W_hy, b_hy, W1y, b1y);

    dim3 grid(NCHUNK, Bn);
    const float* xs_in = xs0_p;
    const float* hx_in = hx0;
    for (int it = 0; it < iters; it++) {
        float* xs_out = out + (size_t)BXT * (1 + it);
        float* hx_out = hx_p + (size_t)(it & 1) * BHT;
        step_kernel<<<grid, TPB, SMEM_BYTES>>>(xs_in, hx_in, xs_out, hx_out,
                                               W1p, b1p, W2p, W1f, b1f, W2f,
                                               W1y, W2y, Wih, bih, Whh, bhh, Wdec, bdec);
        xs_in = xs_out;
        hx_in = hx_out;
    }
    cudaMemcpyAsync(out, out + (size_t)BXT * iters, (size_t)BXT * sizeof(float),
                    cudaMemcpyDeviceToDevice);
}

// round 8
// speedup vs baseline: 1.9208x; 1.1659x over previous
#include <cuda_runtime.h>
#include <math.h>
typedef unsigned long long ull;

#define Bn 16
#define Tn 1000
#define NT 128
#define TPB 512
#define NCHUNK 8
#define NBLK (Bn*NCHUNK)
#define GAMMA_F 1e-4f
#define BXT (Bn*8*Tn)
#define BHT (Bn*48*Tn)

__device__ float g_xs0[BXT];
__device__ float g_cy[BXT];
__device__ float g_yterm[BHT];   // [b][t][48]
__device__ float g_Qi[64], g_QiF[64], g_FtQi[64], g_FtQiF[64], g_HtRiH[64], g_HtRi[32];
__device__ float g_b2sum[48];
__device__ float g_hh[2][Bn][NCHUNK][2][48];  // [parity][b][chunk][0=col0,1=col127][k]
__device__ float g_xh[2][Bn][NCHUNK][2][8];
__device__ unsigned g_cnt;
__device__ volatile unsigned g_gen;

// shared layout (floats); transposed weights W_T[k*48+o] (GRU k*144+row)
constexpr int WPH=0, WPN=2304, WFH=4608, WFN=6912, WYH=9216;
constexpr int W2Po=11520, W2Fo=13824, W2Yo=16128;
constexpr int WIHo=18432, WHHo=25344;
constexpr int WPM=32256, WFM=32640, WYM=33024, WDEC=33408;
constexpr int B1P=33792, B1F=33840, B2S=33888, BIH=33936, BHH=34080, BDEC=34224;
constexpr int SQI=34232, SQIF=34296, SFTQI=34360, SFTQIF=34424, SHTRIH=34488;
constexpr int HLo=34552, HRo=34600;
constexpr int HSH=34648;            // 48x128
constexpr int XSH=40792;            // 8x130 halo
constexpr int MPo=41832, MFo=42856, MYo=43880;
constexpr int R0o=44904, R1o=51048; // 48x128 each
constexpr int SMEM_FLOATS=57192;
constexpr int SMEM_BYTES=SMEM_FLOATS*4;  // 228,768 B

__device__ __forceinline__ ull pack2(float a, float b){ull r;asm("mov.b64 %0,{%1,%2};":"=l"(r):"f"(a),"f"(b));return r;}
__device__ __forceinline__ void unpack2(ull v, float&a, float&b){asm("mov.b64 {%0,%1},%2;":"=f"(a),"=f"(b):"l"(v));}
__device__ __forceinline__ ull fma2(ull a, ull b, ull c){ull d;asm("fma.rn.f32x2 %0,%1,%2,%3;":"=l"(d):"l"(a),"l"(b),"l"(c));return d;}
__device__ __forceinline__ ull add2(ull a, ull b){ull d;asm("add.rn.f32x2 %0,%1,%2;":"=l"(d):"l"(a),"l"(b));return d;}
__device__ __forceinline__ float sigmf(float x){ return 1.f/(1.f+__expf(-x)); }
__device__ __forceinline__ float tanhfast(float x){ return 1.f - 2.f/(__expf(2.f*x)+1.f); }

__device__ __forceinline__ void gridbar(int tid){
    __syncthreads();
    if (tid == 0) {
        unsigned gen = g_gen;
        __threadfence();
        if (atomicAdd(&g_cnt, 1u) == NBLK-1u) {
            g_cnt = 0;
            __threadfence();
            g_gen = gen + 1u;
        } else {
            while (g_gen == gen) { __nanosleep(32); }
        }
        __threadfence();
    }
    __syncthreads();
}

__device__ void gj_invert(double* a, double* inv, int n) {
    for (int i = 0; i < n; i++) for (int j = 0; j < n; j++) inv[i*n+j] = (i==j)?1.0:0.0;
    for (int c = 0; c < n; c++) {
        int piv = c; double best = fabs(a[c*n+c]);
        for (int r = c+1; r < n; r++) { double v = fabs(a[r*n+c]); if (v > best) { best=v; piv=r; } }
        if (piv != c) for (int j = 0; j < n; j++) {
            double t=a[c*n+j]; a[c*n+j]=a[piv*n+j]; a[piv*n+j]=t;
            t=inv[c*n+j]; inv[c*n+j]=inv[piv*n+j]; inv[piv*n+j]=t;
        }
        double ip = 1.0/a[c*n+c];
        for (int j = 0; j < n; j++) { a[c*n+j]*=ip; inv[c*n+j]*=ip; }
        for (int r = 0; r < n; r++) if (r != c) {
            double f = a[r*n+c];
            if (f != 0.0) for (int j = 0; j < n; j++) { a[r*n+j]-=f*a[c*n+j]; inv[r*n+j]-=f*inv[c*n+j]; }
        }
    }
}

__global__ void prep_small(const float* __restrict__ F, const float* __restrict__ H,
                           const float* __restrict__ Q, const float* __restrict__ R,
                           const float* __restrict__ b2p, const float* __restrict__ b2f,
                           const float* __restrict__ b2y) {
    if (threadIdx.x != 0 || blockIdx.x != 0) return;
    g_cnt = 0u;
    double Qd[64], Qi[64], Rd[16], Ri[16], Fd[64], Hd[32];
    for (int i=0;i<64;i++) Qd[i]=(double)Q[i];
    for (int i=0;i<16;i++) Rd[i]=(double)R[i];
    for (int i=0;i<64;i++) Fd[i]=(double)F[i];
    for (int i=0;i<32;i++) Hd[i]=(double)H[i];
    gj_invert(Qd,Qi,8); gj_invert(Rd,Ri,4);
    double QiF[64], FtQi[64], FtQiF[64], HtRi[32], HtRiH[64];
    for (int i=0;i<8;i++) for (int j=0;j<8;j++){ double s=0; for(int k=0;k<8;k++) s+=Qi[i*8+k]*Fd[k*8+j]; QiF[i*8+j]=s; }
    for (int i=0;i<8;i++) for (int j=0;j<8;j++){ double s=0; for(int k=0;k<8;k++) s+=Fd[k*8+i]*Qi[k*8+j]; FtQi[i*8+j]=s; }
    for (int i=0;i<8;i++) for (int j=0;j<8;j++){ double s=0; for(int k=0;k<8;k++) s+=FtQi[i*8+k]*Fd[k*8+j]; FtQiF[i*8+j]=s; }
    for (int i=0;i<8;i++) for (int z=0;z<4;z++){ double s=0; for(int y=0;y<4;y++) s+=Hd[y*8+i]*Ri[y*4+z]; HtRi[i*4+z]=s; }
    for (int i=0;i<8;i++) for (int j=0;j<8;j++){ double s=0; for(int z=0;z<4;z++) s+=HtRi[i*4+z]*Hd[z*8+j]; HtRiH[i*8+j]=s; }
    for (int i=0;i<64;i++){ g_Qi[i]=(float)Qi[i]; g_QiF[i]=(float)QiF[i];
        g_FtQi[i]=(float)FtQi[i]; g_FtQiF[i]=(float)FtQiF[i]; g_HtRiH[i]=(float)HtRiH[i]; }
    for (int i=0;i<32;i++) g_HtRi[i]=(float)HtRi[i];
    for (int o=0;o<48;o++) g_b2sum[o]=b2p[o]+b2f[o]+b2y[o];
}

__global__ void prep_nodes(const float* __restrict__ ys, const float* __restrict__ H,
                           const float* __restrict__ W_hy, const float* __restrict__ b_hy,
                           const float* __restrict__ W1y, const float* __restrict__ b1y) {
    int node = blockIdx.x * blockDim.x + threadIdx.x;
    if (node >= Bn*Tn) return;
    int b = node / Tn, t = node - b*Tn;
    float yv[4];
    #pragma unroll
    for (int z=0;z<4;z++) yv[z] = ys[(b*Tn+t)*4+z];
    #pragma unroll
    for (int i=0;i<8;i++){
        float s0=0.f, s1=0.f;
        #pragma unroll
        for (int y=0;y<4;y++){ s0=fmaf(H[y*8+i],yv[y],s0); s1=fmaf(g_HtRi[i*4+y],yv[y],s1); }
        g_xs0[(b*8+i)*Tn+t]=s0; g_cy[(b*8+i)*Tn+t]=s1;
    }
    float hy[48];
    #pragma unroll
    for (int o=0;o<48;o++){
        float s=b_hy[o];
        #pragma unroll
        for (int y=0;y<4;y++) s=fmaf(W_hy[o*4+y],yv[y],s);
        hy[o]=s;
    }
    for (int o=0;o<48;o++){
        float s=b1y[o];
        #pragma unroll
        for (int k=0;k<48;k++) s=fmaf(W1y[o*104+48+k],hy[k],s);
        g_yterm[(b*Tn+t)*48+o]=s;
    }
}

template<int SHIFT>
__device__ __forceinline__ void edge1v(const float* __restrict__ sm, int WHo_, int WNo_, int WMo_,
    const float* __restrict__ msg, const float* __restrict__ hsh, float* __restrict__ r,
    ull acc[3][2], int rbase, int lane, int cbase,
    const float* __restrict__ lsrc, int lstr, const float* __restrict__ rsrc, int rstr)
{
    #pragma unroll 2
    for (int k = 0; k < 48; k++) {
        float2 v = *(const float2*)&hsh[k*128 + cbase];
        ull b0 = pack2(v.x,v.x), b1 = pack2(v.y,v.y);
        #pragma unroll
        for (int p = 0; p < 3; p++) {
            ull wp = *(const ull*)&sm[WHo_ + k*48 + rbase + 2*p];
            acc[p][0] = fma2(wp,b0,acc[p][0]);
            acc[p][1] = fma2(wp,b1,acc[p][1]);
        }
        if (SHIFT != 0) {
            ull n0, n1;
            if (SHIFT < 0) {
                float pv = __shfl_up_sync(0xffffffffu, v.y, 1);
                if (lane == 0) pv = lsrc[k*lstr];
                n0 = pack2(pv,pv); n1 = b0;
            } else {
                float qv = __shfl_down_sync(0xffffffffu, v.x, 1);
                if (lane == 31) qv = rsrc[k*rstr];
                n0 = b1; n1 = pack2(qv,qv);
            }
            #pragma unroll
            for (int p = 0; p < 3; p++) {
                ull up = *(const ull*)&sm[WNo_ + k*48 + rbase + 2*p];
                acc[p][0] = fma2(up,n0,acc[p][0]);
                acc[p][1] = fma2(up,n1,acc[p][1]);
            }
        }
    }
    #pragma unroll
    for (int k = 0; k < 8; k++) {
        float2 m = *(const float2*)&msg[k*128 + cbase];
        ull b0 = pack2(m.x,m.x), b1 = pack2(m.y,m.y);
        #pragma unroll
        for (int p = 0; p < 3; p++) {
            ull wp = *(const ull*)&sm[WMo_ + k*48 + rbase + 2*p];
            acc[p][0] = fma2(wp,b0,acc[p][0]);
            acc[p][1] = fma2(wp,b1,acc[p][1]);
        }
    }
    #pragma unroll
    for (int p = 0; p < 3; p++) {
        float x0,x1,y0,y1;
        unpack2(acc[p][0],x0,y0); unpack2(acc[p][1],x1,y1);
        int o0 = rbase + 2*p;
        r[o0*128 + cbase]       = fmaxf(x0,0.f);
        r[o0*128 + cbase+1]     = fmaxf(x1,0.f);
        r[(o0+1)*128 + cbase]   = fmaxf(y0,0.f);
        r[(o0+1)*128 + cbase+1] = fmaxf(y1,0.f);
    }
}

__device__ __forceinline__ void layer2v(const float* __restrict__ sm, int W2o_,
    const float* __restrict__ r, ull agg[3][2], int rbase, int cbase)
{
    #pragma unroll 2
    for (int k = 0; k < 48; k++) {
        float2 v = *(const float2*)&r[k*128 + cbase];
        ull b0 = pack2(v.x,v.x), b1 = pack2(v.y,v.y);
        #pragma unroll
        for (int p = 0; p < 3; p++) {
            ull wp = *(const ull*)&sm[W2o_ + k*48 + rbase + 2*p];
            agg[p][0] = fma2(wp,b0,agg[p][0]);
            agg[p][1] = fma2(wp,b1,agg[p][1]);
        }
    }
}

__global__ void __launch_bounds__(TPB, 1)
persist_kernel(const float* __restrict__ hx0, float* __restrict__ out, int iters,
            const float* __restrict__ W1p, const float* __restrict__ b1p,
            const float* __restrict__ W2p,
            const float* __restrict__ W1f, const float* __restrict__ b1f,
            const float* __restrict__ W2f,
            const float* __restrict__ W1y, const float* __restrict__ W2y,
            const float* __restrict__ Wih, const float* __restrict__ bih,
            const float* __restrict__ Whh, const float* __restrict__ bhh,
            const float* __restrict__ Wdec, const float* __restrict__ bdec) {
    extern __shared__ float sm[];
    float* hsh = sm + HSH;  float* xsh = sm + XSH;
    float* r0 = sm + R0o;   float* r1 = sm + R1o;

    const int tid = threadIdx.x;
    const int b = blockIdx.y;
    const int c = blockIdx.x;
    const int t0 = c * NT;

    // ---- one-time staging ----
    for (int idx = tid; idx < 48*104; idx += TPB) {
        int o = idx/104, cc = idx - o*104;
        float vp = W1p[idx], vf = W1f[idx], vy = W1y[idx];
        if (cc < 48) { sm[WPH+cc*48+o]=vp; sm[WFH+cc*48+o]=vf; sm[WYH+cc*48+o]=vy; }
        else if (cc < 96) { int k=cc-48; sm[WPN+k*48+o]=vp; sm[WFN+k*48+o]=vf; }
        else { int k=cc-96; sm[WPM+k*48+o]=vp; sm[WFM+k*48+o]=vf; sm[WYM+k*48+o]=vy; }
    }
    for (int idx = tid; idx < 48*48; idx += TPB) {
        int o = idx/48, k = idx - o*48;
        sm[W2Po+k*48+o]=W2p[idx]; sm[W2Fo+k*48+o]=W2f[idx]; sm[W2Yo+k*48+o]=W2y[idx];
    }
    for (int idx = tid; idx < 144*48; idx += TPB) {
        int o = idx/48, k = idx - o*48;
        sm[WIHo+k*144+o]=Wih[idx]; sm[WHHo+k*144+o]=Whh[idx];
    }
    for (int idx = tid; idx < 384; idx += TPB) sm[WDEC+idx]=Wdec[idx];
    if (tid < 48) { sm[B1P+tid]=b1p[tid]; sm[B1F+tid]=b1f[tid]; sm[B2S+tid]=g_b2sum[tid]; }
    for (int idx = tid; idx < 144; idx += TPB) { sm[BIH+idx]=bih[idx]; sm[BHH+idx]=bhh[idx]; }
    if (tid < 8) sm[BDEC+tid]=bdec[tid];
    for (int idx = tid; idx < 64; idx += TPB) {
        sm[SQI+idx]=g_Qi[idx]; sm[SQIF+idx]=g_QiF[idx]; sm[SFTQI+idx]=g_FtQi[idx];
        sm[SFTQIF+idx]=g_FtQiF[idx]; sm[SHTRIH+idx]=g_HtRiH[idx];
    }
    // initial state
    for (int idx = tid; idx < 48*128; idx += TPB) {
        int k = idx >> 7, cc = idx & 127; int t = t0 + cc;
        hsh[idx] = (t < Tn) ? hx0[(b*48+k)*Tn + t] : 0.f;
    }
    if (tid < 48) {
        int tl = t0 - 1, tr = t0 + 128;
        sm[HLo+tid] = (tl >= 0) ? hx0[(b*48+tid)*Tn + tl] : 0.f;
        sm[HRo+tid] = (tr < Tn) ? hx0[(b*48+tid)*Tn + tr] : 0.f;
    }
    for (int idx = tid; idx < 8*130; idx += TPB) {
        int k = idx / 130, cc = idx - k*130; int t = t0 + cc - 1;
        xsh[idx] = (t >= 0 && t < Tn) ? g_xs0[(b*8+k)*Tn + t] : 0.f;
    }
    __syncthreads();

    const int w = tid >> 5, lane = tid & 31, cg = w & 1, rg = w >> 1;
    const int rbase = 6*rg, cbase = cg*64 + 2*lane;
    const float* lsrc; int lstr; const float* rsrc; int rstr;
    if (cg == 0) { lsrc = sm+HLo; lstr = 1; rsrc = hsh+64; rstr = 128; }
    else         { lsrc = hsh+63; lstr = 128; rsrc = sm+HRo; rstr = 1; }

    for (int it = 0; it < iters; it++) {
        const int par = it & 1;

        // A: messages
        #pragma unroll
        for (int rep = 0; rep < 2; rep++) {
            int item = tid + rep*TPB;
            int i = item >> 7, n = item & 127, t = t0 + n;
            bool valid = t < Tn;
            float accp = 0.f, accf = 0.f;
            float accy = valid ? g_cy[(b*8+i)*Tn + t] : 0.f;
            #pragma unroll
            for (int j = 0; j < 8; j++) {
                float xc = xsh[j*130 + 1 + n];
                accp = fmaf(-sm[SQI+i*8+j], xc, accp);
                accp = fmaf(sm[SQIF+i*8+j], xsh[j*130 + n], accp);
                accf = fmaf(sm[SFTQI+i*8+j], xsh[j*130 + 2 + n], accf);
                accf = fmaf(-sm[SFTQIF+i*8+j], xc, accf);
                accy = fmaf(-sm[SHTRIH+i*8+j], xc, accy);
            }
            sm[MPo + i*128+n] = (valid && t > 0) ? accp : 0.f;
            sm[MFo + i*128+n] = (t < Tn-1) ? accf : 0.f;
            sm[MYo + i*128+n] = valid ? accy : 0.f;
        }
        __syncthreads();

        ull agg[3][2];
        #pragma unroll
        for (int p = 0; p < 3; p++) {
            ull bp = *(const ull*)&sm[B2S + rbase + 2*p];
            agg[p][0] = bp; agg[p][1] = bp;
        }
        // B: edge_p -> r0
        {
            ull acc[3][2];
            #pragma unroll
            for (int p = 0; p < 3; p++) { ull bp = *(const ull*)&sm[B1P+rbase+2*p]; acc[p][0]=bp; acc[p][1]=bp; }
            edge1v<-1>(sm, WPH, WPN, WPM, sm+MPo, hsh, r0, acc, rbase, lane, cbase, lsrc, lstr, rsrc, rstr);
        }
        __syncthreads();
        // C: layer2p(r0) ; edge_f -> r1
        layer2v(sm, W2Po, r0, agg, rbase, cbase);
        {
            ull acc[3][2];
            #pragma unroll
            for (int p = 0; p < 3; p++) { ull bp = *(const ull*)&sm[B1F+rbase+2*p]; acc[p][0]=bp; acc[p][1]=bp; }
            edge1v<1>(sm, WFH, WFN, WFM, sm+MFo, hsh, r1, acc, rbase, lane, cbase, lsrc, lstr, rsrc, rstr);
        }
        __syncthreads();
        // D: layer2f(r1) ; edge_y -> r0
        layer2v(sm, W2Fo, r1, agg, rbase, cbase);
        {
            ull acc[3][2];
            const float* yt = g_yterm + (size_t)b*Tn*48;
            int tc = t0 + cbase;
            #pragma unroll
            for (int p = 0; p < 3; p++) {
                acc[p][0] = (tc   < Tn) ? *(const ull*)&yt[(size_t)tc*48     + rbase+2*p] : 0ull;
                acc[p][1] = (tc+1 < Tn) ? *(const ull*)&yt[(size_t)(tc+1)*48 + rbase+2*p] : 0ull;
            }
            edge1v<0>(sm, WYH, 0, WYM, sm+MYo, hsh, r0, acc, rbase, lane, cbase, lsrc, lstr, rsrc, rstr);
        }
        __syncthreads();
        // E: layer2y(r0) ; spill agg -> r1
        layer2v(sm, W2Yo, r0, agg, rbase, cbase);
        #pragma unroll
        for (int p = 0; p < 3; p++) {
            float x0,x1,y0,y1;
            unpack2(agg[p][0],x0,y0); unpack2(agg[p][1],x1,y1);
            int o0 = rbase + 2*p;
            r1[o0*128+cbase] = x0;   r1[o0*128+cbase+1] = x1;
            r1[(o0+1)*128+cbase] = y0; r1[(o0+1)*128+cbase+1] = y1;
        }
        __syncthreads();

        // F: GRU — read r1(agg)+hsh, write hnew -> r0
        {
            ull A[9][2], Bv[3][2];
            #pragma unroll
            for (int g = 0; g < 3; g++)
                #pragma unroll
                for (int p = 0; p < 3; p++) {
                    ull bi = *(const ull*)&sm[BIH + g*48 + rbase + 2*p];
                    if (g < 2) bi = add2(bi, *(const ull*)&sm[BHH + g*48 + rbase + 2*p]);
                    A[g*3+p][0] = bi; A[g*3+p][1] = bi;
                }
            #pragma unroll
            for (int p = 0; p < 3; p++) {
                ull bb = *(const ull*)&sm[BHH + 96 + rbase + 2*p];
                Bv[p][0] = bb; Bv[p][1] = bb;
            }
            #pragma unroll 1
            for (int k = 0; k < 48; k++) {
                float2 xv = *(const float2*)&r1[k*128 + cbase];
                ull b0 = pack2(xv.x,xv.x), b1 = pack2(xv.y,xv.y);
                #pragma unroll
                for (int g = 0; g < 3; g++)
                    #pragma unroll
                    for (int p = 0; p < 3; p++) {
                        ull wp = *(const ull*)&sm[WIHo + k*144 + g*48 + rbase + 2*p];
                        A[g*3+p][0] = fma2(wp,b0,A[g*3+p][0]);
                        A[g*3+p][1] = fma2(wp,b1,A[g*3+p][1]);
                    }
            }
            #pragma unroll 1
            for (int k = 0; k < 48; k++) {
                float2 hv = *(const float2*)&hsh[k*128 + cbase];
                ull b0 = pack2(hv.x,hv.x), b1 = pack2(hv.y,hv.y);
                #pragma unroll
                for (int g = 0; g < 2; g++)
                    #pragma unroll
                    for (int p = 0; p < 3; p++) {
                        ull wp = *(const ull*)&sm[WHHo + k*144 + g*48 + rbase + 2*p];
                        A[g*3+p][0] = fma2(wp,b0,A[g*3+p][0]);
                        A[g*3+p][1] = fma2(wp,b1,A[g*3+p][1]);
                    }
                #pragma unroll
                for (int p = 0; p < 3; p++) {
                    ull wp = *(const ull*)&sm[WHHo + k*144 + 96 + rbase + 2*p];
                    Bv[p][0] = fma2(wp,b0,Bv[p][0]);
                    Bv[p][1] = fma2(wp,b1,Bv[p][1]);
                }
            }
            #pragma unroll
            for (int p = 0; p < 3; p++)
                #pragma unroll
                for (int cc2 = 0; cc2 < 2; cc2++) {
                    float rv0,rv1,zv0,zv1,nv0,nv1,bn0,bn1;
                    unpack2(A[p][cc2],rv0,rv1); unpack2(A[3+p][cc2],zv0,zv1);
                    unpack2(A[6+p][cc2],nv0,nv1); unpack2(Bv[p][cc2],bn0,bn1);
                    int cc = cbase + cc2;
                    int o0 = rbase + 2*p, o1 = o0 + 1;
                    float rr0 = sigmf(rv0), rr1 = sigmf(rv1);
                    float zz0 = sigmf(zv0), zz1 = sigmf(zv1);
                    float ng0 = tanhfast(nv0 + rr0*bn0), ng1 = tanhfast(nv1 + rr1*bn1);
                    float h0 = hsh[o0*128 + cc], h1 = hsh[o1*128 + cc];
                    r0[o0*128+cc] = (1.f-zz0)*ng0 + zz0*h0;
                    r0[o1*128+cc] = (1.f-zz1)*ng1 + zz1*h1;
                }
        }
        __syncthreads();

        // G: copy hnew -> hsh (masked), publish h boundaries, decoder -> out + xsh
        for (int idx = tid; idx < 48*128; idx += TPB) {
            int cc = idx & 127; int t = t0 + cc;
            hsh[idx] = (t < Tn) ? r0[idx] : 0.f;
        }
        if (tid < 48) {
            g_hh[par][b][c][0][tid] = r0[tid*128 + 0];
            int t127 = t0 + 127;
            g_hh[par][b][c][1][tid] = (t127 < Tn) ? r0[tid*128 + 127] : 0.f;
        }
        {
            float* outp = out + (size_t)BXT * (1 + it);
            #pragma unroll
            for (int rep = 0; rep < 2; rep++) {
                int item = tid + rep*TPB;
                int i = item >> 7, n = item & 127, t = t0 + n;
                float e = sm[BDEC+i];
                #pragma unroll 8
                for (int k = 0; k < 48; k++) e = fmaf(sm[WDEC+i*48+k], r0[k*128+n], e);
                float xn = 0.f;
                if (t < Tn) {
                    xn = xsh[i*130 + 1 + n]
                       + GAMMA_F * (e + sm[MPo+i*128+n] + sm[MFo+i*128+n] + sm[MYo+i*128+n]);
                    xsh[i*130 + 1 + n] = xn;
                    outp[(b*8+i)*Tn + t] = xn;
                }
                if (n == 0)   g_xh[par][b][c][0][i] = xn;
                if (n == 127) g_xh[par][b][c][1][i] = xn;
            }
        }

        // H: grid barrier, then pull neighbor halos
        gridbar(tid);
        if (tid < 48) sm[HLo+tid] = (c > 0) ? g_hh[par][b][c-1][1][tid] : 0.f;
        else if (tid < 96) { int k = tid-48; sm[HRo+k] = (c < NCHUNK-1) ? g_hh[par][b][c+1][0][k] : 0.f; }
        else if (tid < 104) { int i = tid-96; xsh[i*130 + 0] = (c > 0) ? g_xh[par][b][c-1][1][i] : 0.f; }
        else if (tid < 112) { int i = tid-104; xsh[i*130 + 129] = (c < NCHUNK-1) ? g_xh[par][b][c+1][0][i] : 0.f; }
        __syncthreads();
    }
}

extern "C" void kernel_launch(void* const* d_in, const int* in_sizes, int n_in,
                              void* d_out, int out_size) {
    const float* ys   = (const float*)d_in[0];
    const float* hx0  = (const float*)d_in[1];
    const float* F    = (const float*)d_in[2];
    const float* H    = (const float*)d_in[3];
    const float* Q    = (const float*)d_in[4];
    const float* R    = (const float*)d_in[5];
    const float* W_hy = (const float*)d_in[6];
    const float* b_hy = (const float*)d_in[7];
    const float* W1p  = (const float*)d_in[8];
    const float* b1p  = (const float*)d_in[9];
    const float* W2p  = (const float*)d_in[10];
    const float* b2p  = (const float*)d_in[11];
    const float* W1f  = (const float*)d_in[12];
    const float* b1f  = (const float*)d_in[13];
    const float* W2f  = (const float*)d_in[14];
    const float* b2f  = (const float*)d_in[15];
    const float* W1y  = (const float*)d_in[16];
    const float* b1y  = (const float*)d_in[17];
    const float* W2y  = (const float*)d_in[18];
    const float* b2y  = (const float*)d_in[19];
    const float* Wih  = (const float*)d_in[20];
    const float* bih  = (const float*)d_in[21];
    const float* Whh  = (const float*)d_in[22];
    const float* bhh  = (const float*)d_in[23];
    const float* Wdec = (const float*)d_in[24];
    const float* bdec = (const float*)d_in[25];
    float* out = (float*)d_out;

    const int iters = out_size / BXT - 1;

    cudaFuncSetAttribute(persist_kernel, cudaFuncAttributeMaxDynamicSharedMemorySize, SMEM_BYTES);

    prep_small<<<1, 32>>>(F, H, Q, R, b2p, b2f, b2y);
    prep_nodes<<<(Bn*Tn + 127)/128, 128>>>(ys, H, W_hy, b_hy, W1y, b1y);

    dim3 grid(NCHUNK, Bn);
    persist_kernel<<<grid, TPB, SMEM_BYTES>>>(hx0, out, iters,
        W1p, b1p, W2p, W1f, b1f, W2f, W1y, W2y, Wih, bih, Whh, bhh, Wdec, bdec);

    cudaMemcpyAsync(out, out + (size_t)BXT * iters, (size_t)BXT * sizeof(float),
                    cudaMemcpyDeviceToDevice);
}

// round 9
// speedup vs baseline: 2.0912x; 1.0887x over previous
#include <cuda_runtime.h>
#include <math.h>
typedef unsigned long long ull;

#define Bn 16
#define Tn 1000
#define NT 128
#define TPB 512
#define NCHUNK 8
#define NBLK (Bn*NCHUNK)
#define GAMMA_F 1e-4f
#define BXT (Bn*8*Tn)
#define BHT (Bn*48*Tn)

__device__ float g_xs0[BXT];
__device__ float g_cy[BXT];
__device__ float g_yterm[BHT];   // [b][t][48]
__device__ float g_Qi[64], g_QiF[64], g_FtQi[64], g_FtQiF[64], g_HtRiH[64], g_HtRi[32];
__device__ float g_b2sum[48];
__device__ float g_hh[2][Bn][NCHUNK][2][48];
__device__ float g_xh[2][Bn][NCHUNK][2][8];
__device__ unsigned g_cnt;
__device__ volatile unsigned g_gen;

// shared layout (floats)
// WEP/WEF: interleaved [k][pair p<24][{c0,c1,n0,n1}] (4608 each)
// WG: interleaved [k][pair p<72][{ih0,ih1,hh0,hh1}] (13824)
constexpr int WEP=0, WEF=4608, WYH=9216;
constexpr int W2P=11520, W2F=13824, W2Y=16128;
constexpr int WG=18432;
constexpr int WPM=32256, WFM=32640, WYM=33024, WDEC=33408;
constexpr int B1P=33792, B1F=33840, B2S=33888, BIH=33936, BHH=34080, BDEC=34224;
constexpr int SQI=34232, SQIF=34296, SFTQI=34360, SFTQIF=34424, SHTRIH=34488;
constexpr int HLo=34552, HRo=34600;
constexpr int HSH=34648;            // 48x128
constexpr int XSH=40792;            // 8x130 halo
constexpr int MPo=41832, MFo=42856, MYo=43880;
constexpr int R0o=44904, R1o=51048; // 48x128 each
constexpr int SMEM_FLOATS=57192;
constexpr int SMEM_BYTES=SMEM_FLOATS*4;  // 228,768 B

__device__ __forceinline__ ull pack2(float a, float b){ull r;asm("mov.b64 %0,{%1,%2};":"=l"(r):"f"(a),"f"(b));return r;}
__device__ __forceinline__ void unpack2(ull v, float&a, float&b){asm("mov.b64 {%0,%1},%2;":"=f"(a),"=f"(b):"l"(v));}
__device__ __forceinline__ ull fma2(ull a, ull b, ull c){ull d;asm("fma.rn.f32x2 %0,%1,%2,%3;":"=l"(d):"l"(a),"l"(b),"l"(c));return d;}
__device__ __forceinline__ ull add2(ull a, ull b){ull d;asm("add.rn.f32x2 %0,%1,%2;":"=l"(d):"l"(a),"l"(b));return d;}
__device__ __forceinline__ float sigmf(float x){ return 1.f/(1.f+__expf(-x)); }
__device__ __forceinline__ float tanhfast(float x){ return 1.f - 2.f/(__expf(2.f*x)+1.f); }

__device__ __forceinline__ void gridbar(int tid){
    __syncthreads();
    if (tid == 0) {
        unsigned gen = g_gen;
        __threadfence();
        if (atomicAdd(&g_cnt, 1u) == NBLK-1u) {
            g_cnt = 0;
            __threadfence();
            g_gen = gen + 1u;
        } else {
            while (g_gen == gen) { __nanosleep(32); }
        }
        __threadfence();
    }
    __syncthreads();
}

// 64-thread parallel prep: fp64 GJ inverses in shared + small products
__global__ void prep_small(const float* __restrict__ F, const float* __restrict__ H,
                           const float* __restrict__ Q, const float* __restrict__ R,
                           const float* __restrict__ b2p, const float* __restrict__ b2f,
                           const float* __restrict__ b2y) {
    __shared__ double A8[64], I8[64], A4[16], I4[16], T2[64], TH[32];
    int t = threadIdx.x;           // 64 threads
    int r = t >> 3, j = t & 7;
    if (t == 0) g_cnt = 0u;
    A8[t] = (double)Q[t]; I8[t] = (r==j) ? 1.0 : 0.0;
    if (t < 16) { A4[t] = (double)R[t]; I4[t] = ((t>>2)==(t&3)) ? 1.0 : 0.0; }
    __syncthreads();
    // 8x8 GJ (no pivoting; Q is SPD)
    for (int c = 0; c < 8; c++) {
        double piv = A8[c*8+c];
        double f = A8[r*8+c] / piv;
        double acj = A8[c*8+j], icj = I8[c*8+j];
        __syncthreads();
        if (r == c) { A8[t] = acj / piv; I8[t] = icj / piv; }
        else        { A8[t] -= f*acj;    I8[t] -= f*icj; }
        __syncthreads();
    }
    // 4x4 GJ (R is SPD)
    for (int c = 0; c < 4; c++) {
        double piv=1.0, f=0.0, acj=0.0, icj=0.0;
        if (t < 16) {
            int r4 = t>>2;
            piv = A4[c*4+c]; f = A4[r4*4+c]/piv; acj = A4[c*4+(t&3)]; icj = I4[c*4+(t&3)];
        }
        __syncthreads();
        if (t < 16) {
            int r4 = t>>2;
            if (r4 == c) { A4[t] = acj/piv; I4[t] = icj/piv; }
            else         { A4[t] -= f*acj;  I4[t] -= f*icj; }
        }
        __syncthreads();
    }
    // products
    g_Qi[t] = (float)I8[t];
    double s = 0;
    for (int k = 0; k < 8; k++) s += I8[r*8+k]*(double)F[k*8+j];
    g_QiF[t] = (float)s;
    s = 0;
    for (int k = 0; k < 8; k++) s += (double)F[k*8+r]*I8[k*8+j];
    T2[t] = s; g_FtQi[t] = (float)s;
    if (t < 32) {
        int i = t>>2, z = t&3;
        double u = 0;
        for (int y = 0; y < 4; y++) u += (double)H[y*8+i]*I4[y*4+z];
        TH[t] = u; g_HtRi[t] = (float)u;
    }
    __syncthreads();
    s = 0;
    for (int k = 0; k < 8; k++) s += T2[r*8+k]*(double)F[k*8+j];
    g_FtQiF[t] = (float)s;
    s = 0;
    for (int z = 0; z < 4; z++) s += TH[r*4+z]*(double)H[z*8+j];
    g_HtRiH[t] = (float)s;
    if (t < 48) g_b2sum[t] = b2p[t]+b2f[t]+b2y[t];
}

__global__ void prep_nodes(const float* __restrict__ ys, const float* __restrict__ H,
                           const float* __restrict__ W_hy, const float* __restrict__ b_hy,
                           const float* __restrict__ W1y, const float* __restrict__ b1y) {
    int node = blockIdx.x * blockDim.x + threadIdx.x;
    if (node >= Bn*Tn) return;
    int b = node / Tn, t = node - b*Tn;
    float yv[4];
    #pragma unroll
    for (int z=0;z<4;z++) yv[z] = ys[(b*Tn+t)*4+z];
    #pragma unroll
    for (int i=0;i<8;i++){
        float s0=0.f, s1=0.f;
        #pragma unroll
        for (int y=0;y<4;y++){ s0=fmaf(H[y*8+i],yv[y],s0); s1=fmaf(g_HtRi[i*4+y],yv[y],s1); }
        g_xs0[(b*8+i)*Tn+t]=s0; g_cy[(b*8+i)*Tn+t]=s1;
    }
    float hy[48];
    #pragma unroll
    for (int o=0;o<48;o++){
        float s=b_hy[o];
        #pragma unroll
        for (int y=0;y<4;y++) s=fmaf(W_hy[o*4+y],yv[y],s);
        hy[o]=s;
    }
    for (int o=0;o<48;o++){
        float s=b1y[o];
        #pragma unroll
        for (int k=0;k<48;k++) s=fmaf(W1y[o*104+48+k],hy[k],s);
        g_yterm[(b*Tn+t)*48+o]=s;
    }
}

// edge (past/fut): interleaved center+neighbor weight quads
template<int SHIFT>
__device__ __forceinline__ void edge1pf(const float* __restrict__ sm, int WEo_, int WMo_,
    const float* __restrict__ msg, const float* __restrict__ hsh, float* __restrict__ r,
    ull acc[3][2], int rg, int rbase, int lane, int cbase,
    const float* __restrict__ lsrc, int lstr, const float* __restrict__ rsrc, int rstr)
{
    #pragma unroll 2
    for (int k = 0; k < 48; k++) {
        float2 v = *(const float2*)&hsh[k*128 + cbase];
        ull b0 = pack2(v.x,v.x), b1 = pack2(v.y,v.y);
        ull n0, n1;
        if (SHIFT < 0) {
            float pv = __shfl_up_sync(0xffffffffu, v.y, 1);
            if (lane == 0) pv = lsrc[k*lstr];
            n0 = pack2(pv,pv); n1 = b0;
        } else {
            float qv = __shfl_down_sync(0xffffffffu, v.x, 1);
            if (lane == 31) qv = rsrc[k*rstr];
            n0 = b1; n1 = pack2(qv,qv);
        }
        const ulonglong2* wrow = (const ulonglong2*)&sm[WEo_ + (k*24 + 3*rg)*4];
        #pragma unroll
        for (int p = 0; p < 3; p++) {
            ulonglong2 wv = wrow[p];
            acc[p][0] = fma2(wv.x, b0, acc[p][0]);
            acc[p][1] = fma2(wv.x, b1, acc[p][1]);
            acc[p][0] = fma2(wv.y, n0, acc[p][0]);
            acc[p][1] = fma2(wv.y, n1, acc[p][1]);
        }
    }
    #pragma unroll
    for (int k = 0; k < 8; k++) {
        float2 m = *(const float2*)&msg[k*128 + cbase];
        ull b0 = pack2(m.x,m.x), b1 = pack2(m.y,m.y);
        #pragma unroll
        for (int p = 0; p < 3; p++) {
            ull wp = *(const ull*)&sm[WMo_ + k*48 + rbase + 2*p];
            acc[p][0] = fma2(wp,b0,acc[p][0]);
            acc[p][1] = fma2(wp,b1,acc[p][1]);
        }
    }
    #pragma unroll
    for (int p = 0; p < 3; p++) {
        float x0,x1,y0,y1;
        unpack2(acc[p][0],x0,y0); unpack2(acc[p][1],x1,y1);
        int o0 = rbase + 2*p;
        r[o0*128 + cbase]       = fmaxf(x0,0.f);
        r[o0*128 + cbase+1]     = fmaxf(x1,0.f);
        r[(o0+1)*128 + cbase]   = fmaxf(y0,0.f);
        r[(o0+1)*128 + cbase+1] = fmaxf(y1,0.f);
    }
}

// edge y: center-only, [k][o] table
__device__ __forceinline__ void edge1y(const float* __restrict__ sm,
    const float* __restrict__ msg, const float* __restrict__ hsh, float* __restrict__ r,
    ull acc[3][2], int rbase, int cbase)
{
    #pragma unroll 2
    for (int k = 0; k < 48; k++) {
        float2 v = *(const float2*)&hsh[k*128 + cbase];
        ull b0 = pack2(v.x,v.x), b1 = pack2(v.y,v.y);
        #pragma unroll
        for (int p = 0; p < 3; p++) {
            ull wp = *(const ull*)&sm[WYH + k*48 + rbase + 2*p];
            acc[p][0] = fma2(wp,b0,acc[p][0]);
            acc[p][1] = fma2(wp,b1,acc[p][1]);
        }
    }
    #pragma unroll
    for (int k = 0; k < 8; k++) {
        float2 m = *(const float2*)&msg[k*128 + cbase];
        ull b0 = pack2(m.x,m.x), b1 = pack2(m.y,m.y);
        #pragma unroll
        for (int p = 0; p < 3; p++) {
            ull wp = *(const ull*)&sm[WYM + k*48 + rbase + 2*p];
            acc[p][0] = fma2(wp,b0,acc[p][0]);
            acc[p][1] = fma2(wp,b1,acc[p][1]);
        }
    }
    #pragma unroll
    for (int p = 0; p < 3; p++) {
        float x0,x1,y0,y1;
        unpack2(acc[p][0],x0,y0); unpack2(acc[p][1],x1,y1);
        int o0 = rbase + 2*p;
        r[o0*128 + cbase]       = fmaxf(x0,0.f);
        r[o0*128 + cbase+1]     = fmaxf(x1,0.f);
        r[(o0+1)*128 + cbase]   = fmaxf(y0,0.f);
        r[(o0+1)*128 + cbase+1] = fmaxf(y1,0.f);
    }
}

__device__ __forceinline__ void layer2v(const float* __restrict__ sm, int W2o_,
    const float* __restrict__ r, ull agg[3][2], int rbase, int cbase)
{
    #pragma unroll 2
    for (int k = 0; k < 48; k++) {
        float2 v = *(const float2*)&r[k*128 + cbase];
        ull b0 = pack2(v.x,v.x), b1 = pack2(v.y,v.y);
        #pragma unroll
        for (int p = 0; p < 3; p++) {
            ull wp = *(const ull*)&sm[W2o_ + k*48 + rbase + 2*p];
            agg[p][0] = fma2(wp,b0,agg[p][0]);
            agg[p][1] = fma2(wp,b1,agg[p][1]);
        }
    }
}

__global__ void __launch_bounds__(TPB, 1)
persist_kernel(const float* __restrict__ hx0, float* __restrict__ out, int iters,
            const float* __restrict__ W1p, const float* __restrict__ b1p,
            const float* __restrict__ W2p,
            const float* __restrict__ W1f, const float* __restrict__ b1f,
            const float* __restrict__ W2f,
            const float* __restrict__ W1y, const float* __restrict__ W2y,
            const float* __restrict__ Wih, const float* __restrict__ bih,
            const float* __restrict__ Whh, const float* __restrict__ bhh,
            const float* __restrict__ Wdec, const float* __restrict__ bdec) {
    extern __shared__ float sm[];
    float* hsh = sm + HSH;  float* xsh = sm + XSH;
    float* r0 = sm + R0o;   float* r1 = sm + R1o;

    const int tid = threadIdx.x;
    const int b = blockIdx.y;
    const int c = blockIdx.x;
    const int t0 = c * NT;

    // ---- one-time staging ----
    // interleaved edge tables {c0,c1,n0,n1}
    for (int idx = tid; idx < 48*24; idx += TPB) {
        int k = idx/24, p = idx - k*24;
        float* d = &sm[WEP + idx*4];
        d[0] = W1p[(2*p)*104 + k];      d[1] = W1p[(2*p+1)*104 + k];
        d[2] = W1p[(2*p)*104 + 48 + k]; d[3] = W1p[(2*p+1)*104 + 48 + k];
        float* e = &sm[WEF + idx*4];
        e[0] = W1f[(2*p)*104 + k];      e[1] = W1f[(2*p+1)*104 + k];
        e[2] = W1f[(2*p)*104 + 48 + k]; e[3] = W1f[(2*p+1)*104 + 48 + k];
    }
    for (int idx = tid; idx < 48*48; idx += TPB) {
        int o = idx/48, k = idx - o*48;
        sm[WYH + k*48 + o] = W1y[o*104 + k];
        sm[W2P + k*48 + o] = W2p[idx];
        sm[W2F + k*48 + o] = W2f[idx];
        sm[W2Y + k*48 + o] = W2y[idx];
    }
    // interleaved GRU table {ih0,ih1,hh0,hh1}
    for (int idx = tid; idx < 48*72; idx += TPB) {
        int k = idx/72, p = idx - k*72;
        float* d = &sm[WG + idx*4];
        d[0] = Wih[(2*p)*48 + k]; d[1] = Wih[(2*p+1)*48 + k];
        d[2] = Whh[(2*p)*48 + k]; d[3] = Whh[(2*p+1)*48 + k];
    }
    for (int idx = tid; idx < 48*8; idx += TPB) {
        int o = idx/8, k = idx - o*8;
        sm[WPM + k*48 + o] = W1p[o*104 + 96 + k];
        sm[WFM + k*48 + o] = W1f[o*104 + 96 + k];
        sm[WYM + k*48 + o] = W1y[o*104 + 96 + k];
    }
    for (int idx = tid; idx < 384; idx += TPB) sm[WDEC+idx]=Wdec[idx];
    if (tid < 48) { sm[B1P+tid]=b1p[tid]; sm[B1F+tid]=b1f[tid]; sm[B2S+tid]=g_b2sum[tid]; }
    for (int idx = tid; idx < 144; idx += TPB) { sm[BIH+idx]=bih[idx]; sm[BHH+idx]=bhh[idx]; }
    if (tid < 8) sm[BDEC+tid]=bdec[tid];
    for (int idx = tid; idx < 64; idx += TPB) {
        sm[SQI+idx]=g_Qi[idx]; sm[SQIF+idx]=g_QiF[idx]; sm[SFTQI+idx]=g_FtQi[idx];
        sm[SFTQIF+idx]=g_FtQiF[idx]; sm[SHTRIH+idx]=g_HtRiH[idx];
    }
    // initial state
    for (int idx = tid; idx < 48*128; idx += TPB) {
        int k = idx >> 7, cc = idx & 127; int t = t0 + cc;
        hsh[idx] = (t < Tn) ? hx0[(b*48+k)*Tn + t] : 0.f;
    }
    if (tid < 48) {
        int tl = t0 - 1, tr = t0 + 128;
        sm[HLo+tid] = (tl >= 0) ? hx0[(b*48+tid)*Tn + tl] : 0.f;
        sm[HRo+tid] = (tr < Tn) ? hx0[(b*48+tid)*Tn + tr] : 0.f;
    }
    for (int idx = tid; idx < 8*130; idx += TPB) {
        int k = idx / 130, cc = idx - k*130; int t = t0 + cc - 1;
        xsh[idx] = (t >= 0 && t < Tn) ? g_xs0[(b*8+k)*Tn + t] : 0.f;
    }
    __syncthreads();

    const int w = tid >> 5, lane = tid & 31, cg = w & 1, rg = w >> 1;
    const int rbase = 6*rg, cbase = cg*64 + 2*lane;
    const float* lsrc; int lstr; const float* rsrc; int rstr;
    if (cg == 0) { lsrc = sm+HLo; lstr = 1; rsrc = hsh+64; rstr = 128; }
    else         { lsrc = hsh+63; lstr = 128; rsrc = sm+HRo; rstr = 1; }

    for (int it = 0; it < iters; it++) {
        const int par = it & 1;

        // A: messages
        #pragma unroll
        for (int rep = 0; rep < 2; rep++) {
            int item = tid + rep*TPB;
            int i = item >> 7, n = item & 127, t = t0 + n;
            bool valid = t < Tn;
            float accp = 0.f, accf = 0.f;
            float accy = valid ? g_cy[(b*8+i)*Tn + t] : 0.f;
            #pragma unroll
            for (int j = 0; j < 8; j++) {
                float xc = xsh[j*130 + 1 + n];
                accp = fmaf(-sm[SQI+i*8+j], xc, accp);
                accp = fmaf(sm[SQIF+i*8+j], xsh[j*130 + n], accp);
                accf = fmaf(sm[SFTQI+i*8+j], xsh[j*130 + 2 + n], accf);
                accf = fmaf(-sm[SFTQIF+i*8+j], xc, accf);
                accy = fmaf(-sm[SHTRIH+i*8+j], xc, accy);
            }
            sm[MPo + i*128+n] = (valid && t > 0) ? accp : 0.f;
            sm[MFo + i*128+n] = (t < Tn-1) ? accf : 0.f;
            sm[MYo + i*128+n] = valid ? accy : 0.f;
        }
        __syncthreads();

        ull agg[3][2];
        #pragma unroll
        for (int p = 0; p < 3; p++) {
            ull bp = *(const ull*)&sm[B2S + rbase + 2*p];
            agg[p][0] = bp; agg[p][1] = bp;
        }
        // B: edge_p -> r0
        {
            ull acc[3][2];
            #pragma unroll
            for (int p = 0; p < 3; p++) { ull bp = *(const ull*)&sm[B1P+rbase+2*p]; acc[p][0]=bp; acc[p][1]=bp; }
            edge1pf<-1>(sm, WEP, WPM, sm+MPo, hsh, r0, acc, rg, rbase, lane, cbase, lsrc, lstr, rsrc, rstr);
        }
        __syncthreads();
        // C: layer2p(r0) ; edge_f -> r1
        layer2v(sm, W2P, r0, agg, rbase, cbase);
        {
            ull acc[3][2];
            #pragma unroll
            for (int p = 0; p < 3; p++) { ull bp = *(const ull*)&sm[B1F+rbase+2*p]; acc[p][0]=bp; acc[p][1]=bp; }
            edge1pf<1>(sm, WEF, WFM, sm+MFo, hsh, r1, acc, rg, rbase, lane, cbase, lsrc, lstr, rsrc, rstr);
        }
        __syncthreads();
        // D: layer2f(r1) ; edge_y -> r0
        layer2v(sm, W2F, r1, agg, rbase, cbase);
        {
            ull acc[3][2];
            const float* yt = g_yterm + (size_t)b*Tn*48;
            int tc = t0 + cbase;
            #pragma unroll
            for (int p = 0; p < 3; p++) {
                acc[p][0] = (tc   < Tn) ? *(const ull*)&yt[(size_t)tc*48     + rbase+2*p] : 0ull;
                acc[p][1] = (tc+1 < Tn) ? *(const ull*)&yt[(size_t)(tc+1)*48 + rbase+2*p] : 0ull;
            }
            edge1y(sm, sm+MYo, hsh, r0, acc, rbase, cbase);
        }
        __syncthreads();
        // E: layer2y(r0) ; spill agg -> r1
        layer2v(sm, W2Y, r0, agg, rbase, cbase);
        #pragma unroll
        for (int p = 0; p < 3; p++) {
            float x0,x1,y0,y1;
            unpack2(agg[p][0],x0,y0); unpack2(agg[p][1],x1,y1);
            int o0 = rbase + 2*p;
            r1[o0*128+cbase] = x0;   r1[o0*128+cbase+1] = x1;
            r1[(o0+1)*128+cbase] = y0; r1[(o0+1)*128+cbase+1] = y1;
        }
        __syncthreads();

        // F: GRU — single k-loop over agg(r1) + hsh, interleaved WG quads; hnew -> r0
        {
            ull A[9][2], Bv[3][2];
            #pragma unroll
            for (int g = 0; g < 3; g++)
                #pragma unroll
                for (int p = 0; p < 3; p++) {
                    ull bi = *(const ull*)&sm[BIH + g*48 + rbase + 2*p];
                    if (g < 2) bi = add2(bi, *(const ull*)&sm[BHH + g*48 + rbase + 2*p]);
                    A[g*3+p][0] = bi; A[g*3+p][1] = bi;
                }
            #pragma unroll
            for (int p = 0; p < 3; p++) {
                ull bb = *(const ull*)&sm[BHH + 96 + rbase + 2*p];
                Bv[p][0] = bb; Bv[p][1] = bb;
            }
            #pragma unroll 1
            for (int k = 0; k < 48; k++) {
                float2 xv = *(const float2*)&r1[k*128 + cbase];
                float2 hv = *(const float2*)&hsh[k*128 + cbase];
                ull xb0 = pack2(xv.x,xv.x), xb1 = pack2(xv.y,xv.y);
                ull hb0 = pack2(hv.x,hv.x), hb1 = pack2(hv.y,hv.y);
                const ulonglong2* wg = (const ulonglong2*)&sm[WG + k*72*4];
                #pragma unroll
                for (int j = 0; j < 3; j++) {
                    ulonglong2 w0 = wg[3*rg + j];
                    A[j][0] = fma2(w0.x, xb0, A[j][0]); A[j][1] = fma2(w0.x, xb1, A[j][1]);
                    A[j][0] = fma2(w0.y, hb0, A[j][0]); A[j][1] = fma2(w0.y, hb1, A[j][1]);
                    ulonglong2 w1 = wg[24 + 3*rg + j];
                    A[3+j][0] = fma2(w1.x, xb0, A[3+j][0]); A[3+j][1] = fma2(w1.x, xb1, A[3+j][1]);
                    A[3+j][0] = fma2(w1.y, hb0, A[3+j][0]); A[3+j][1] = fma2(w1.y, hb1, A[3+j][1]);
                    ulonglong2 w2 = wg[48 + 3*rg + j];
                    A[6+j][0] = fma2(w2.x, xb0, A[6+j][0]); A[6+j][1] = fma2(w2.x, xb1, A[6+j][1]);
                    Bv[j][0]  = fma2(w2.y, hb0, Bv[j][0]);  Bv[j][1]  = fma2(w2.y, hb1, Bv[j][1]);
                }
            }
            #pragma unroll
            for (int p = 0; p < 3; p++)
                #pragma unroll
                for (int cc2 = 0; cc2 < 2; cc2++) {
                    float rv0,rv1,zv0,zv1,nv0,nv1,bn0,bn1;
                    unpack2(A[p][cc2],rv0,rv1); unpack2(A[3+p][cc2],zv0,zv1);
                    unpack2(A[6+p][cc2],nv0,nv1); unpack2(Bv[p][cc2],bn0,bn1);
                    int cc = cbase + cc2;
                    int o0 = rbase + 2*p, o1 = o0 + 1;
                    float rr0 = sigmf(rv0), rr1 = sigmf(rv1);
                    float zz0 = sigmf(zv0), zz1 = sigmf(zv1);
                    float ng0 = tanhfast(nv0 + rr0*bn0), ng1 = tanhfast(nv1 + rr1*bn1);
                    float h0 = hsh[o0*128 + cc], h1 = hsh[o1*128 + cc];
                    r0[o0*128+cc] = (1.f-zz0)*ng0 + zz0*h0;
                    r0[o1*128+cc] = (1.f-zz1)*ng1 + zz1*h1;
                }
        }
        __syncthreads();

        // G: hnew -> hsh (masked, vectorized), publish boundaries, decoder
        for (int idx = tid*4; idx < 48*128; idx += TPB*4) {
            float4 v = *(const float4*)&r0[idx];
            int cc = idx & 127; int t = t0 + cc;
            if (t+3 >= Tn) {
                v.x = (t   < Tn) ? v.x : 0.f;
                v.y = (t+1 < Tn) ? v.y : 0.f;
                v.z = (t+2 < Tn) ? v.z : 0.f;
                v.w = (t+3 < Tn) ? v.w : 0.f;
            }
            *(float4*)&hsh[idx] = v;
        }
        if (tid < 48) {
            g_hh[par][b][c][0][tid] = r0[tid*128 + 0];
            int t127 = t0 + 127;
            g_hh[par][b][c][1][tid] = (t127 < Tn) ? r0[tid*128 + 127] : 0.f;
        }
        {
            float* outp = out + (size_t)BXT * (1 + it);
            #pragma unroll
            for (int rep = 0; rep < 2; rep++) {
                int item = tid + rep*TPB;
                int i = item >> 7, n = item & 127, t = t0 + n;
                float e = sm[BDEC+i];
                #pragma unroll 8
                for (int k = 0; k < 48; k++) e = fmaf(sm[WDEC+i*48+k], r0[k*128+n], e);
                float xn = 0.f;
                if (t < Tn) {
                    xn = xsh[i*130 + 1 + n]
                       + GAMMA_F * (e + sm[MPo+i*128+n] + sm[MFo+i*128+n] + sm[MYo+i*128+n]);
                    xsh[i*130 + 1 + n] = xn;
                    outp[(b*8+i)*Tn + t] = xn;
                }
                if (n == 0)   g_xh[par][b][c][0][i] = xn;
                if (n == 127) g_xh[par][b][c][1][i] = xn;
            }
        }

        // H: grid barrier, pull neighbor halos
        gridbar(tid);
        if (tid < 48) sm[HLo+tid] = (c > 0) ? g_hh[par][b][c-1][1][tid] : 0.f;
        else if (tid < 96) { int k = tid-48; sm[HRo+k] = (c < NCHUNK-1) ? g_hh[par][b][c+1][0][k] : 0.f; }
        else if (tid < 104) { int i = tid-96; xsh[i*130 + 0] = (c > 0) ? g_xh[par][b][c-1][1][i] : 0.f; }
        else if (tid < 112) { int i = tid-104; xsh[i*130 + 129] = (c < NCHUNK-1) ? g_xh[par][b][c+1][0][i] : 0.f; }
        __syncthreads();
    }
}

extern "C" void kernel_launch(void* const* d_in, const int* in_sizes, int n_in,
                              void* d_out, int out_size) {
    const float* ys   = (const float*)d_in[0];
    const float* hx0  = (const float*)d_in[1];
    const float* F    = (const float*)d_in[2];
    const float* H    = (const float*)d_in[3];
    const float* Q    = (const float*)d_in[4];
    const float* R    = (const float*)d_in[5];
    const float* W_hy = (const float*)d_in[6];
    const float* b_hy = (const float*)d_in[7];
    const float* W1p  = (const float*)d_in[8];
    const float* b1p  = (const float*)d_in[9];
    const float* W2p  = (const float*)d_in[10];
    const float* b2p  = (const float*)d_in[11];
    const float* W1f  = (const float*)d_in[12];
    const float* b1f  = (const float*)d_in[13];
    const float* W2f  = (const float*)d_in[14];
    const float* b2f  = (const float*)d_in[15];
    const float* W1y  = (const float*)d_in[16];
    const float* b1y  = (const float*)d_in[17];
    const float* W2y  = (const float*)d_in[18];
    const float* b2y  = (const float*)d_in[19];
    const float* Wih  = (const float*)d_in[20];
    const float* bih  = (const float*)d_in[21];
    const float* Whh  = (const float*)d_in[22];
    const float* bhh  = (const float*)d_in[23];
    const float* Wdec = (const float*)d_in[24];
    const float* bdec = (const float*)d_in[25];
    float* out = (float*)d_out;

    const int iters = out_size / BXT - 1;

    cudaFuncSetAttribute(persist_kernel, cudaFuncAttributeMaxDynamicSharedMemorySize, SMEM_BYTES);

    prep_small<<<1, 64>>>(F, H, Q, R, b2p, b2f, b2y);
    prep_nodes<<<(Bn*Tn + 127)/128, 128>>>(ys, H, W_hy, b_hy, W1y, b1y);

    dim3 grid(NCHUNK, Bn);
    persist_kernel<<<grid, TPB, SMEM_BYTES>>>(hx0, out, iters,
        W1p, b1p, W2p, W1f, b1f, W2f, W1y, W2y, Wih, bih, Whh, bhh, Wdec, bdec);

    cudaMemcpyAsync(out, out + (size_t)BXT * iters, (size_t)BXT * sizeof(float),
                    cudaMemcpyDeviceToDevice);
}

// round 10
// speedup vs baseline: 2.1505x; 1.0284x over previous
#include <cuda_runtime.h>
#include <math.h>
typedef unsigned long long ull;

#define Bn 16
#define Tn 1000
#define NT 128
#define TPB 512
#define NCHUNK 8
#define NBLK (Bn*NCHUNK)
#define GAMMA_F 1e-4f
#define BXT (Bn*8*Tn)
#define BHT (Bn*48*Tn)

__device__ float g_xs0[BXT];
__device__ float g_cy[BXT];
__device__ float g_yterm[BHT];   // [b][t][48]
__device__ float g_Qi[64], g_QiF[64], g_FtQi[64], g_FtQiF[64], g_HtRiH[64], g_HtRi[32];
__device__ float g_b2sum[48];
__device__ float g_hh[2][Bn][NCHUNK][2][48];
__device__ float g_xh[2][Bn][NCHUNK][2][8];
__device__ unsigned g_cnt;
__device__ volatile unsigned g_gen;

// shared layout (floats)
constexpr int WEP=0, WEF=4608, WYH=9216;
constexpr int W2P=11520, W2F=13824, W2Y=16128;
constexpr int WG=18432;
constexpr int WPM=32256, WFM=32640, WYM=33024, WDEC=33408;
constexpr int B1P=33792, B1F=33840, B2S=33888, BIH=33936, BHH=34080, BDEC=34224;
constexpr int SQI=34232, SQIF=34296, SFTQI=34360, SFTQIF=34424, SHTRIH=34488;
constexpr int HLo=34552, HRo=34600;
constexpr int BUF0=34648;           // 48x128
constexpr int XSH=40792;            // 8x130 halo
constexpr int MPo=41832, MFo=42856, MYo=43880;
constexpr int BUF1=44904, SCR=51048; // 48x128 each
constexpr int SMEM_FLOATS=57192;
constexpr int SMEM_BYTES=SMEM_FLOATS*4;  // 228,768 B

__device__ __forceinline__ ull pack2(float a, float b){ull r;asm("mov.b64 %0,{%1,%2};":"=l"(r):"f"(a),"f"(b));return r;}
__device__ __forceinline__ void unpack2(ull v, float&a, float&b){asm("mov.b64 {%0,%1},%2;":"=f"(a),"=f"(b):"l"(v));}
__device__ __forceinline__ ull fma2(ull a, ull b, ull c){ull d;asm("fma.rn.f32x2 %0,%1,%2,%3;":"=l"(d):"l"(a),"l"(b),"l"(c));return d;}
__device__ __forceinline__ ull add2(ull a, ull b){ull d;asm("add.rn.f32x2 %0,%1,%2;":"=l"(d):"l"(a),"l"(b));return d;}
__device__ __forceinline__ float sigmf(float x){ return 1.f/(1.f+__expf(-x)); }
__device__ __forceinline__ float tanhfast(float x){ return 1.f - 2.f/(__expf(2.f*x)+1.f); }

// 64-thread parallel prep
__global__ void prep_small(const float* __restrict__ F, const float* __restrict__ H,
                           const float* __restrict__ Q, const float* __restrict__ R,
                           const float* __restrict__ b2p, const float* __restrict__ b2f,
                           const float* __restrict__ b2y) {
    __shared__ double A8[64], I8[64], A4[16], I4[16], T2[64], TH[32];
    int t = threadIdx.x;
    int r = t >> 3, j = t & 7;
    if (t == 0) g_cnt = 0u;
    A8[t] = (double)Q[t]; I8[t] = (r==j) ? 1.0 : 0.0;
    if (t < 16) { A4[t] = (double)R[t]; I4[t] = ((t>>2)==(t&3)) ? 1.0 : 0.0; }
    __syncthreads();
    for (int c = 0; c < 8; c++) {
        double piv = A8[c*8+c];
        double f = A8[r*8+c] / piv;
        double acj = A8[c*8+j], icj = I8[c*8+j];
        __syncthreads();
        if (r == c) { A8[t] = acj / piv; I8[t] = icj / piv; }
        else        { A8[t] -= f*acj;    I8[t] -= f*icj; }
        __syncthreads();
    }
    for (int c = 0; c < 4; c++) {
        double piv=1.0, f=0.0, acj=0.0, icj=0.0;
        if (t < 16) {
            int r4 = t>>2;
            piv = A4[c*4+c]; f = A4[r4*4+c]/piv; acj = A4[c*4+(t&3)]; icj = I4[c*4+(t&3)];
        }
        __syncthreads();
        if (t < 16) {
            int r4 = t>>2;
            if (r4 == c) { A4[t] = acj/piv; I4[t] = icj/piv; }
            else         { A4[t] -= f*acj;  I4[t] -= f*icj; }
        }
        __syncthreads();
    }
    g_Qi[t] = (float)I8[t];
    double s = 0;
    for (int k = 0; k < 8; k++) s += I8[r*8+k]*(double)F[k*8+j];
    g_QiF[t] = (float)s;
    s = 0;
    for (int k = 0; k < 8; k++) s += (double)F[k*8+r]*I8[k*8+j];
    T2[t] = s; g_FtQi[t] = (float)s;
    if (t < 32) {
        int i = t>>2, z = t&3;
        double u = 0;
        for (int y = 0; y < 4; y++) u += (double)H[y*8+i]*I4[y*4+z];
        TH[t] = u; g_HtRi[t] = (float)u;
    }
    __syncthreads();
    s = 0;
    for (int k = 0; k < 8; k++) s += T2[r*8+k]*(double)F[k*8+j];
    g_FtQiF[t] = (float)s;
    s = 0;
    for (int z = 0; z < 4; z++) s += TH[r*4+z]*(double)H[z*8+j];
    g_HtRiH[t] = (float)s;
    if (t < 48) g_b2sum[t] = b2p[t]+b2f[t]+b2y[t];
}

__global__ void prep_nodes(const float* __restrict__ ys, const float* __restrict__ H,
                           const float* __restrict__ W_hy, const float* __restrict__ b_hy,
                           const float* __restrict__ W1y, const float* __restrict__ b1y) {
    int node = blockIdx.x * blockDim.x + threadIdx.x;
    if (node >= Bn*Tn) return;
    int b = node / Tn, t = node - b*Tn;
    float yv[4];
    #pragma unroll
    for (int z=0;z<4;z++) yv[z] = ys[(b*Tn+t)*4+z];
    #pragma unroll
    for (int i=0;i<8;i++){
        float s0=0.f, s1=0.f;
        #pragma unroll
        for (int y=0;y<4;y++){ s0=fmaf(H[y*8+i],yv[y],s0); s1=fmaf(g_HtRi[i*4+y],yv[y],s1); }
        g_xs0[(b*8+i)*Tn+t]=s0; g_cy[(b*8+i)*Tn+t]=s1;
    }
    float hy[48];
    #pragma unroll
    for (int o=0;o<48;o++){
        float s=b_hy[o];
        #pragma unroll
        for (int y=0;y<4;y++) s=fmaf(W_hy[o*4+y],yv[y],s);
        hy[o]=s;
    }
    for (int o=0;o<48;o++){
        float s=b1y[o];
        #pragma unroll
        for (int k=0;k<48;k++) s=fmaf(W1y[o*104+48+k],hy[k],s);
        g_yterm[(b*Tn+t)*48+o]=s;
    }
}

// messages (provisional at boundary cols; fixed later from neighbor publishes)
__device__ __forceinline__ void msgphase(float* __restrict__ sm, const float* __restrict__ xsh,
                                         int b, int t0, int tid) {
    #pragma unroll
    for (int rep = 0; rep < 2; rep++) {
        int item = tid + rep*TPB;
        int i = item >> 7, n = item & 127, t = t0 + n;
        bool valid = t < Tn;
        float accp = 0.f, accf = 0.f;
        float accy = valid ? g_cy[(b*8+i)*Tn + t] : 0.f;
        #pragma unroll
        for (int j = 0; j < 8; j++) {
            float xc = xsh[j*130 + 1 + n];
            accp = fmaf(-sm[SQI+i*8+j], xc, accp);
            accp = fmaf(sm[SQIF+i*8+j], xsh[j*130 + n], accp);
            accf = fmaf(sm[SFTQI+i*8+j], xsh[j*130 + 2 + n], accf);
            accf = fmaf(-sm[SFTQIF+i*8+j], xc, accf);
            accy = fmaf(-sm[SHTRIH+i*8+j], xc, accy);
        }
        sm[MPo + i*128+n] = (valid && t > 0) ? accp : 0.f;
        sm[MFo + i*128+n] = (t < Tn-1) ? accf : 0.f;
        sm[MYo + i*128+n] = valid ? accy : 0.f;
    }
}

template<int SHIFT>
__device__ __forceinline__ void edge1pf(const float* __restrict__ sm, int WEo_, int WMo_,
    const float* __restrict__ msg, const float* __restrict__ hsh, float* __restrict__ r,
    ull acc[3][2], int rg, int rbase, int lane, int cbase,
    const float* __restrict__ lsrc, int lstr, const float* __restrict__ rsrc, int rstr)
{
    #pragma unroll 4
    for (int k = 0; k < 48; k++) {
        float2 v = *(const float2*)&hsh[k*128 + cbase];
        ull b0 = pack2(v.x,v.x), b1 = pack2(v.y,v.y);
        ull n0, n1;
        if (SHIFT < 0) {
            float pv = __shfl_up_sync(0xffffffffu, v.y, 1);
            if (lane == 0) pv = lsrc[k*lstr];
            n0 = pack2(pv,pv); n1 = b0;
        } else {
            float qv = __shfl_down_sync(0xffffffffu, v.x, 1);
            if (lane == 31) qv = rsrc[k*rstr];
            n0 = b1; n1 = pack2(qv,qv);
        }
        const ulonglong2* wrow = (const ulonglong2*)&sm[WEo_ + (k*24 + 3*rg)*4];
        #pragma unroll
        for (int p = 0; p < 3; p++) {
            ulonglong2 wv = wrow[p];
            acc[p][0] = fma2(wv.x, b0, acc[p][0]);
            acc[p][1] = fma2(wv.x, b1, acc[p][1]);
            acc[p][0] = fma2(wv.y, n0, acc[p][0]);
            acc[p][1] = fma2(wv.y, n1, acc[p][1]);
        }
    }
    #pragma unroll
    for (int k = 0; k < 8; k++) {
        float2 m = *(const float2*)&msg[k*128 + cbase];
        ull b0 = pack2(m.x,m.x), b1 = pack2(m.y,m.y);
        #pragma unroll
        for (int p = 0; p < 3; p++) {
            ull wp = *(const ull*)&sm[WMo_ + k*48 + rbase + 2*p];
            acc[p][0] = fma2(wp,b0,acc[p][0]);
            acc[p][1] = fma2(wp,b1,acc[p][1]);
        }
    }
    #pragma unroll
    for (int p = 0; p < 3; p++) {
        float x0,x1,y0,y1;
        unpack2(acc[p][0],x0,y0); unpack2(acc[p][1],x1,y1);
        int o0 = rbase + 2*p;
        r[o0*128 + cbase]       = fmaxf(x0,0.f);
        r[o0*128 + cbase+1]     = fmaxf(x1,0.f);
        r[(o0+1)*128 + cbase]   = fmaxf(y0,0.f);
        r[(o0+1)*128 + cbase+1] = fmaxf(y1,0.f);
    }
}

__device__ __forceinline__ void edge1y(const float* __restrict__ sm,
    const float* __restrict__ msg, const float* __restrict__ hsh, float* __restrict__ r,
    ull acc[3][2], int rbase, int cbase)
{
    #pragma unroll 4
    for (int k = 0; k < 48; k++) {
        float2 v = *(const float2*)&hsh[k*128 + cbase];
        ull b0 = pack2(v.x,v.x), b1 = pack2(v.y,v.y);
        #pragma unroll
        for (int p = 0; p < 3; p++) {
            ull wp = *(const ull*)&sm[WYH + k*48 + rbase + 2*p];
            acc[p][0] = fma2(wp,b0,acc[p][0]);
            acc[p][1] = fma2(wp,b1,acc[p][1]);
        }
    }
    #pragma unroll
    for (int k = 0; k < 8; k++) {
        float2 m = *(const float2*)&msg[k*128 + cbase];
        ull b0 = pack2(m.x,m.x), b1 = pack2(m.y,m.y);
        #pragma unroll
        for (int p = 0; p < 3; p++) {
            ull wp = *(const ull*)&sm[WYM + k*48 + rbase + 2*p];
            acc[p][0] = fma2(wp,b0,acc[p][0]);
            acc[p][1] = fma2(wp,b1,acc[p][1]);
        }
    }
    #pragma unroll
    for (int p = 0; p < 3; p++) {
        float x0,x1,y0,y1;
        unpack2(acc[p][0],x0,y0); unpack2(acc[p][1],x1,y1);
        int o0 = rbase + 2*p;
        r[o0*128 + cbase]       = fmaxf(x0,0.f);
        r[o0*128 + cbase+1]     = fmaxf(x1,0.f);
        r[(o0+1)*128 + cbase]   = fmaxf(y0,0.f);
        r[(o0+1)*128 + cbase+1] = fmaxf(y1,0.f);
    }
}

__device__ __forceinline__ void layer2v(const float* __restrict__ sm, int W2o_,
    const float* __restrict__ r, ull agg[3][2], int rbase, int cbase)
{
    #pragma unroll 4
    for (int k = 0; k < 48; k++) {
        float2 v = *(const float2*)&r[k*128 + cbase];
        ull b0 = pack2(v.x,v.x), b1 = pack2(v.y,v.y);
        #pragma unroll
        for (int p = 0; p < 3; p++) {
            ull wp = *(const ull*)&sm[W2o_ + k*48 + rbase + 2*p];
            agg[p][0] = fma2(wp,b0,agg[p][0]);
            agg[p][1] = fma2(wp,b1,agg[p][1]);
        }
    }
}

__global__ void __launch_bounds__(TPB, 1)
persist_kernel(const float* __restrict__ hx0, float* __restrict__ out, int iters,
            const float* __restrict__ W1p, const float* __restrict__ b1p,
            const float* __restrict__ W2p,
            const float* __restrict__ W1f, const float* __restrict__ b1f,
            const float* __restrict__ W2f,
            const float* __restrict__ W1y, const float* __restrict__ W2y,
            const float* __restrict__ Wih, const float* __restrict__ bih,
            const float* __restrict__ Whh, const float* __restrict__ bhh,
            const float* __restrict__ Wdec, const float* __restrict__ bdec) {
    extern __shared__ float sm[];
    float* xsh = sm + XSH;
    float* buf0 = sm + BUF0;  float* buf1 = sm + BUF1;  float* scr = sm + SCR;

    const int tid = threadIdx.x;
    const int b = blockIdx.y;
    const int c = blockIdx.x;
    const int t0 = c * NT;

    // ---- one-time staging ----
    for (int idx = tid; idx < 48*24; idx += TPB) {
        int k = idx/24, p = idx - k*24;
        float* d = &sm[WEP + idx*4];
        d[0] = W1p[(2*p)*104 + k];      d[1] = W1p[(2*p+1)*104 + k];
        d[2] = W1p[(2*p)*104 + 48 + k]; d[3] = W1p[(2*p+1)*104 + 48 + k];
        float* e = &sm[WEF + idx*4];
        e[0] = W1f[(2*p)*104 + k];      e[1] = W1f[(2*p+1)*104 + k];
        e[2] = W1f[(2*p)*104 + 48 + k]; e[3] = W1f[(2*p+1)*104 + 48 + k];
    }
    for (int idx = tid; idx < 48*48; idx += TPB) {
        int o = idx/48, k = idx - o*48;
        sm[WYH + k*48 + o] = W1y[o*104 + k];
        sm[W2P + k*48 + o] = W2p[idx];
        sm[W2F + k*48 + o] = W2f[idx];
        sm[W2Y + k*48 + o] = W2y[idx];
    }
    for (int idx = tid; idx < 48*72; idx += TPB) {
        int k = idx/72, p = idx - k*72;
        float* d = &sm[WG + idx*4];
        d[0] = Wih[(2*p)*48 + k]; d[1] = Wih[(2*p+1)*48 + k];
        d[2] = Whh[(2*p)*48 + k]; d[3] = Whh[(2*p+1)*48 + k];
    }
    for (int idx = tid; idx < 48*8; idx += TPB) {
        int o = idx/8, k = idx - o*8;
        sm[WPM + k*48 + o] = W1p[o*104 + 96 + k];
        sm[WFM + k*48 + o] = W1f[o*104 + 96 + k];
        sm[WYM + k*48 + o] = W1y[o*104 + 96 + k];
    }
    for (int idx = tid; idx < 384; idx += TPB) sm[WDEC+idx]=Wdec[idx];
    if (tid < 48) { sm[B1P+tid]=b1p[tid]; sm[B1F+tid]=b1f[tid]; sm[B2S+tid]=g_b2sum[tid]; }
    for (int idx = tid; idx < 144; idx += TPB) { sm[BIH+idx]=bih[idx]; sm[BHH+idx]=bhh[idx]; }
    if (tid < 8) sm[BDEC+tid]=bdec[tid];
    for (int idx = tid; idx < 64; idx += TPB) {
        sm[SQI+idx]=g_Qi[idx]; sm[SQIF+idx]=g_QiF[idx]; sm[SFTQI+idx]=g_FtQi[idx];
        sm[SFTQIF+idx]=g_FtQiF[idx]; sm[SHTRIH+idx]=g_HtRiH[idx];
    }
    for (int idx = tid; idx < 48*128; idx += TPB) {
        int k = idx >> 7, cc = idx & 127; int t = t0 + cc;
        buf0[idx] = (t < Tn) ? hx0[(b*48+k)*Tn + t] : 0.f;
    }
    if (tid < 48) {
        int tl = t0 - 1, tr = t0 + 128;
        sm[HLo+tid] = (tl >= 0) ? hx0[(b*48+tid)*Tn + tl] : 0.f;
        sm[HRo+tid] = (tr < Tn) ? hx0[(b*48+tid)*Tn + tr] : 0.f;
    }
    for (int idx = tid; idx < 8*130; idx += TPB) {
        int k = idx / 130, cc = idx - k*130; int t = t0 + cc - 1;
        xsh[idx] = (t >= 0 && t < Tn) ? g_xs0[(b*8+k)*Tn + t] : 0.f;
    }
    __syncthreads();

    const int w = tid >> 5, lane = tid & 31, cg = w & 1, rg = w >> 1;
    const int rbase = 6*rg, cbase = cg*64 + 2*lane;
    const int inv = Tn - t0;   // first invalid column (>=128 if none)

    // prologue: messages for it=0 (halos staged => exact)
    msgphase(sm, xsh, b, t0, tid);
    __syncthreads();

    for (int it = 0; it < iters; it++) {
        float* hcur  = (it & 1) ? buf1 : buf0;
        float* hnext = (it & 1) ? buf0 : buf1;
        const float* lsrc; int lstr; const float* rsrc; int rstr;
        if (cg == 0) { lsrc = sm+HLo; lstr = 1; rsrc = hcur+64; rstr = 128; }
        else         { lsrc = hcur+63; lstr = 128; rsrc = sm+HRo; rstr = 1; }

        ull agg[3][2];
        #pragma unroll
        for (int p = 0; p < 3; p++) {
            ull bp = *(const ull*)&sm[B2S + rbase + 2*p];
            agg[p][0] = bp; agg[p][1] = bp;
        }
        // B: edge_p -> hnext
        {
            ull acc[3][2];
            #pragma unroll
            for (int p = 0; p < 3; p++) { ull bp = *(const ull*)&sm[B1P+rbase+2*p]; acc[p][0]=bp; acc[p][1]=bp; }
            edge1pf<-1>(sm, WEP, WPM, sm+MPo, hcur, hnext, acc, rg, rbase, lane, cbase, lsrc, lstr, rsrc, rstr);
        }
        __syncthreads();
        // C: layer2p(hnext) ; edge_f -> scr
        layer2v(sm, W2P, hnext, agg, rbase, cbase);
        {
            ull acc[3][2];
            #pragma unroll
            for (int p = 0; p < 3; p++) { ull bp = *(const ull*)&sm[B1F+rbase+2*p]; acc[p][0]=bp; acc[p][1]=bp; }
            edge1pf<1>(sm, WEF, WFM, sm+MFo, hcur, scr, acc, rg, rbase, lane, cbase, lsrc, lstr, rsrc, rstr);
        }
        __syncthreads();
        // D: layer2f(scr) ; edge_y -> hnext
        layer2v(sm, W2F, scr, agg, rbase, cbase);
        {
            ull acc[3][2];
            const float* yt = g_yterm + (size_t)b*Tn*48;
            int tc = t0 + cbase;
            #pragma unroll
            for (int p = 0; p < 3; p++) {
                acc[p][0] = (tc   < Tn) ? *(const ull*)&yt[(size_t)tc*48     + rbase+2*p] : 0ull;
                acc[p][1] = (tc+1 < Tn) ? *(const ull*)&yt[(size_t)(tc+1)*48 + rbase+2*p] : 0ull;
            }
            edge1y(sm, sm+MYo, hcur, hnext, acc, rbase, cbase);
        }
        __syncthreads();
        // E: layer2y(hnext) ; spill agg -> scr
        layer2v(sm, W2Y, hnext, agg, rbase, cbase);
        #pragma unroll
        for (int p = 0; p < 3; p++) {
            float x0,x1,y0,y1;
            unpack2(agg[p][0],x0,y0); unpack2(agg[p][1],x1,y1);
            int o0 = rbase + 2*p;
            scr[o0*128+cbase] = x0;   scr[o0*128+cbase+1] = x1;
            scr[(o0+1)*128+cbase] = y0; scr[(o0+1)*128+cbase+1] = y1;
        }
        __syncthreads();

        // F: GRU — reads scr(agg) + hcur, writes hnew -> hnext
        {
            ull A[9][2], Bv[3][2];
            #pragma unroll
            for (int g = 0; g < 3; g++)
                #pragma unroll
                for (int p = 0; p < 3; p++) {
                    ull bi = *(const ull*)&sm[BIH + g*48 + rbase + 2*p];
                    if (g < 2) bi = add2(bi, *(const ull*)&sm[BHH + g*48 + rbase + 2*p]);
                    A[g*3+p][0] = bi; A[g*3+p][1] = bi;
                }
            #pragma unroll
            for (int p = 0; p < 3; p++) {
                ull bb = *(const ull*)&sm[BHH + 96 + rbase + 2*p];
                Bv[p][0] = bb; Bv[p][1] = bb;
            }
            #pragma unroll 2
            for (int k = 0; k < 48; k++) {
                float2 xv = *(const float2*)&scr[k*128 + cbase];
                float2 hv = *(const float2*)&hcur[k*128 + cbase];
                ull xb0 = pack2(xv.x,xv.x), xb1 = pack2(xv.y,xv.y);
                ull hb0 = pack2(hv.x,hv.x), hb1 = pack2(hv.y,hv.y);
                const ulonglong2* wg = (const ulonglong2*)&sm[WG + k*72*4];
                #pragma unroll
                for (int j = 0; j < 3; j++) {
                    ulonglong2 w0 = wg[3*rg + j];
                    A[j][0] = fma2(w0.x, xb0, A[j][0]); A[j][1] = fma2(w0.x, xb1, A[j][1]);
                    A[j][0] = fma2(w0.y, hb0, A[j][0]); A[j][1] = fma2(w0.y, hb1, A[j][1]);
                    ulonglong2 w1 = wg[24 + 3*rg + j];
                    A[3+j][0] = fma2(w1.x, xb0, A[3+j][0]); A[3+j][1] = fma2(w1.x, xb1, A[3+j][1]);
                    A[3+j][0] = fma2(w1.y, hb0, A[3+j][0]); A[3+j][1] = fma2(w1.y, hb1, A[3+j][1]);
                    ulonglong2 w2 = wg[48 + 3*rg + j];
                    A[6+j][0] = fma2(w2.x, xb0, A[6+j][0]); A[6+j][1] = fma2(w2.x, xb1, A[6+j][1]);
                    Bv[j][0]  = fma2(w2.y, hb0, Bv[j][0]);  Bv[j][1]  = fma2(w2.y, hb1, Bv[j][1]);
                }
            }
            #pragma unroll
            for (int p = 0; p < 3; p++)
                #pragma unroll
                for (int cc2 = 0; cc2 < 2; cc2++) {
                    float rv0,rv1,zv0,zv1,nv0,nv1,bn0,bn1;
                    unpack2(A[p][cc2],rv0,rv1); unpack2(A[3+p][cc2],zv0,zv1);
                    unpack2(A[6+p][cc2],nv0,nv1); unpack2(Bv[p][cc2],bn0,bn1);
                    int cc = cbase + cc2;
                    int o0 = rbase + 2*p, o1 = o0 + 1;
                    float rr0 = sigmf(rv0), rr1 = sigmf(rv1);
                    float zz0 = sigmf(zv0), zz1 = sigmf(zv1);
                    float ng0 = tanhfast(nv0 + rr0*bn0), ng1 = tanhfast(nv1 + rr1*bn1);
                    float h0 = hcur[o0*128 + cc], h1 = hcur[o1*128 + cc];
                    hnext[o0*128+cc] = (1.f-zz0)*ng0 + zz0*h0;
                    hnext[o1*128+cc] = (1.f-zz1)*ng1 + zz1*h1;
                }
        }
        __syncthreads();

        // G: zero first invalid column (shift-leak guard), publish boundaries, decoder
        const int par = it & 1;
        if (inv < 128 && tid < 48) hnext[tid*128 + inv] = 0.f;
        if (tid < 48) {
            g_hh[par][b][c][0][tid] = hnext[tid*128 + 0];
            int t127 = t0 + 127;
            g_hh[par][b][c][1][tid] = (t127 < Tn) ? hnext[tid*128 + 127] : 0.f;
        }
        {
            float* outp = out + (size_t)BXT * (1 + it);
            #pragma unroll
            for (int rep = 0; rep < 2; rep++) {
                int item = tid + rep*TPB;
                int i = item >> 7, n = item & 127, t = t0 + n;
                float e = sm[BDEC+i];
                #pragma unroll 8
                for (int k = 0; k < 48; k++) e = fmaf(sm[WDEC+i*48+k], hnext[k*128+n], e);
                float xn = 0.f;
                if (t < Tn) {
                    xn = xsh[i*130 + 1 + n]
                       + GAMMA_F * (e + sm[MPo+i*128+n] + sm[MFo+i*128+n] + sm[MYo+i*128+n]);
                    xsh[i*130 + 1 + n] = xn;
                    outp[(b*8+i)*Tn + t] = xn;
                }
                if (n == 0)   g_xh[par][b][c][0][i] = xn;
                if (n == 127) g_xh[par][b][c][1][i] = xn;
            }
        }
        __syncthreads();

        if (it + 1 < iters) {
            // arrive early; compute next-iter messages in the barrier shadow
            unsigned gen = 0;
            if (tid == 0) {
                gen = g_gen;
                __threadfence();
                if (atomicAdd(&g_cnt, 1u) == NBLK-1u) {
                    g_cnt = 0;
                    __threadfence();
                    g_gen = gen + 1u;
                }
            }
            msgphase(sm, xsh, b, t0, tid);   // boundary cols provisional
            if (tid == 0) {
                while (g_gen == gen) { __nanosleep(32); }
                __threadfence();
            }
            __syncthreads();
            // H: pull h halos; fix boundary messages from neighbor publishes
            if (tid < 48) {
                sm[HLo+tid] = (c > 0) ? g_hh[par][b][c-1][1][tid] : 0.f;
            } else if (tid < 96) {
                int k = tid-48;
                sm[HRo+k] = (c < NCHUNK-1) ? g_hh[par][b][c+1][0][k] : 0.f;
            } else if (tid < 104) {
                int i = tid-96;
                float a = 0.f;
                if (c > 0) {
                    const float* xl = g_xh[par][b][c-1][1];
                    #pragma unroll
                    for (int j = 0; j < 8; j++)
                        a += -sm[SQI+i*8+j]*xsh[j*130+1] + sm[SQIF+i*8+j]*xl[j];
                }
                sm[MPo + i*128 + 0] = a;
            } else if (tid < 112) {
                int i = tid-104;
                float a = 0.f;
                if (c < NCHUNK-1) {
                    const float* xr = g_xh[par][b][c+1][0];
                    #pragma unroll
                    for (int j = 0; j < 8; j++)
                        a += sm[SFTQI+i*8+j]*xr[j] - sm[SFTQIF+i*8+j]*xsh[j*130+128];
                }
                sm[MFo + i*128 + 127] = a;
            }
            __syncthreads();
        }
    }
}

extern "C" void kernel_launch(void* const* d_in, const int* in_sizes, int n_in,
                              void* d_out, int out_size) {
    const float* ys   = (const float*)d_in[0];
    const float* hx0  = (const float*)d_in[1];
    const float* F    = (const float*)d_in[2];
    const float* H    = (const float*)d_in[3];
    const float* Q    = (const float*)d_in[4];
    const float* R    = (const float*)d_in[5];
    const float* W_hy = (const float*)d_in[6];
    const float* b_hy = (const float*)d_in[7];
    const float* W1p  = (const float*)d_in[8];
    const float* b1p  = (const float*)d_in[9];
    const float* W2p  = (const float*)d_in[10];
    const float* b2p  = (const float*)d_in[11];
    const float* W1f  = (const float*)d_in[12];
    const float* b1f  = (const float*)d_in[13];
    const float* W2f  = (const float*)d_in[14];
    const float* b2f  = (const float*)d_in[15];
    const float* W1y  = (const float*)d_in[16];
    const float* b1y  = (const float*)d_in[17];
    const float* W2y  = (const float*)d_in[18];
    const float* b2y  = (const float*)d_in[19];
    const float* Wih  = (const float*)d_in[20];
    const float* bih  = (const float*)d_in[21];
    const float* Whh  = (const float*)d_in[22];
    const float* bhh  = (const float*)d_in[23];
    const float* Wdec = (const float*)d_in[24];
    const float* bdec = (const float*)d_in[25];
    float* out = (float*)d_out;

    const int iters = out_size / BXT - 1;

    cudaFuncSetAttribute(persist_kernel, cudaFuncAttributeMaxDynamicSharedMemorySize, SMEM_BYTES);

    prep_small<<<1, 64>>>(F, H, Q, R, b2p, b2f, b2y);
    prep_nodes<<<(Bn*Tn + 127)/128, 128>>>(ys, H, W_hy, b_hy, W1y, b1y);

    dim3 grid(NCHUNK, Bn);
    persist_kernel<<<grid, TPB, SMEM_BYTES>>>(hx0, out, iters,
        W1p, b1p, W2p, W1f, b1f, W2f, W1y, W2y, Wih, bih, Whh, bhh, Wdec, bdec);

    cudaMemcpyAsync(out, out + (size_t)BXT * iters, (size_t)BXT * sizeof(float),
                    cudaMemcpyDeviceToDevice);
}

// round 12
// speedup vs baseline: 2.1958x; 1.0211x over previous
#include <cuda_runtime.h>
#include <math.h>
typedef unsigned long long ull;

#define Bn 16
#define Tn 1000
#define NT 128
#define TPB 512
#define NCHUNK 8
#define NBLK (Bn*NCHUNK)
#define GAMMA_F 1e-4f
#define BXT (Bn*8*Tn)

__device__ float g_cy[BXT];
__device__ float g_hh[2][Bn][NCHUNK][2][48];
__device__ float g_xh[2][Bn][NCHUNK][2][8];
__device__ unsigned g_cnt;
__device__ volatile unsigned g_gen;

// shared layout (floats)
constexpr int WEP=0, WEF=4608, WYH=9216;
constexpr int W2P=11520, W2F=13824, W2Y=16128;
constexpr int WG=18432;
constexpr int WPM=32256, WFM=32640, WYM=33024, WDEC=33408;
constexpr int B1P=33792, B1F=33840, B2S=33888, BIH=33936, BHH=34080, BDEC=34224;
constexpr int SQI=34232, SQIF=34296, SFTQI=34360, SFTQIF=34424, SHTRIH=34488;
constexpr int HLo=34552, HRo=34600;
constexpr int BUF0=34648;           // 48x128
constexpr int XSH=40792;            // 8x130 halo
constexpr int MPo=41832, MFo=42856, MYo=43880;
constexpr int BUF1=44904, SCR=51048; // 48x128 each
constexpr int SMEM_FLOATS=57192;
constexpr int SMEM_BYTES=SMEM_FLOATS*4;  // 228,768 B

__device__ __forceinline__ ull pack2(float a, float b){ull r;asm("mov.b64 %0,{%1,%2};":"=l"(r):"f"(a),"f"(b));return r;}
__device__ __forceinline__ void unpack2(ull v, float&a, float&b){asm("mov.b64 {%0,%1},%2;":"=f"(a),"=f"(b):"l"(v));}
__device__ __forceinline__ ull fma2(ull a, ull b, ull c){ull d;asm("fma.rn.f32x2 %0,%1,%2,%3;":"=l"(d):"l"(a),"l"(b),"l"(c));return d;}
__device__ __forceinline__ ull add2(ull a, ull b){ull d;asm("add.rn.f32x2 %0,%1,%2;":"=l"(d):"l"(a),"l"(b));return d;}
__device__ __forceinline__ float sigmf(float x){ return 1.f/(1.f+__expf(-x)); }
__device__ __forceinline__ float tanhfast(float x){ return 1.f - 2.f/(__expf(2.f*x)+1.f); }

__device__ __forceinline__ void msgphase(float* __restrict__ sm, const float* __restrict__ xsh,
                                         int b, int t0, int tid) {
    #pragma unroll
    for (int rep = 0; rep < 2; rep++) {
        int item = tid + rep*TPB;
        int i = item >> 7, n = item & 127, t = t0 + n;
        bool valid = t < Tn;
        float accp = 0.f, accf = 0.f;
        float accy = valid ? g_cy[(b*8+i)*Tn + t] : 0.f;
        #pragma unroll
        for (int j = 0; j < 8; j++) {
            float xc = xsh[j*130 + 1 + n];
            accp = fmaf(-sm[SQI+i*8+j], xc, accp);
            accp = fmaf(sm[SQIF+i*8+j], xsh[j*130 + n], accp);
            accf = fmaf(sm[SFTQI+i*8+j], xsh[j*130 + 2 + n], accf);
            accf = fmaf(-sm[SFTQIF+i*8+j], xc, accf);
            accy = fmaf(-sm[SHTRIH+i*8+j], xc, accy);
        }
        sm[MPo + i*128+n] = (valid && t > 0) ? accp : 0.f;
        sm[MFo + i*128+n] = (t < Tn-1) ? accf : 0.f;
        sm[MYo + i*128+n] = valid ? accy : 0.f;
    }
}

template<int SHIFT>
__device__ __forceinline__ void edge1pf(const float* __restrict__ sm, int WEo_, int WMo_,
    const float* __restrict__ msg, const float* __restrict__ hsh, float* __restrict__ r,
    ull acc[3][2], int rg, int rbase, int lane, int cbase,
    const float* __restrict__ lsrc, int lstr, const float* __restrict__ rsrc, int rstr)
{
    #pragma unroll 4
    for (int k = 0; k < 48; k++) {
        float2 v = *(const float2*)&hsh[k*128 + cbase];
        ull b0 = pack2(v.x,v.x), b1 = pack2(v.y,v.y);
        ull n0, n1;
        if (SHIFT < 0) {
            float pv = __shfl_up_sync(0xffffffffu, v.y, 1);
            if (lane == 0) pv = lsrc[k*lstr];
            n0 = pack2(pv,pv); n1 = b0;
        } else {
            float qv = __shfl_down_sync(0xffffffffu, v.x, 1);
            if (lane == 31) qv = rsrc[k*rstr];
            n0 = b1; n1 = pack2(qv,qv);
        }
        const ulonglong2* wrow = (const ulonglong2*)&sm[WEo_ + (k*24 + 3*rg)*4];
        #pragma unroll
        for (int p = 0; p < 3; p++) {
            ulonglong2 wv = wrow[p];
            acc[p][0] = fma2(wv.x, b0, acc[p][0]);
            acc[p][1] = fma2(wv.x, b1, acc[p][1]);
            acc[p][0] = fma2(wv.y, n0, acc[p][0]);
            acc[p][1] = fma2(wv.y, n1, acc[p][1]);
        }
    }
    #pragma unroll
    for (int k = 0; k < 8; k++) {
        float2 m = *(const float2*)&msg[k*128 + cbase];
        ull b0 = pack2(m.x,m.x), b1 = pack2(m.y,m.y);
        #pragma unroll
        for (int p = 0; p < 3; p++) {
            ull wp = *(const ull*)&sm[WMo_ + k*48 + rbase + 2*p];
            acc[p][0] = fma2(wp,b0,acc[p][0]);
            acc[p][1] = fma2(wp,b1,acc[p][1]);
        }
    }
    #pragma unroll
    for (int p = 0; p < 3; p++) {
        float x0,x1,y0,y1;
        unpack2(acc[p][0],x0,y0); unpack2(acc[p][1],x1,y1);
        int o0 = rbase + 2*p;
        r[o0*128 + cbase]       = fmaxf(x0,0.f);
        r[o0*128 + cbase+1]     = fmaxf(x1,0.f);
        r[(o0+1)*128 + cbase]   = fmaxf(y0,0.f);
        r[(o0+1)*128 + cbase+1] = fmaxf(y1,0.f);
    }
}

__device__ __forceinline__ void edge1y(const float* __restrict__ sm,
    const float* __restrict__ msg, const float* __restrict__ hsh, float* __restrict__ r,
    ull acc[3][2], int rbase, int cbase)
{
    #pragma unroll 4
    for (int k = 0; k < 48; k++) {
        float2 v = *(const float2*)&hsh[k*128 + cbase];
        ull b0 = pack2(v.x,v.x), b1 = pack2(v.y,v.y);
        #pragma unroll
        for (int p = 0; p < 3; p++) {
            ull wp = *(const ull*)&sm[WYH + k*48 + rbase + 2*p];
            acc[p][0] = fma2(wp,b0,acc[p][0]);
            acc[p][1] = fma2(wp,b1,acc[p][1]);
        }
    }
    #pragma unroll
    for (int k = 0; k < 8; k++) {
        float2 m = *(const float2*)&msg[k*128 + cbase];
        ull b0 = pack2(m.x,m.x), b1 = pack2(m.y,m.y);
        #pragma unroll
        for (int p = 0; p < 3; p++) {
            ull wp = *(const ull*)&sm[WYM + k*48 + rbase + 2*p];
            acc[p][0] = fma2(wp,b0,acc[p][0]);
            acc[p][1] = fma2(wp,b1,acc[p][1]);
        }
    }
    #pragma unroll
    for (int p = 0; p < 3; p++) {
        float x0,x1,y0,y1;
        unpack2(acc[p][0],x0,y0); unpack2(acc[p][1],x1,y1);
        int o0 = rbase + 2*p;
        r[o0*128 + cbase]       = fmaxf(x0,0.f);
        r[o0*128 + cbase+1]     = fmaxf(x1,0.f);
        r[(o0+1)*128 + cbase]   = fmaxf(y0,0.f);
        r[(o0+1)*128 + cbase+1] = fmaxf(y1,0.f);
    }
}

__device__ __forceinline__ void layer2v(const float* __restrict__ sm, int W2o_,
    const float* __restrict__ r, ull agg[3][2], int rbase, int cbase)
{
    #pragma unroll 4
    for (int k = 0; k < 48; k++) {
        float2 v = *(const float2*)&r[k*128 + cbase];
        ull b0 = pack2(v.x,v.x), b1 = pack2(v.y,v.y);
        #pragma unroll
        for (int p = 0; p < 3; p++) {
            ull wp = *(const ull*)&sm[W2o_ + k*48 + rbase + 2*p];
            agg[p][0] = fma2(wp,b0,agg[p][0]);
            agg[p][1] = fma2(wp,b1,agg[p][1]);
        }
    }
}

__global__ void __launch_bounds__(TPB, 1)
persist_kernel(const float* __restrict__ ys, const float* __restrict__ hx0,
            const float* __restrict__ Fm, const float* __restrict__ Hm,
            const float* __restrict__ Qm, const float* __restrict__ Rm,
            const float* __restrict__ W_hy, const float* __restrict__ b_hy,
            float* __restrict__ out, int iters,
            const float* __restrict__ W1p, const float* __restrict__ b1p,
            const float* __restrict__ W2p, const float* __restrict__ b2p,
            const float* __restrict__ W1f, const float* __restrict__ b1f,
            const float* __restrict__ W2f, const float* __restrict__ b2f,
            const float* __restrict__ W1y, const float* __restrict__ b1y,
            const float* __restrict__ W2y, const float* __restrict__ b2y,
            const float* __restrict__ Wih, const float* __restrict__ bih,
            const float* __restrict__ Whh, const float* __restrict__ bhh,
            const float* __restrict__ Wdec, const float* __restrict__ bdec) {
    extern __shared__ float sm[];
    float* xsh = sm + XSH;
    float* buf0 = sm + BUF0;  float* buf1 = sm + BUF1;  float* scr = sm + SCR;

    const int tid = threadIdx.x;
    const int b = blockIdx.y;
    const int c = blockIdx.x;
    const int t0 = c * NT;

    // ================= INIT =================
    // --- fp64 Gauss-Jordan in scr overlay (all threads reach syncs) ---
    {
        double* dA8 = (double*)scr;        // 64
        double* dI8 = dA8 + 64;            // 64
        double* dA4 = dI8 + 64;            // 16
        double* dI4 = dA4 + 16;            // 16
        double* dT2 = dI4 + 16;            // 64
        double* dTH = dT2 + 64;            // 32
        const int r8 = tid >> 3, j8 = tid & 7;
        if (tid < 64) {
            dA8[tid] = (double)Qm[tid]; dI8[tid] = (r8==j8) ? 1.0 : 0.0;
            if (tid < 16) { dA4[tid] = (double)Rm[tid]; dI4[tid] = ((tid>>2)==(tid&3)) ? 1.0 : 0.0; }
        }
        __syncthreads();
        for (int cg2 = 0; cg2 < 8; cg2++) {
            double piv=1.0, f=0.0, acj=0.0, icj=0.0;
            if (tid < 64) {
                piv = dA8[cg2*8+cg2]; f = dA8[r8*8+cg2]/piv;
                acj = dA8[cg2*8+j8]; icj = dI8[cg2*8+j8];
            }
            __syncthreads();
            if (tid < 64) {
                if (r8 == cg2) { dA8[tid] = acj/piv; dI8[tid] = icj/piv; }
                else           { dA8[tid] -= f*acj;  dI8[tid] -= f*icj; }
            }
            __syncthreads();
        }
        for (int cg2 = 0; cg2 < 4; cg2++) {
            double piv=1.0, f=0.0, acj=0.0, icj=0.0;
            if (tid < 16) {
                int r4 = tid>>2;
                piv = dA4[cg2*4+cg2]; f = dA4[r4*4+cg2]/piv;
                acj = dA4[cg2*4+(tid&3)]; icj = dI4[cg2*4+(tid&3)];
            }
            __syncthreads();
            if (tid < 16) {
                int r4 = tid>>2;
                if (r4 == cg2) { dA4[tid] = acj/piv; dI4[tid] = icj/piv; }
                else           { dA4[tid] -= f*acj;  dI4[tid] -= f*icj; }
            }
            __syncthreads();
        }
        if (tid < 64) {
            sm[SQI+tid] = (float)dI8[tid];
            double s = 0;
            for (int k = 0; k < 8; k++) s += dI8[r8*8+k]*(double)Fm[k*8+j8];
            sm[SQIF+tid] = (float)s;
            s = 0;
            for (int k = 0; k < 8; k++) s += (double)Fm[k*8+r8]*dI8[k*8+j8];
            dT2[tid] = s; sm[SFTQI+tid] = (float)s;
            if (tid < 32) {
                int i = tid>>2, z = tid&3;
                double u = 0;
                for (int y = 0; y < 4; y++) u += (double)Hm[y*8+i]*dI4[y*4+z];
                dTH[tid] = u; sm[MPo+tid] = (float)u;   // HtRi (float) parked in MPo
            }
        }
        __syncthreads();
        if (tid < 64) {
            double s = 0;
            for (int k = 0; k < 8; k++) s += dT2[r8*8+k]*(double)Fm[k*8+j8];
            sm[SFTQIF+tid] = (float)s;
            s = 0;
            for (int z = 0; z < 4; z++) s += dTH[r8*4+z]*(double)Hm[z*8+j8];
            sm[SHTRIH+tid] = (float)s;
        }
        if (tid < 48) sm[B2S+tid] = b2p[tid]+b2f[tid]+b2y[tid];
        __syncthreads();
    }

    // --- weights staged once ---
    for (int idx = tid; idx < 48*24; idx += TPB) {
        int k = idx/24, p = idx - k*24;
        float* d = &sm[WEP + idx*4];
        d[0] = W1p[(2*p)*104 + k];      d[1] = W1p[(2*p+1)*104 + k];
        d[2] = W1p[(2*p)*104 + 48 + k]; d[3] = W1p[(2*p+1)*104 + 48 + k];
        float* e = &sm[WEF + idx*4];
        e[0] = W1f[(2*p)*104 + k];      e[1] = W1f[(2*p+1)*104 + k];
        e[2] = W1f[(2*p)*104 + 48 + k]; e[3] = W1f[(2*p+1)*104 + 48 + k];
    }
    for (int idx = tid; idx < 48*48; idx += TPB) {
        int o = idx/48, k = idx - o*48;
        sm[WYH + k*48 + o] = W1y[o*104 + k];
        sm[W2P + k*48 + o] = W2p[idx];
        sm[W2F + k*48 + o] = W2f[idx];
        sm[W2Y + k*48 + o] = W2y[idx];
    }
    for (int idx = tid; idx < 48*72; idx += TPB) {
        int k = idx/72, p = idx - k*72;
        float* d = &sm[WG + idx*4];
        d[0] = Wih[(2*p)*48 + k]; d[1] = Wih[(2*p+1)*48 + k];
        d[2] = Whh[(2*p)*48 + k]; d[3] = Whh[(2*p+1)*48 + k];
    }
    for (int idx = tid; idx < 48*8; idx += TPB) {
        int o = idx/8, k = idx - o*8;
        sm[WPM + k*48 + o] = W1p[o*104 + 96 + k];
        sm[WFM + k*48 + o] = W1f[o*104 + 96 + k];
        sm[WYM + k*48 + o] = W1y[o*104 + 96 + k];
    }
    for (int idx = tid; idx < 384; idx += TPB) sm[WDEC+idx]=Wdec[idx];
    if (tid < 48) { sm[B1P+tid]=b1p[tid]; sm[B1F+tid]=b1f[tid]; }
    for (int idx = tid; idx < 144; idx += TPB) { sm[BIH+idx]=bih[idx]; sm[BHH+idx]=bhh[idx]; }
    if (tid < 8) sm[BDEC+tid]=bdec[tid];

    // --- state init: hsh from hx0, xsh = H^T y (xs0), cy -> global, hy -> scr ---
    for (int idx = tid; idx < 48*128; idx += TPB) {
        int k = idx >> 7, cc = idx & 127; int t = t0 + cc;
        buf0[idx] = (t < Tn) ? hx0[(b*48+k)*Tn + t] : 0.f;
    }
    if (tid < 48) {
        int tl = t0 - 1, tr = t0 + 128;
        sm[HLo+tid] = (tl >= 0) ? hx0[(b*48+tid)*Tn + tl] : 0.f;
        sm[HRo+tid] = (tr < Tn) ? hx0[(b*48+tid)*Tn + tr] : 0.f;
    }
    for (int idx = tid; idx < 8*130; idx += TPB) {
        int k = idx / 130, cc = idx - k*130; int t = t0 + cc - 1;
        float v = 0.f;
        if (t >= 0 && t < Tn) {
            const float* yp = &ys[((size_t)b*Tn + t)*4];
            #pragma unroll
            for (int y = 0; y < 4; y++) v = fmaf(Hm[y*8+k], yp[y], v);
        }
        xsh[idx] = v;
    }
    for (int idx = tid; idx < 8*128; idx += TPB) {
        int i = idx >> 7, n = idx & 127; int t = t0 + n;
        if (t < Tn) {
            const float* yp = &ys[((size_t)b*Tn + t)*4];
            float s = 0.f;
            #pragma unroll
            for (int y = 0; y < 4; y++) s = fmaf(sm[MPo+i*4+y], yp[y], s);
            g_cy[(b*8+i)*Tn + t] = s;
        }
    }
    for (int idx = tid; idx < 48*128; idx += TPB) {
        int o = idx >> 7, cc = idx & 127; int t = t0 + cc;
        float s = 0.f;
        if (t < Tn) {
            const float* yp = &ys[((size_t)b*Tn + t)*4];
            s = b_hy[o];
            #pragma unroll
            for (int y = 0; y < 4; y++) s = fmaf(W_hy[o*4+y], yp[y], s);
        }
        scr[idx] = s;   // hy
    }
    __syncthreads();

    const int w = tid >> 5, lane = tid & 31, cg = w & 1, rg = w >> 1;
    const int rbase = 6*rg, cbase = cg*64 + 2*lane;
    const int inv = Tn - t0;

    // --- yterm -> registers (iteration-invariant) ---
    ull ytr0[3], ytr1[3];
    #pragma unroll
    for (int p = 0; p < 3; p++) {
        int o0 = rbase + 2*p, o1 = o0 + 1;
        float a0=0.f, a1=0.f, b0v=0.f, b1v=0.f;
        if (t0 + cbase < Tn) {
            a0 = b1y[o0]; a1 = b1y[o1];
            for (int k = 0; k < 48; k++) {
                float hv = scr[k*128 + cbase];
                a0 = fmaf(W1y[o0*104+48+k], hv, a0);
                a1 = fmaf(W1y[o1*104+48+k], hv, a1);
            }
        }
        if (t0 + cbase + 1 < Tn) {
            b0v = b1y[o0]; b1v = b1y[o1];
            for (int k = 0; k < 48; k++) {
                float hv = scr[k*128 + cbase + 1];
                b0v = fmaf(W1y[o0*104+48+k], hv, b0v);
                b1v = fmaf(W1y[o1*104+48+k], hv, b1v);
            }
        }
        ytr0[p] = pack2(a0, a1);
        ytr1[p] = pack2(b0v, b1v);
    }
    __syncthreads();   // scr free

    // prologue messages (it=0)
    msgphase(sm, xsh, b, t0, tid);
    __syncthreads();

    // ================= MAIN LOOP =================
    for (int it = 0; it < iters; it++) {
        float* hcur  = (it & 1) ? buf1 : buf0;
        float* hnext = (it & 1) ? buf0 : buf1;
        const float* lsrc; int lstr; const float* rsrc; int rstr;
        if (cg == 0) { lsrc = sm+HLo; lstr = 1; rsrc = hcur+64; rstr = 128; }
        else         { lsrc = hcur+63; lstr = 128; rsrc = sm+HRo; rstr = 1; }

        ull agg[3][2];
        #pragma unroll
        for (int p = 0; p < 3; p++) {
            ull bp = *(const ull*)&sm[B2S + rbase + 2*p];
            agg[p][0] = bp; agg[p][1] = bp;
        }
        // B: edge_p -> hnext
        {
            ull acc[3][2];
            #pragma unroll
            for (int p = 0; p < 3; p++) { ull bp = *(const ull*)&sm[B1P+rbase+2*p]; acc[p][0]=bp; acc[p][1]=bp; }
            edge1pf<-1>(sm, WEP, WPM, sm+MPo, hcur, hnext, acc, rg, rbase, lane, cbase, lsrc, lstr, rsrc, rstr);
        }
        __syncthreads();
        // C: layer2p(hnext) ; edge_f -> scr
        layer2v(sm, W2P, hnext, agg, rbase, cbase);
        {
            ull acc[3][2];
            #pragma unroll
            for (int p = 0; p < 3; p++) { ull bp = *(const ull*)&sm[B1F+rbase+2*p]; acc[p][0]=bp; acc[p][1]=bp; }
            edge1pf<1>(sm, WEF, WFM, sm+MFo, hcur, scr, acc, rg, rbase, lane, cbase, lsrc, lstr, rsrc, rstr);
        }
        __syncthreads();
        // D: layer2f(scr) ; edge_y -> hnext
        layer2v(sm, W2F, scr, agg, rbase, cbase);
        {
            ull acc[3][2];
            #pragma unroll
            for (int p = 0; p < 3; p++) { acc[p][0] = ytr0[p]; acc[p][1] = ytr1[p]; }
            edge1y(sm, sm+MYo, hcur, hnext, acc, rbase, cbase);
        }
        __syncthreads();
        // E: layer2y(hnext) ; spill agg -> scr
        layer2v(sm, W2Y, hnext, agg, rbase, cbase);
        #pragma unroll
        for (int p = 0; p < 3; p++) {
            float x0,x1,y0,y1;
            unpack2(agg[p][0],x0,y0); unpack2(agg[p][1],x1,y1);
            int o0 = rbase + 2*p;
            scr[o0*128+cbase] = x0;   scr[o0*128+cbase+1] = x1;
            scr[(o0+1)*128+cbase] = y0; scr[(o0+1)*128+cbase+1] = y1;
        }
        __syncthreads();

        // F: GRU
        {
            ull A[9][2], Bv[3][2];
            #pragma unroll
            for (int g = 0; g < 3; g++)
                #pragma unroll
                for (int p = 0; p < 3; p++) {
                    ull bi = *(const ull*)&sm[BIH + g*48 + rbase + 2*p];
                    if (g < 2) bi = add2(bi, *(const ull*)&sm[BHH + g*48 + rbase + 2*p]);
                    A[g*3+p][0] = bi; A[g*3+p][1] = bi;
                }
            #pragma unroll
            for (int p = 0; p < 3; p++) {
                ull bb = *(const ull*)&sm[BHH + 96 + rbase + 2*p];
                Bv[p][0] = bb; Bv[p][1] = bb;
            }
            #pragma unroll 2
            for (int k = 0; k < 48; k++) {
                float2 xv = *(const float2*)&scr[k*128 + cbase];
                float2 hv = *(const float2*)&hcur[k*128 + cbase];
                ull xb0 = pack2(xv.x,xv.x), xb1 = pack2(xv.y,xv.y);
                ull hb0 = pack2(hv.x,hv.x), hb1 = pack2(hv.y,hv.y);
                const ulonglong2* wg = (const ulonglong2*)&sm[WG + k*72*4];
                #pragma unroll
                for (int j = 0; j < 3; j++) {
                    ulonglong2 w0 = wg[3*rg + j];
                    A[j][0] = fma2(w0.x, xb0, A[j][0]); A[j][1] = fma2(w0.x, xb1, A[j][1]);
                    A[j][0] = fma2(w0.y, hb0, A[j][0]); A[j][1] = fma2(w0.y, hb1, A[j][1]);
                    ulonglong2 w1 = wg[24 + 3*rg + j];
                    A[3+j][0] = fma2(w1.x, xb0, A[3+j][0]); A[3+j][1] = fma2(w1.x, xb1, A[3+j][1]);
                    A[3+j][0] = fma2(w1.y, hb0, A[3+j][0]); A[3+j][1] = fma2(w1.y, hb1, A[3+j][1]);
                    ulonglong2 w2 = wg[48 + 3*rg + j];
                    A[6+j][0] = fma2(w2.x, xb0, A[6+j][0]); A[6+j][1] = fma2(w2.x, xb1, A[6+j][1]);
                    Bv[j][0]  = fma2(w2.y, hb0, Bv[j][0]);  Bv[j][1]  = fma2(w2.y, hb1, Bv[j][1]);
                }
            }
            #pragma unroll
            for (int p = 0; p < 3; p++)
                #pragma unroll
                for (int cc2 = 0; cc2 < 2; cc2++) {
                    float rv0,rv1,zv0,zv1,nv0,nv1,bn0,bn1;
                    unpack2(A[p][cc2],rv0,rv1); unpack2(A[3+p][cc2],zv0,zv1);
                    unpack2(A[6+p][cc2],nv0,nv1); unpack2(Bv[p][cc2],bn0,bn1);
                    int cc = cbase + cc2;
                    int o0 = rbase + 2*p, o1 = o0 + 1;
                    float rr0 = sigmf(rv0), rr1 = sigmf(rv1);
                    float zz0 = sigmf(zv0), zz1 = sigmf(zv1);
                    float ng0 = tanhfast(nv0 + rr0*bn0), ng1 = tanhfast(nv1 + rr1*bn1);
                    float h0 = hcur[o0*128 + cc], h1 = hcur[o1*128 + cc];
                    hnext[o0*128+cc] = (1.f-zz0)*ng0 + zz0*h0;
                    hnext[o1*128+cc] = (1.f-zz1)*ng1 + zz1*h1;
                }
        }
        __syncthreads();

        // G: shift-leak guard, publish, decoder
        const int par = it & 1;
        if (inv < 128 && tid < 48) hnext[tid*128 + inv] = 0.f;
        if (tid < 48) {
            g_hh[par][b][c][0][tid] = hnext[tid*128 + 0];
            int t127 = t0 + 127;
            g_hh[par][b][c][1][tid] = (t127 < Tn) ? hnext[tid*128 + 127] : 0.f;
        }
        {
            float* outp = out + (size_t)BXT * (1 + it);
            bool last = (it == iters - 1);
            #pragma unroll
            for (int rep = 0; rep < 2; rep++) {
                int item = tid + rep*TPB;
                int i = item >> 7, n = item & 127, t = t0 + n;
                float e = sm[BDEC+i];
                #pragma unroll 8
                for (int k = 0; k < 48; k++) e = fmaf(sm[WDEC+i*48+k], hnext[k*128+n], e);
                float xn = 0.f;
                if (t < Tn) {
                    xn = xsh[i*130 + 1 + n]
                       + GAMMA_F * (e + sm[MPo+i*128+n] + sm[MFo+i*128+n] + sm[MYo+i*128+n]);
                    xsh[i*130 + 1 + n] = xn;
                    outp[(b*8+i)*Tn + t] = xn;
                    if (last) out[(b*8+i)*Tn + t] = xn;   // final xs slot
                }
                if (n == 0)   g_xh[par][b][c][0][i] = xn;
                if (n == 127) g_xh[par][b][c][1][i] = xn;
            }
        }
        __syncthreads();

        if (it + 1 < iters) {
            unsigned gen = 0;
            if (tid == 0) {
                gen = g_gen;
                __threadfence();
                if (atomicAdd(&g_cnt, 1u) == NBLK-1u) {
                    g_cnt = 0;
                    __threadfence();
                    g_gen = gen + 1u;
                }
            }
            msgphase(sm, xsh, b, t0, tid);   // boundary cols provisional
            if (tid == 0) {
                while (g_gen == gen) { __nanosleep(32); }
                __threadfence();
            }
            __syncthreads();
            if (tid < 48) {
                sm[HLo+tid] = (c > 0) ? g_hh[par][b][c-1][1][tid] : 0.f;
            } else if (tid < 96) {
                int k = tid-48;
                sm[HRo+k] = (c < NCHUNK-1) ? g_hh[par][b][c+1][0][k] : 0.f;
            } else if (tid < 104) {
                int i = tid-96;
                float a = 0.f;
                if (c > 0) {
                    const float* xl = g_xh[par][b][c-1][1];
                    #pragma unroll
                    for (int j = 0; j < 8; j++)
                        a += -sm[SQI+i*8+j]*xsh[j*130+1] + sm[SQIF+i*8+j]*xl[j];
                }
                sm[MPo + i*128 + 0] = a;
            } else if (tid < 112) {
                int i = tid-104;
                float a = 0.f;
                if (c < NCHUNK-1) {
                    const float* xr = g_xh[par][b][c+1][0];
                    #pragma unroll
                    for (int j = 0; j < 8; j++)
                        a += sm[SFTQI+i*8+j]*xr[j] - sm[SFTQIF+i*8+j]*xsh[j*130+128];
                }
                sm[MFo + i*128 + 127] = a;
            }
            __syncthreads();
        }
    }
}

extern "C" void kernel_launch(void* const* d_in, const int* in_sizes, int n_in,
                              void* d_out, int out_size) {
    const float* ys   = (const float*)d_in[0];
    const float* hx0  = (const float*)d_in[1];
    const float* F    = (const float*)d_in[2];
    const float* H    = (const float*)d_in[3];
    const float* Q    = (const float*)d_in[4];
    const float* R    = (const float*)d_in[5];
    const float* W_hy = (const float*)d_in[6];
    const float* b_hy = (const float*)d_in[7];
    const float* W1p  = (const float*)d_in[8];
    const float* b1p  = (const float*)d_in[9];
    const float* W2p  = (const float*)d_in[10];
    const float* b2p  = (const float*)d_in[11];
    const float* W1f  = (const float*)d_in[12];
    const float* b1f  = (const float*)d_in[13];
    const float* W2f  = (const float*)d_in[14];
    const float* b2f  = (const float*)d_in[15];
    const float* W1y  = (const float*)d_in[16];
    const float* b1y  = (const float*)d_in[17];
    const float* W2y  = (const float*)d_in[18];
    const float* b2y  = (const float*)d_in[19];
    const float* Wih  = (const float*)d_in[20];
    const float* bih  = (const float*)d_in[21];
    const float* Whh  = (const float*)d_in[22];
    const float* bhh  = (const float*)d_in[23];
    const float* Wdec = (const float*)d_in[24];
    const float* bdec = (const float*)d_in[25];
    float* out = (float*)d_out;

    const int iters = out_size / BXT - 1;

    cudaFuncSetAttribute(persist_kernel, cudaFuncAttributeMaxDynamicSharedMemorySize, SMEM_BYTES);

    dim3 grid(NCHUNK, Bn);
    persist_kernel<<<grid, TPB, SMEM_BYTES>>>(ys, hx0, F, H, Q, R, W_hy, b_hy,
        out, iters,
        W1p, b1p, W2p, b2p, W1f, b1f, W2f, b2f, W1y, b1y, W2y, b2y,
        Wih, bih, Whh, bhh, Wdec, bdec);
}